// round 3
// baseline (speedup 1.0000x reference)
#include <cuda_runtime.h>
#include <cuda_bf16.h>
#include <math.h>
#include <stdint.h>

#define NSLOPE 0.2f
#define EPSBN 1e-5f
#define NMAX 50000
#define EMAX 800000
#define TOTMAX (EMAX + NMAX)

// ------------------------------ scratch (device globals; no allocation) ---
__device__ float g_bufA[(size_t)NMAX * 256];
__device__ float g_bufB[(size_t)NMAX * 256];
__device__ float g_h2[(size_t)NMAX * 64];
__device__ float g_asrc[(size_t)NMAX * 4];
__device__ float g_adst[(size_t)NMAX * 4];
__device__ float g_m[(size_t)NMAX * 4];
__device__ float g_watt[(size_t)TOTMAX * 4];
__device__ int   g_deg[NMAX];
__device__ int   g_off[NMAX + 1];
__device__ int   g_cur[NMAX];
__device__ int   g_csrc[TOTMAX];
__device__ int   g_cdst[TOTMAX];
__device__ float g_Y1[(size_t)EMAX * 128];
__device__ float g_Wp[64 * 256];
__device__ float g_stats[512];
__device__ float g_bnsc[256];
__device__ float g_bnsh[256];

__device__ __forceinline__ float lrelu(float v) { return v > 0.f ? v : NSLOPE * v; }

// ======================= HMMA helpers =====================================
#define SW(o) ((o) ^ (((o) >> 3) & 0x70))

__device__ __forceinline__ uint32_t s2u(const void* p) {
    uint32_t a;
    asm("{ .reg .u64 t; cvta.to.shared.u64 t, %1; cvt.u32.u64 %0, t; }" : "=r"(a) : "l"(p));
    return a;
}

__device__ __forceinline__ void mma_bf16(float* c, const uint32_t* a, const uint32_t* b) {
    asm volatile(
        "mma.sync.aligned.m16n8k16.row.col.f32.bf16.bf16.f32 "
        "{%0,%1,%2,%3}, {%4,%5,%6,%7}, {%8,%9}, {%0,%1,%2,%3};"
        : "+f"(c[0]), "+f"(c[1]), "+f"(c[2]), "+f"(c[3])
        : "r"(a[0]), "r"(a[1]), "r"(a[2]), "r"(a[3]), "r"(b[0]), "r"(b[1]));
}

__device__ __forceinline__ void ldsm4(uint32_t* r, uint32_t addr) {
    asm volatile("ldmatrix.sync.aligned.m8n8.x4.shared.b16 {%0,%1,%2,%3}, [%4];"
                 : "=r"(r[0]), "=r"(r[1]), "=r"(r[2]), "=r"(r[3]) : "r"(addr));
}

__device__ __forceinline__ void ldsm2(uint32_t* r, uint32_t addr) {
    asm volatile("ldmatrix.sync.aligned.m8n8.x2.shared.b16 {%0,%1}, [%2];"
                 : "=r"(r[0]), "=r"(r[1]) : "r"(addr));
}

__device__ __forceinline__ uint32_t bfbits(float v) {
    __nv_bfloat16 b = __float2bfloat16_rn(v);
    return (uint32_t)__bfloat16_as_ushort(b);
}
__device__ __forceinline__ float bfval(uint32_t bits) {
    return __bfloat162float(__ushort_as_bfloat16((unsigned short)bits));
}

// ======================= split-bf16 HMMA GEMM =============================
// D[M, *] tile = A[M, Kt] @ B[Kt, ldb-cols], block tile 128 x NT, K-chunk 64.
// ASRC: 0 = dense A (lda = Kt); 1 = A[e][k] = |h2[src[e]][k] - h2[dst[e]][k]| (Kt=64)
// EPI : 0 = C[m][colBase+n] = acc
//       1 = Y1[e][n] = lrelu(acc + PQ[s][n] + PQ[d][128+n] + ea[e]*w192[n] + bm1[n])
//       2 = out[e] = sum_n lrelu(acc[n] + bm2[n]) * wm3[n] + bm3   (NT == 64)
template <int NT, int ASRC, int EPI>
__global__ __launch_bounds__(256) void hmma_gemm(
    const float* __restrict__ A, const float* __restrict__ B, float* __restrict__ C,
    int M, int Kt, int ldb, int ldc,
    const int* __restrict__ ei, int E,
    const float* __restrict__ h2g, const float* __restrict__ PQ,
    const float* __restrict__ ea, const float* __restrict__ w192,
    const float* __restrict__ bias, const float* __restrict__ wm3,
    const float* __restrict__ bm3)
{
    extern __shared__ char sm[];
    constexpr int A_HI = 0;
    constexpr int A_LO = 16384;
    constexpr int B_HI = 32768;
    constexpr int B_LO = 32768 + NT * 128;
    constexpr int WNF = (NT / 2) / 8;           // n-frags per warp
    constexpr int LOGN = (NT == 64) ? 6 : 7;

    const uint32_t sb = s2u(sm);
    const int t = threadIdx.x;
    const int wid = t >> 5, lane = t & 31;
    const int rowBase = blockIdx.x * 128;
    const int colBase = blockIdx.y * NT;
    const int mBase = (wid & 3) * 32;
    const int nBase = (wid >> 2) * (NT / 2);

    float acc[2][WNF][4];
#pragma unroll
    for (int i = 0; i < 2; i++)
#pragma unroll
        for (int j = 0; j < WNF; j++)
#pragma unroll
            for (int q = 0; q < 4; q++) acc[i][j][q] = 0.f;

    for (int kc = 0; kc < Kt; kc += 64) {
        __syncthreads();
        // ---- A tile: 128 rows x 64 cols fp32 -> hi/lo bf16, SW128 ----
#pragma unroll
        for (int it = 0; it < 8; it++) {
            int idx = t + it * 256;              // 0..2047 float4s
            int r = idx >> 4, q = idx & 15;
            float4 v;
            if (ASRC == 0) {
                int gm = rowBase + r;
                if (gm >= M) gm = 0;
                v = *(const float4*)(A + (size_t)gm * Kt + kc + q * 4);
            } else {
                int e = rowBase + r;
                if (e >= M) e = 0;
                int s = ei[e], d = ei[E + e];
                float4 a4 = *(const float4*)(h2g + (size_t)s * 64 + q * 4);
                float4 b4 = *(const float4*)(h2g + (size_t)d * 64 + q * 4);
                v = make_float4(fabsf(a4.x - b4.x), fabsf(a4.y - b4.y),
                                fabsf(a4.z - b4.z), fabsf(a4.w - b4.w));
            }
            uint32_t hx = bfbits(v.x), hy = bfbits(v.y), hz = bfbits(v.z), hw = bfbits(v.w);
            uint32_t lx = bfbits(v.x - bfval(hx)), ly = bfbits(v.y - bfval(hy));
            uint32_t lz = bfbits(v.z - bfval(hz)), lw = bfbits(v.w - bfval(hw));
            int so = SW(r * 128 + q * 8);
            *(uint2*)(sm + A_HI + so) = make_uint2(hx | (hy << 16), hz | (hw << 16));
            *(uint2*)(sm + A_LO + so) = make_uint2(lx | (ly << 16), lz | (lw << 16));
        }
        // ---- B tile: 64 k-rows x NT cols -> [n][k] bf16 hi/lo, SW128 ----
#pragma unroll
        for (int it = 0; it < NT / 4; it++) {
            int idx = t + it * 256;
            int k = idx >> LOGN, n = idx & (NT - 1);
            float w = B[(size_t)(kc + k) * ldb + colBase + n];
            uint32_t hb = bfbits(w);
            uint32_t lb = bfbits(w - bfval(hb));
            int so = SW(n * 128 + k * 2);
            *(unsigned short*)(sm + B_HI + so) = (unsigned short)hb;
            *(unsigned short*)(sm + B_LO + so) = (unsigned short)lb;
        }
        __syncthreads();

        // ---- MMA phase ----
#pragma unroll
        for (int ks = 0; ks < 4; ks++) {
            const int k0 = ks * 16;
            uint32_t ahi[2][4], alo[2][4];
#pragma unroll
            for (int fi = 0; fi < 2; fi++) {
                int row = mBase + 16 * fi + (lane & 15);
                int bo = SW(row * 128 + (k0 + ((lane >> 4) << 3)) * 2);
                ldsm4(ahi[fi], sb + A_HI + bo);
                ldsm4(alo[fi], sb + A_LO + bo);
            }
#pragma unroll
            for (int fj = 0; fj < WNF; fj++) {
                int row = nBase + 8 * fj + (lane & 7);
                int bo = SW(row * 128 + (k0 + (((lane >> 3) & 1) << 3)) * 2);
                uint32_t bh[2], bl[2];
                ldsm2(bh, sb + B_HI + bo);
                ldsm2(bl, sb + B_LO + bo);
#pragma unroll
                for (int fi = 0; fi < 2; fi++) {
                    mma_bf16(acc[fi][fj], ahi[fi], bh);
                    mma_bf16(acc[fi][fj], ahi[fi], bl);
                    mma_bf16(acc[fi][fj], alo[fi], bh);
                }
            }
        }
    }

    // ---- epilogue ----
    if (EPI == 0) {
#pragma unroll
        for (int fi = 0; fi < 2; fi++) {
            int r0 = rowBase + mBase + 16 * fi + (lane >> 2);
#pragma unroll
            for (int fj = 0; fj < WNF; fj++) {
                int c = colBase + nBase + 8 * fj + (lane & 3) * 2;
                if (r0 < M)
                    *(float2*)(C + (size_t)r0 * ldc + c) =
                        make_float2(acc[fi][fj][0], acc[fi][fj][1]);
                if (r0 + 8 < M)
                    *(float2*)(C + (size_t)(r0 + 8) * ldc + c) =
                        make_float2(acc[fi][fj][2], acc[fi][fj][3]);
            }
        }
    } else if (EPI == 1) {
#pragma unroll
        for (int fi = 0; fi < 2; fi++) {
#pragma unroll
            for (int half = 0; half < 2; half++) {
                int r = rowBase + mBase + 16 * fi + (lane >> 2) + half * 8;
                if (r >= M) continue;
                int s = ei[r], d = ei[E + r];
                float eav = ea[r];
                const float* pqs = PQ + (size_t)s * 256;
                const float* pqd = PQ + (size_t)d * 256 + 128;
#pragma unroll
                for (int fj = 0; fj < WNF; fj++) {
                    int c = nBase + 8 * fj + (lane & 3) * 2;
                    float2 p1 = *(const float2*)(pqs + c);
                    float2 p2 = *(const float2*)(pqd + c);
                    float2 wv = *(const float2*)(w192 + c);
                    float2 bv = *(const float2*)(bias + c);
                    float v0 = acc[fi][fj][half * 2 + 0] + p1.x + p2.x + eav * wv.x + bv.x;
                    float v1 = acc[fi][fj][half * 2 + 1] + p1.y + p2.y + eav * wv.y + bv.y;
                    *(float2*)(C + (size_t)r * ldc + c) = make_float2(lrelu(v0), lrelu(v1));
                }
            }
        }
    } else {  // EPI == 2, NT == 64: fused final dot
        __syncthreads();               // everyone done reading smem tiles
        float* st = (float*)sm;        // staging [128][65]
#pragma unroll
        for (int fi = 0; fi < 2; fi++) {
            int lr = mBase + 16 * fi + (lane >> 2);
#pragma unroll
            for (int fj = 0; fj < WNF; fj++) {
                int c = nBase + 8 * fj + (lane & 3) * 2;
                st[lr * 65 + c] = acc[fi][fj][0];
                st[lr * 65 + c + 1] = acc[fi][fj][1];
                st[(lr + 8) * 65 + c] = acc[fi][fj][2];
                st[(lr + 8) * 65 + c + 1] = acc[fi][fj][3];
            }
        }
        __syncthreads();
        int row = wid * 16 + (lane >> 1);
        int half = lane & 1;
        float ssum = 0.f;
#pragma unroll
        for (int i = 0; i < 32; i++) {
            int c = half * 32 + i;
            float v = st[row * 65 + c];
            v = lrelu(v + bias[c]);
            ssum += v * wm3[c];
        }
        ssum += __shfl_xor_sync(0xffffffffu, ssum, 1);
        int gm = rowBase + row;
        if (half == 0 && gm < M) C[gm] = ssum + bm3[0];
    }
}

// ------------------------------ CSR build ---------------------------------
__global__ void init_deg_kernel(int* __restrict__ deg, int n)
{
    int i = blockIdx.x * blockDim.x + threadIdx.x;
    if (i < n) deg[i] = 1;
}

__global__ void count_kernel(const int* __restrict__ ei, int E, int* __restrict__ deg)
{
    int i = blockIdx.x * blockDim.x + threadIdx.x;
    if (i < E) atomicAdd(&deg[ei[E + i]], 1);
}

__global__ void scan_kernel(const int* __restrict__ deg, int* __restrict__ off, int n)
{
    __shared__ int sh[1024];
    __shared__ int carry_s;
    int t = threadIdx.x;
    if (t == 0) carry_s = 0;
    __syncthreads();
    for (int base = 0; base < n; base += 1024) {
        int i = base + t;
        int v = (i < n) ? deg[i] : 0;
        sh[t] = v;
        __syncthreads();
        int sum = v;
        for (int ofs = 1; ofs < 1024; ofs <<= 1) {
            int add = (t >= ofs) ? sh[t - ofs] : 0;
            __syncthreads();
            sum += add;
            sh[t] = sum;
            __syncthreads();
        }
        int carry = carry_s;
        if (i < n) off[i] = carry + sum - v;
        __syncthreads();
        if (t == 1023) carry_s = carry + sum;
        __syncthreads();
    }
    if (t == 0) off[n] = carry_s;
}

__global__ void copy_cur_kernel(const int* __restrict__ off, int* __restrict__ cur, int n)
{
    int i = blockIdx.x * blockDim.x + threadIdx.x;
    if (i < n) cur[i] = off[i];
}

__global__ void scatter_edges_kernel(const int* __restrict__ ei, int E,
                                     int* __restrict__ cur,
                                     int* __restrict__ csrc, int* __restrict__ cdst)
{
    int i = blockIdx.x * blockDim.x + threadIdx.x;
    if (i >= E) return;
    int d = ei[E + i];
    int pos = atomicAdd(&cur[d], 1);
    csrc[pos] = ei[i];
    cdst[pos] = d;
}

__global__ void scatter_loops_kernel(int N, int* __restrict__ cur,
                                     int* __restrict__ csrc, int* __restrict__ cdst)
{
    int n = blockIdx.x * blockDim.x + threadIdx.x;
    if (n >= N) return;
    int pos = atomicAdd(&cur[n], 1);
    csrc[pos] = n;
    cdst[pos] = n;
}

// ------------------------------ GAT attention -----------------------------
__global__ void alpha_kernel(const float* __restrict__ h,
                             const float* __restrict__ aw_s, const float* __restrict__ aw_d,
                             float* __restrict__ asrc, float* __restrict__ adst, int N)
{
    int id = blockIdx.x * blockDim.x + threadIdx.x;
    if (id >= N * 4) return;
    int n = id >> 2, hh = id & 3;
    const float4* row = (const float4*)(h + (size_t)n * 256 + hh * 64);
    const float4* ws  = (const float4*)(aw_s + hh * 64);
    const float4* wd  = (const float4*)(aw_d + hh * 64);
    float sa = 0.f, sb = 0.f;
#pragma unroll
    for (int q = 0; q < 16; q++) {
        float4 v = row[q];
        float4 a = ws[q], b = wd[q];
        sa += v.x * a.x + v.y * a.y + v.z * a.z + v.w * a.w;
        sb += v.x * b.x + v.y * b.y + v.z * b.z + v.w * b.w;
    }
    asrc[id] = sa;
    adst[id] = sb;
}

__global__ void gat_max_kernel(const float4* __restrict__ asrc4, const float4* __restrict__ adst4,
                               const int* __restrict__ off, const int* __restrict__ csrc,
                               float4* __restrict__ m4, int N)
{
    int w = (blockIdx.x * blockDim.x + threadIdx.x) >> 5;
    int lane = threadIdx.x & 31;
    if (w >= N) return;
    float4 ad = adst4[w];
    float m0 = -1e30f, m1 = -1e30f, m2 = -1e30f, m3 = -1e30f;
    int hi = off[w + 1];
    for (int p = off[w] + lane; p < hi; p += 32) {
        int s = csrc[p];
        float4 as = asrc4[s];
        float e0 = lrelu(as.x + ad.x), e1 = lrelu(as.y + ad.y);
        float e2 = lrelu(as.z + ad.z), e3 = lrelu(as.w + ad.w);
        m0 = fmaxf(m0, e0); m1 = fmaxf(m1, e1); m2 = fmaxf(m2, e2); m3 = fmaxf(m3, e3);
    }
#pragma unroll
    for (int o = 16; o > 0; o >>= 1) {
        m0 = fmaxf(m0, __shfl_xor_sync(0xffffffffu, m0, o));
        m1 = fmaxf(m1, __shfl_xor_sync(0xffffffffu, m1, o));
        m2 = fmaxf(m2, __shfl_xor_sync(0xffffffffu, m2, o));
        m3 = fmaxf(m3, __shfl_xor_sync(0xffffffffu, m3, o));
    }
    if (lane == 0) m4[w] = make_float4(m0, m1, m2, m3);
}

__global__ void watt_kernel(const float4* __restrict__ asrc4, const float4* __restrict__ adst4,
                            const float4* __restrict__ m4,
                            const int* __restrict__ csrc, const int* __restrict__ cdst,
                            float4* __restrict__ watt4, int tot)
{
    int p = blockIdx.x * blockDim.x + threadIdx.x;
    if (p >= tot) return;
    int s = csrc[p], d = cdst[p];
    float4 as = asrc4[s], ad = adst4[d], mm = m4[d];
    float4 w;
    w.x = expf(lrelu(as.x + ad.x) - mm.x);
    w.y = expf(lrelu(as.y + ad.y) - mm.y);
    w.z = expf(lrelu(as.z + ad.z) - mm.z);
    w.w = expf(lrelu(as.w + ad.w) - mm.w);
    watt4[p] = w;
}

__global__ __launch_bounds__(256) void gat_aggregate_kernel(
    const float* __restrict__ h, const float* __restrict__ watt,
    const int* __restrict__ off, const int* __restrict__ csrc,
    const float* __restrict__ bias, float* __restrict__ out, int concat)
{
    int d = blockIdx.x;
    int t = threadIdx.x;
    int hh = t >> 6;
    int lo = off[d], hi = off[d + 1];
    float acc = 0.f, den = 0.f;
    for (int p = lo; p < hi; ++p) {
        int s = csrc[p];
        float w = watt[p * 4 + hh];
        den += w;
        acc += w * h[(size_t)s * 256 + t];
    }
    acc /= den;
    if (concat) {
        out[(size_t)d * 256 + t] = acc + bias[t];
    } else {
        __shared__ float red[256];
        red[t] = acc;
        __syncthreads();
        if (t < 64)
            out[(size_t)d * 64 + t] =
                0.25f * (red[t] + red[t + 64] + red[t + 128] + red[t + 192]) + bias[t];
    }
}

// ------------------------------ BatchNorm ---------------------------------
__global__ void zero_kernel(float* __restrict__ p, int n)
{
    int i = blockIdx.x * blockDim.x + threadIdx.x;
    if (i < n) p[i] = 0.f;
}

__global__ void bn_stats_kernel(const float* __restrict__ X, int rows, int cols,
                                float* __restrict__ stats, int rowsPerBlock)
{
    int t = threadIdx.x;
    int c = t % cols;
    int rsub = t / cols;
    int rstep = 256 / cols;
    int r0 = blockIdx.x * rowsPerBlock;
    int r1 = r0 + rowsPerBlock; if (r1 > rows) r1 = rows;
    float s = 0.f, s2 = 0.f;
    for (int r = r0 + rsub; r < r1; r += rstep) {
        float v = X[(size_t)r * cols + c];
        s += v;
        s2 += v * v;
    }
    atomicAdd(&stats[c], s);
    atomicAdd(&stats[cols + c], s2);
}

__global__ void bn_final_kernel(const float* __restrict__ stats,
                                const float* __restrict__ g, const float* __restrict__ be,
                                int rows, int cols,
                                float* __restrict__ sc, float* __restrict__ sh)
{
    int c = threadIdx.x;
    if (c >= cols) return;
    float inv = 1.f / (float)rows;
    float mean = stats[c] * inv;
    float var = stats[cols + c] * inv - mean * mean;
    float scale = g[c] * rsqrtf(var + EPSBN);
    sc[c] = scale;
    sh[c] = be[c] - mean * scale;
}

__global__ void bn_apply_kernel(float* __restrict__ X, int n, int cols,
                                const float* __restrict__ sc, const float* __restrict__ sh,
                                int act)
{
    int i = blockIdx.x * blockDim.x + threadIdx.x;
    if (i >= n) return;
    int c = i % cols;
    float v = X[i] * sc[c] + sh[c];
    if (act) v = lrelu(v);
    X[i] = v;
}

// ------------------------------ misc --------------------------------------
__global__ void build_wp_kernel(const float* __restrict__ Wm1, float* __restrict__ Wp)
{
    int idx = blockIdx.x * blockDim.x + threadIdx.x;
    if (idx >= 64 * 256) return;
    int i = idx >> 8, j = idx & 255;
    Wp[idx] = (j < 128) ? Wm1[i * 128 + j] : Wm1[(64 + i) * 128 + (j - 128)];
}

// ------------------------------ host orchestration ------------------------
extern "C" void kernel_launch(void* const* d_in, const int* in_sizes, int n_in,
                              void* d_out, int out_size)
{
    const float* x  = (const float*)d_in[0];
    const int*   ei = (const int*)d_in[1];
    const float* ea = (const float*)d_in[2];
    const int N = in_sizes[0] / 128;
    const int E = in_sizes[2];

    const float *W0, *as0, *ad0, *b0, *g0, *be0;
    const float *W1, *as1, *ad1, *b1, *g1, *be1;
    const float *W2, *as2, *ad2, *b2, *g2, *be2;
    if (in_sizes[7] == 256 * 256) {
        W0 = (const float*)d_in[3];  as0 = (const float*)d_in[4];  ad0 = (const float*)d_in[5];  b0 = (const float*)d_in[6];
        W1 = (const float*)d_in[7];  as1 = (const float*)d_in[8];  ad1 = (const float*)d_in[9];  b1 = (const float*)d_in[10];
        W2 = (const float*)d_in[11]; as2 = (const float*)d_in[12]; ad2 = (const float*)d_in[13]; b2 = (const float*)d_in[14];
        g0 = (const float*)d_in[15]; be0 = (const float*)d_in[16];
        g1 = (const float*)d_in[17]; be1 = (const float*)d_in[18];
        g2 = (const float*)d_in[19]; be2 = (const float*)d_in[20];
    } else {
        W0 = (const float*)d_in[3];  as0 = (const float*)d_in[4];  ad0 = (const float*)d_in[5];  b0 = (const float*)d_in[6];
        g0 = (const float*)d_in[7];  be0 = (const float*)d_in[8];
        W1 = (const float*)d_in[9];  as1 = (const float*)d_in[10]; ad1 = (const float*)d_in[11]; b1 = (const float*)d_in[12];
        g1 = (const float*)d_in[13]; be1 = (const float*)d_in[14];
        W2 = (const float*)d_in[15]; as2 = (const float*)d_in[16]; ad2 = (const float*)d_in[17]; b2 = (const float*)d_in[18];
        g2 = (const float*)d_in[19]; be2 = (const float*)d_in[20];
    }
    const float* Wm1 = (const float*)d_in[21];
    const float* bm1 = (const float*)d_in[22];
    const float* Wm2 = (const float*)d_in[23];
    const float* bm2 = (const float*)d_in[24];
    const float* Wm3 = (const float*)d_in[25];
    const float* bm3 = (const float*)d_in[26];
    float* out = (float*)d_out;

    float *bufA, *bufB, *h2, *asrc, *adst, *m, *watt, *Y1, *Wp, *stats, *bnsc, *bnsh;
    int *deg, *off, *cur, *csrc, *cdst;
    cudaGetSymbolAddress((void**)&bufA, g_bufA);
    cudaGetSymbolAddress((void**)&bufB, g_bufB);
    cudaGetSymbolAddress((void**)&h2, g_h2);
    cudaGetSymbolAddress((void**)&asrc, g_asrc);
    cudaGetSymbolAddress((void**)&adst, g_adst);
    cudaGetSymbolAddress((void**)&m, g_m);
    cudaGetSymbolAddress((void**)&watt, g_watt);
    cudaGetSymbolAddress((void**)&Y1, g_Y1);
    cudaGetSymbolAddress((void**)&Wp, g_Wp);
    cudaGetSymbolAddress((void**)&stats, g_stats);
    cudaGetSymbolAddress((void**)&bnsc, g_bnsc);
    cudaGetSymbolAddress((void**)&bnsh, g_bnsh);
    cudaGetSymbolAddress((void**)&deg, g_deg);
    cudaGetSymbolAddress((void**)&off, g_off);
    cudaGetSymbolAddress((void**)&cur, g_cur);
    cudaGetSymbolAddress((void**)&csrc, g_csrc);
    cudaGetSymbolAddress((void**)&cdst, g_cdst);

    const int tot = E + N;

    const int SM128 = 32768 + 2 * 128 * 128;   // 65536
    const int SM64  = 32768 + 2 * 64 * 128;    // 49152
    static bool attr_done = false;
    if (!attr_done) {
        cudaFuncSetAttribute(hmma_gemm<128, 0, 0>, cudaFuncAttributeMaxDynamicSharedMemorySize, SM128);
        cudaFuncSetAttribute(hmma_gemm<128, 1, 1>, cudaFuncAttributeMaxDynamicSharedMemorySize, SM128);
        cudaFuncSetAttribute(hmma_gemm<64, 0, 2>,  cudaFuncAttributeMaxDynamicSharedMemorySize, SM64);
        attr_done = true;
    }

    // ---- CSR build ----
    init_deg_kernel<<<(N + 255) / 256, 256>>>(deg, N);
    count_kernel<<<(E + 255) / 256, 256>>>(ei, E, deg);
    scan_kernel<<<1, 1024>>>(deg, off, N);
    copy_cur_kernel<<<(N + 255) / 256, 256>>>(off, cur, N);
    scatter_edges_kernel<<<(E + 255) / 256, 256>>>(ei, E, cur, csrc, cdst);
    scatter_loops_kernel<<<(N + 255) / 256, 256>>>(N, cur, csrc, cdst);

    // node GEMM: C[M, Ncols] = A[M, Kt] @ B[Kt, Ncols], Ncols in {128, 256}
    auto node_gemm = [&](const float* A, const float* B, float* C, int M, int Kt, int Ncols) {
        dim3 grid((M + 127) / 128, Ncols / 128);
        hmma_gemm<128, 0, 0><<<grid, 256, SM128>>>(
            A, B, C, M, Kt, Ncols, Ncols, nullptr, 0, nullptr, nullptr,
            nullptr, nullptr, nullptr, nullptr, nullptr);
    };

    auto gat_layer = [&](const float* Xin, int Kin, const float* W,
                         const float* aws, const float* awd, const float* bias,
                         float* hbuf, float* outbuf, int concat) {
        node_gemm(Xin, W, hbuf, N, Kin, 256);
        alpha_kernel<<<(N * 4 + 255) / 256, 256>>>(hbuf, aws, awd, asrc, adst, N);
        gat_max_kernel<<<(N * 32 + 255) / 256, 256>>>((const float4*)asrc, (const float4*)adst,
                                                      off, csrc, (float4*)m, N);
        watt_kernel<<<(tot + 255) / 256, 256>>>((const float4*)asrc, (const float4*)adst,
                                                (const float4*)m, csrc, cdst, (float4*)watt, tot);
        gat_aggregate_kernel<<<N, 256>>>(hbuf, watt, off, csrc, bias, outbuf, concat);
    };

    auto bnorm = [&](float* X, int cols, const float* g, const float* be, int act) {
        zero_kernel<<<1, 512>>>(stats, 2 * cols);
        const int rpb = 256;
        bn_stats_kernel<<<(N + rpb - 1) / rpb, 256>>>(X, N, cols, stats, rpb);
        bn_final_kernel<<<1, cols>>>(stats, g, be, N, cols, bnsc, bnsh);
        bn_apply_kernel<<<(N * cols + 255) / 256, 256>>>(X, N * cols, cols, bnsc, bnsh, act);
    };

    // ---- 3 GAT layers ----
    gat_layer(x, 128, W0, as0, ad0, b0, bufA, bufB, 1);
    bnorm(bufB, 256, g0, be0, 1);

    gat_layer(bufB, 256, W1, as1, ad1, b1, bufA, bufB, 1);
    bnorm(bufB, 256, g1, be1, 1);

    gat_layer(bufB, 256, W2, as2, ad2, b2, bufA, h2, 0);
    bnorm(h2, 64, g2, be2, 0);

    // ---- Edge MLP ----
    build_wp_kernel<<<(64 * 256 + 255) / 256, 256>>>(Wm1, Wp);
    node_gemm(h2, Wp, bufA, N, 64, 256);   // bufA = PQ (N x 256)

    // Y1 = lrelu(|h2[s]-h2[d]| @ C + PQ[s] + PQ[d] + ea*w192 + bm1), fused
    hmma_gemm<128, 1, 1><<<dim3((E + 127) / 128, 1), 256, SM128>>>(
        nullptr, Wm1 + 128 * 128, Y1, E, 64, 128, 128, ei, E, h2, bufA, ea,
        Wm1 + 192 * 128, bm1, nullptr, nullptr);

    // out = lrelu(Y1 @ Wm2 + bm2) . Wm3 + bm3, fused
    hmma_gemm<64, 0, 2><<<dim3((E + 127) / 128, 1), 256, SM64>>>(
        Y1, Wm2, out, E, 128, 64, 1, nullptr, 0, nullptr, nullptr, nullptr,
        nullptr, bm2, Wm3, bm3);
}

// round 4
// speedup vs baseline: 1.6599x; 1.6599x over previous
#include <cuda_runtime.h>
#include <cuda_bf16.h>
#include <math.h>
#include <stdint.h>

#define NSLOPE 0.2f
#define EPSBN 1e-5f
#define NMAX 50000
#define EMAX 800000
#define TOTMAX (EMAX + NMAX)

// ------------------------------ scratch (device globals; no allocation) ---
__device__ float g_bufA[(size_t)NMAX * 256];
__device__ float g_bufB[(size_t)NMAX * 256];
__device__ float g_h2[(size_t)NMAX * 64];
__device__ float g_asrc[(size_t)NMAX * 4];
__device__ float g_adst[(size_t)NMAX * 4];
__device__ float g_m[(size_t)NMAX * 4];
__device__ float g_watt[(size_t)TOTMAX * 4];
__device__ int   g_deg[NMAX];
__device__ int   g_off[NMAX + 1];
__device__ int   g_cur[NMAX];
__device__ int   g_csrc[TOTMAX];
__device__ int   g_cdst[TOTMAX];
__device__ float g_stats[512];
__device__ float g_bnsc[256];
__device__ float g_bnsh[256];
// split-bf16 buffers
__device__ __nv_bfloat16 g_xhi[(size_t)NMAX * 256];
__device__ __nv_bfloat16 g_xlo[(size_t)NMAX * 256];
__device__ __nv_bfloat16 g_y1hi[(size_t)EMAX * 128];
__device__ __nv_bfloat16 g_y1lo[(size_t)EMAX * 128];
__device__ __nv_bfloat16 g_w0hi[256 * 128],  g_w0lo[256 * 128];
__device__ __nv_bfloat16 g_w1hi[256 * 256],  g_w1lo[256 * 256];
__device__ __nv_bfloat16 g_w2hi[256 * 256],  g_w2lo[256 * 256];
__device__ __nv_bfloat16 g_wphi[256 * 64],   g_wplo[256 * 64];
__device__ __nv_bfloat16 g_cthi[128 * 64],   g_ctlo[128 * 64];
__device__ __nv_bfloat16 g_wm2hi[64 * 128],  g_wm2lo[64 * 128];

__device__ __forceinline__ float lrelu(float v) { return v > 0.f ? v : NSLOPE * v; }

// ======================= HMMA helpers =====================================
#define SW(o) ((o) ^ (((o) >> 3) & 0x70))

__device__ __forceinline__ uint32_t s2u(const void* p) {
    uint32_t a;
    asm("{ .reg .u64 t; cvta.to.shared.u64 t, %1; cvt.u32.u64 %0, t; }" : "=r"(a) : "l"(p));
    return a;
}

__device__ __forceinline__ void mma_bf16(float* c, const uint32_t* a, const uint32_t* b) {
    asm volatile(
        "mma.sync.aligned.m16n8k16.row.col.f32.bf16.bf16.f32 "
        "{%0,%1,%2,%3}, {%4,%5,%6,%7}, {%8,%9}, {%0,%1,%2,%3};"
        : "+f"(c[0]), "+f"(c[1]), "+f"(c[2]), "+f"(c[3])
        : "r"(a[0]), "r"(a[1]), "r"(a[2]), "r"(a[3]), "r"(b[0]), "r"(b[1]));
}

__device__ __forceinline__ void ldsm4(uint32_t* r, uint32_t addr) {
    asm volatile("ldmatrix.sync.aligned.m8n8.x4.shared.b16 {%0,%1,%2,%3}, [%4];"
                 : "=r"(r[0]), "=r"(r[1]), "=r"(r[2]), "=r"(r[3]) : "r"(addr));
}

__device__ __forceinline__ void ldsm2(uint32_t* r, uint32_t addr) {
    asm volatile("ldmatrix.sync.aligned.m8n8.x2.shared.b16 {%0,%1}, [%2];"
                 : "=r"(r[0]), "=r"(r[1]) : "r"(addr));
}

__device__ __forceinline__ uint32_t bfbits(float v) {
    __nv_bfloat16 b = __float2bfloat16_rn(v);
    return (uint32_t)__bfloat16_as_ushort(b);
}
__device__ __forceinline__ float bfval(uint32_t bits) {
    return __bfloat162float(__ushort_as_bfloat16((unsigned short)bits));
}

// ======================= split-bf16 HMMA GEMM =============================
// Block tile 128 x NT, K-chunk 64. acc = Ahi*Bhi + Ahi*Blo + Alo*Bhi (fp32 acc).
// ASRC: 0 = pre-split bf16 A (Ahi/Alo, lda = Kt)
//       1 = A[e][k] = |h2[src[e]][k] - h2[dst[e]][k]| (fp32 gather+split, Kt=64)
//       2 = dense fp32 A converted in-loader (Afp, lda = Kt)
// B: pre-split bf16, transposed layout Bt[n][k] (ldb = Kt), n = global col.
// EPI : 0 = C[m][colBase+n] = acc (fp32)
//       1 = split-bf16 Y1 out: lrelu(acc + PQ[s][n] + PQ[d][128+n] + ea*w192 + bm1)
//       2 = out[e] = sum_n lrelu(acc[n] + bm2[n]) * wm3[n] + bm3   (NT == 64)
template <int NT, int ASRC, int EPI>
__global__ __launch_bounds__(256) void hmma_gemm(
    const __nv_bfloat16* __restrict__ Ahi, const __nv_bfloat16* __restrict__ Alo,
    const __nv_bfloat16* __restrict__ Bhi, const __nv_bfloat16* __restrict__ Blo,
    float* __restrict__ C, __nv_bfloat16* __restrict__ Chi, __nv_bfloat16* __restrict__ Clo,
    int M, int Kt, int ldc,
    const float* __restrict__ Afp,
    const int* __restrict__ ei, int E, const float* __restrict__ h2g,
    const float* __restrict__ PQ, const float* __restrict__ ea,
    const float* __restrict__ w192, const float* __restrict__ bias,
    const float* __restrict__ wm3, const float* __restrict__ bm3)
{
    extern __shared__ char sm[];
    constexpr int A_HI = 0;
    constexpr int A_LO = 16384;
    constexpr int B_HI = 32768;
    constexpr int B_LO = 32768 + NT * 128;
    constexpr int WNF = (NT / 2) / 8;

    const uint32_t sb = s2u(sm);
    const int t = threadIdx.x;
    const int wid = t >> 5, lane = t & 31;
    const int rowBase = blockIdx.x * 128;
    const int colBase = blockIdx.y * NT;
    const int mBase = (wid & 3) * 32;
    const int nBase = (wid >> 2) * (NT / 2);

    float acc[2][WNF][4];
#pragma unroll
    for (int i = 0; i < 2; i++)
#pragma unroll
        for (int j = 0; j < WNF; j++)
#pragma unroll
            for (int q = 0; q < 4; q++) acc[i][j][q] = 0.f;

    for (int kc = 0; kc < Kt; kc += 64) {
        __syncthreads();
        // ---- A tile ----
        if (ASRC == 0) {
#pragma unroll
            for (int it = 0; it < 4; it++) {
                int idx = t + it * 256;          // 128 rows x 8 octets
                int r = idx >> 3, q = idx & 7;
                int gm = rowBase + r; if (gm >= M) gm = 0;
                size_t off = (size_t)gm * Kt + kc + q * 8;
                int so = SW(r * 128 + q * 16);
                *(uint4*)(sm + A_HI + so) = *(const uint4*)(Ahi + off);
                *(uint4*)(sm + A_LO + so) = *(const uint4*)(Alo + off);
            }
        } else {
#pragma unroll
            for (int it = 0; it < 8; it++) {
                int idx = t + it * 256;          // 128 rows x 16 float4s
                int r = idx >> 4, q = idx & 15;
                float4 v;
                if (ASRC == 2) {
                    int gm = rowBase + r; if (gm >= M) gm = 0;
                    v = *(const float4*)(Afp + (size_t)gm * Kt + kc + q * 4);
                } else {
                    int e = rowBase + r; if (e >= M) e = 0;
                    int s = ei[e], d = ei[E + e];
                    float4 a4 = *(const float4*)(h2g + (size_t)s * 64 + q * 4);
                    float4 b4 = *(const float4*)(h2g + (size_t)d * 64 + q * 4);
                    v = make_float4(fabsf(a4.x - b4.x), fabsf(a4.y - b4.y),
                                    fabsf(a4.z - b4.z), fabsf(a4.w - b4.w));
                }
                uint32_t hx = bfbits(v.x), hy = bfbits(v.y), hz = bfbits(v.z), hw = bfbits(v.w);
                uint32_t lx = bfbits(v.x - bfval(hx)), ly = bfbits(v.y - bfval(hy));
                uint32_t lz = bfbits(v.z - bfval(hz)), lw = bfbits(v.w - bfval(hw));
                int so = SW(r * 128 + q * 8);
                *(uint2*)(sm + A_HI + so) = make_uint2(hx | (hy << 16), hz | (hw << 16));
                *(uint2*)(sm + A_LO + so) = make_uint2(lx | (ly << 16), lz | (lw << 16));
            }
        }
        // ---- B tile (pre-split, [n][k]) ----
#pragma unroll
        for (int it = 0; it < NT / 32; it++) {
            int idx = t + it * 256;              // NT rows x 8 octets
            int n = idx >> 3, q = idx & 7;
            size_t off = (size_t)(colBase + n) * Kt + kc + q * 8;
            int so = SW(n * 128 + q * 16);
            *(uint4*)(sm + B_HI + so) = *(const uint4*)(Bhi + off);
            *(uint4*)(sm + B_LO + so) = *(const uint4*)(Blo + off);
        }
        __syncthreads();

        // ---- MMA ----
#pragma unroll
        for (int ks = 0; ks < 4; ks++) {
            const int k0 = ks * 16;
            uint32_t ahi[2][4], alo[2][4];
#pragma unroll
            for (int fi = 0; fi < 2; fi++) {
                int row = mBase + 16 * fi + (lane & 15);
                int bo = SW(row * 128 + (k0 + ((lane >> 4) << 3)) * 2);
                ldsm4(ahi[fi], sb + A_HI + bo);
                ldsm4(alo[fi], sb + A_LO + bo);
            }
#pragma unroll
            for (int fj = 0; fj < WNF; fj++) {
                int row = nBase + 8 * fj + (lane & 7);
                int bo = SW(row * 128 + (k0 + (((lane >> 3) & 1) << 3)) * 2);
                uint32_t bh[2], bl[2];
                ldsm2(bh, sb + B_HI + bo);
                ldsm2(bl, sb + B_LO + bo);
#pragma unroll
                for (int fi = 0; fi < 2; fi++) {
                    mma_bf16(acc[fi][fj], ahi[fi], bh);
                    mma_bf16(acc[fi][fj], ahi[fi], bl);
                    mma_bf16(acc[fi][fj], alo[fi], bh);
                }
            }
        }
    }

    // ---- epilogue ----
    if (EPI == 0) {
#pragma unroll
        for (int fi = 0; fi < 2; fi++) {
            int r0 = rowBase + mBase + 16 * fi + (lane >> 2);
#pragma unroll
            for (int fj = 0; fj < WNF; fj++) {
                int c = colBase + nBase + 8 * fj + (lane & 3) * 2;
                if (r0 < M)
                    *(float2*)(C + (size_t)r0 * ldc + c) =
                        make_float2(acc[fi][fj][0], acc[fi][fj][1]);
                if (r0 + 8 < M)
                    *(float2*)(C + (size_t)(r0 + 8) * ldc + c) =
                        make_float2(acc[fi][fj][2], acc[fi][fj][3]);
            }
        }
    } else if (EPI == 1) {
#pragma unroll
        for (int fi = 0; fi < 2; fi++) {
#pragma unroll
            for (int half = 0; half < 2; half++) {
                int r = rowBase + mBase + 16 * fi + (lane >> 2) + half * 8;
                if (r >= M) continue;
                int s = ei[r], d = ei[E + r];
                float eav = ea[r];
                const float* pqs = PQ + (size_t)s * 256;
                const float* pqd = PQ + (size_t)d * 256 + 128;
#pragma unroll
                for (int fj = 0; fj < WNF; fj++) {
                    int c = nBase + 8 * fj + (lane & 3) * 2;
                    float2 p1 = *(const float2*)(pqs + c);
                    float2 p2 = *(const float2*)(pqd + c);
                    float2 wv = *(const float2*)(w192 + c);
                    float2 bv = *(const float2*)(bias + c);
                    float v0 = lrelu(acc[fi][fj][half * 2 + 0] + p1.x + p2.x + eav * wv.x + bv.x);
                    float v1 = lrelu(acc[fi][fj][half * 2 + 1] + p1.y + p2.y + eav * wv.y + bv.y);
                    __nv_bfloat16 h0 = __float2bfloat16_rn(v0);
                    __nv_bfloat16 h1 = __float2bfloat16_rn(v1);
                    __nv_bfloat16 l0 = __float2bfloat16_rn(v0 - __bfloat162float(h0));
                    __nv_bfloat16 l1 = __float2bfloat16_rn(v1 - __bfloat162float(h1));
                    __nv_bfloat162 hp; hp.x = h0; hp.y = h1;
                    __nv_bfloat162 lp; lp.x = l0; lp.y = l1;
                    *(__nv_bfloat162*)(Chi + (size_t)r * 128 + c) = hp;
                    *(__nv_bfloat162*)(Clo + (size_t)r * 128 + c) = lp;
                }
            }
        }
    } else {  // EPI == 2, NT == 64: fused final dot
        __syncthreads();
        float* st = (float*)sm;        // [128][65]
#pragma unroll
        for (int fi = 0; fi < 2; fi++) {
            int lr = mBase + 16 * fi + (lane >> 2);
#pragma unroll
            for (int fj = 0; fj < WNF; fj++) {
                int c = nBase + 8 * fj + (lane & 3) * 2;
                st[lr * 65 + c] = acc[fi][fj][0];
                st[lr * 65 + c + 1] = acc[fi][fj][1];
                st[(lr + 8) * 65 + c] = acc[fi][fj][2];
                st[(lr + 8) * 65 + c + 1] = acc[fi][fj][3];
            }
        }
        __syncthreads();
        int row = wid * 16 + (lane >> 1);
        int half = lane & 1;
        float ssum = 0.f;
#pragma unroll
        for (int i = 0; i < 32; i++) {
            int c = half * 32 + i;
            float v = st[row * 65 + c];
            v = lrelu(v + bias[c]);
            ssum += v * wm3[c];
        }
        ssum += __shfl_xor_sync(0xffffffffu, ssum, 1);
        int gm = rowBase + row;
        if (half == 0 && gm < M) C[gm] = ssum + bm3[0];
    }
}

// ------------------------------ split / prep kernels ----------------------
// X fp32 -> bf16 hi/lo; optional per-col affine + lrelu (fused BN apply)
__global__ void split_act_kernel(const float* __restrict__ X,
                                 __nv_bfloat16* __restrict__ hi, __nv_bfloat16* __restrict__ lo,
                                 int n, int colsMask,
                                 const float* __restrict__ sc, const float* __restrict__ sh)
{
    int i = blockIdx.x * blockDim.x + threadIdx.x;
    if (i >= n) return;
    float v = X[i];
    if (sc) {
        int c = i & colsMask;
        v = lrelu(v * sc[c] + sh[c]);
    }
    __nv_bfloat16 h = __float2bfloat16_rn(v);
    hi[i] = h;
    lo[i] = __float2bfloat16_rn(v - __bfloat162float(h));
}

// W [K][C] fp32 -> Wt hi/lo [C][K] bf16
__global__ void split_wt_kernel(const float* __restrict__ W,
                                __nv_bfloat16* __restrict__ hi, __nv_bfloat16* __restrict__ lo,
                                int K, int C)
{
    int i = blockIdx.x * blockDim.x + threadIdx.x;
    if (i >= K * C) return;
    int k = i / C, c = i % C;
    float v = W[i];
    __nv_bfloat16 h = __float2bfloat16_rn(v);
    hi[(size_t)c * K + k] = h;
    lo[(size_t)c * K + k] = __float2bfloat16_rn(v - __bfloat162float(h));
}

// Wp^T from Wm1: wpt[c][k] = c<128 ? Wm1[k][c] : Wm1[64+k][c-128]; k<64, c<256
__global__ void split_wp_kernel(const float* __restrict__ Wm1,
                                __nv_bfloat16* __restrict__ hi, __nv_bfloat16* __restrict__ lo)
{
    int i = blockIdx.x * blockDim.x + threadIdx.x;
    if (i >= 64 * 256) return;
    int c = i >> 6, k = i & 63;
    float v = (c < 128) ? Wm1[k * 128 + c] : Wm1[(64 + k) * 128 + (c - 128)];
    __nv_bfloat16 h = __float2bfloat16_rn(v);
    hi[i] = h;
    lo[i] = __float2bfloat16_rn(v - __bfloat162float(h));
}

// ------------------------------ CSR build ---------------------------------
__global__ void init_deg_kernel(int* __restrict__ deg, int n)
{
    int i = blockIdx.x * blockDim.x + threadIdx.x;
    if (i < n) deg[i] = 1;
}

__global__ void count_kernel(const int* __restrict__ ei, int E, int* __restrict__ deg)
{
    int i = blockIdx.x * blockDim.x + threadIdx.x;
    if (i < E) atomicAdd(&deg[ei[E + i]], 1);
}

__global__ void scan_kernel(const int* __restrict__ deg, int* __restrict__ off, int n)
{
    __shared__ int sh[1024];
    __shared__ int carry_s;
    int t = threadIdx.x;
    if (t == 0) carry_s = 0;
    __syncthreads();
    for (int base = 0; base < n; base += 1024) {
        int i = base + t;
        int v = (i < n) ? deg[i] : 0;
        sh[t] = v;
        __syncthreads();
        int sum = v;
        for (int ofs = 1; ofs < 1024; ofs <<= 1) {
            int add = (t >= ofs) ? sh[t - ofs] : 0;
            __syncthreads();
            sum += add;
            sh[t] = sum;
            __syncthreads();
        }
        int carry = carry_s;
        if (i < n) off[i] = carry + sum - v;
        __syncthreads();
        if (t == 1023) carry_s = carry + sum;
        __syncthreads();
    }
    if (t == 0) off[n] = carry_s;
}

__global__ void copy_cur_kernel(const int* __restrict__ off, int* __restrict__ cur, int n)
{
    int i = blockIdx.x * blockDim.x + threadIdx.x;
    if (i < n) cur[i] = off[i];
}

__global__ void scatter_edges_kernel(const int* __restrict__ ei, int E,
                                     int* __restrict__ cur,
                                     int* __restrict__ csrc, int* __restrict__ cdst)
{
    int i = blockIdx.x * blockDim.x + threadIdx.x;
    if (i >= E) return;
    int d = ei[E + i];
    int pos = atomicAdd(&cur[d], 1);
    csrc[pos] = ei[i];
    cdst[pos] = d;
}

__global__ void scatter_loops_kernel(int N, int* __restrict__ cur,
                                     int* __restrict__ csrc, int* __restrict__ cdst)
{
    int n = blockIdx.x * blockDim.x + threadIdx.x;
    if (n >= N) return;
    int pos = atomicAdd(&cur[n], 1);
    csrc[pos] = n;
    cdst[pos] = n;
}

// ------------------------------ GAT attention -----------------------------
__global__ void alpha_kernel(const float* __restrict__ h,
                             const float* __restrict__ aw_s, const float* __restrict__ aw_d,
                             float* __restrict__ asrc, float* __restrict__ adst, int N)
{
    int id = blockIdx.x * blockDim.x + threadIdx.x;
    if (id >= N * 4) return;
    int n = id >> 2, hh = id & 3;
    const float4* row = (const float4*)(h + (size_t)n * 256 + hh * 64);
    const float4* ws  = (const float4*)(aw_s + hh * 64);
    const float4* wd  = (const float4*)(aw_d + hh * 64);
    float sa = 0.f, sb = 0.f;
#pragma unroll
    for (int q = 0; q < 16; q++) {
        float4 v = row[q];
        float4 a = ws[q], b = wd[q];
        sa += v.x * a.x + v.y * a.y + v.z * a.z + v.w * a.w;
        sb += v.x * b.x + v.y * b.y + v.z * b.z + v.w * b.w;
    }
    asrc[id] = sa;
    adst[id] = sb;
}

__global__ void gat_max_kernel(const float4* __restrict__ asrc4, const float4* __restrict__ adst4,
                               const int* __restrict__ off, const int* __restrict__ csrc,
                               float4* __restrict__ m4, int N)
{
    int w = (blockIdx.x * blockDim.x + threadIdx.x) >> 5;
    int lane = threadIdx.x & 31;
    if (w >= N) return;
    float4 ad = adst4[w];
    float m0 = -1e30f, m1 = -1e30f, m2 = -1e30f, m3 = -1e30f;
    int hi = off[w + 1];
    for (int p = off[w] + lane; p < hi; p += 32) {
        int s = csrc[p];
        float4 as = asrc4[s];
        float e0 = lrelu(as.x + ad.x), e1 = lrelu(as.y + ad.y);
        float e2 = lrelu(as.z + ad.z), e3 = lrelu(as.w + ad.w);
        m0 = fmaxf(m0, e0); m1 = fmaxf(m1, e1); m2 = fmaxf(m2, e2); m3 = fmaxf(m3, e3);
    }
#pragma unroll
    for (int o = 16; o > 0; o >>= 1) {
        m0 = fmaxf(m0, __shfl_xor_sync(0xffffffffu, m0, o));
        m1 = fmaxf(m1, __shfl_xor_sync(0xffffffffu, m1, o));
        m2 = fmaxf(m2, __shfl_xor_sync(0xffffffffu, m2, o));
        m3 = fmaxf(m3, __shfl_xor_sync(0xffffffffu, m3, o));
    }
    if (lane == 0) m4[w] = make_float4(m0, m1, m2, m3);
}

__global__ void watt_kernel(const float4* __restrict__ asrc4, const float4* __restrict__ adst4,
                            const float4* __restrict__ m4,
                            const int* __restrict__ csrc, const int* __restrict__ cdst,
                            float4* __restrict__ watt4, int tot)
{
    int p = blockIdx.x * blockDim.x + threadIdx.x;
    if (p >= tot) return;
    int s = csrc[p], d = cdst[p];
    float4 as = asrc4[s], ad = adst4[d], mm = m4[d];
    float4 w;
    w.x = expf(lrelu(as.x + ad.x) - mm.x);
    w.y = expf(lrelu(as.y + ad.y) - mm.y);
    w.z = expf(lrelu(as.z + ad.z) - mm.z);
    w.w = expf(lrelu(as.w + ad.w) - mm.w);
    watt4[p] = w;
}

__global__ __launch_bounds__(128) void gat_aggregate_kernel(
    const float* __restrict__ h, const float* __restrict__ watt,
    const int* __restrict__ off, const int* __restrict__ csrc,
    const float* __restrict__ bias, float* __restrict__ out, int concat)
{
    int d = blockIdx.x;
    int t = threadIdx.x;            // 128
    int c = t * 2;
    int hh = t >> 5;
    int lo = off[d], hi = off[d + 1];
    float accx = 0.f, accy = 0.f, den = 0.f;
    int s_n = csrc[lo];
    float w_n = watt[lo * 4 + hh];
    for (int p = lo; p < hi; ++p) {
        int s = s_n;
        float w = w_n;
        int pn = p + 1;
        if (pn < hi) { s_n = csrc[pn]; w_n = watt[pn * 4 + hh]; }
        float2 hv = *(const float2*)(h + (size_t)s * 256 + c);
        den += w;
        accx += w * hv.x;
        accy += w * hv.y;
    }
    float inv = 1.f / den;
    accx *= inv; accy *= inv;
    if (concat) {
        *(float2*)(out + (size_t)d * 256 + c) =
            make_float2(accx + bias[c], accy + bias[c + 1]);
    } else {
        __shared__ float red[256];
        red[c] = accx; red[c + 1] = accy;
        __syncthreads();
        if (t < 32) {
#pragma unroll
            for (int j = 0; j < 2; j++) {
                int cc = t * 2 + j;
                out[(size_t)d * 64 + cc] =
                    0.25f * (red[cc] + red[cc + 64] + red[cc + 128] + red[cc + 192]) + bias[cc];
            }
        }
    }
}

// ------------------------------ BatchNorm ---------------------------------
__global__ void zero_kernel(float* __restrict__ p, int n)
{
    int i = blockIdx.x * blockDim.x + threadIdx.x;
    if (i < n) p[i] = 0.f;
}

__global__ void bn_stats_kernel(const float* __restrict__ X, int rows, int cols,
                                float* __restrict__ stats, int rowsPerBlock)
{
    int t = threadIdx.x;
    int c = t % cols;
    int rsub = t / cols;
    int rstep = 256 / cols;
    int r0 = blockIdx.x * rowsPerBlock;
    int r1 = r0 + rowsPerBlock; if (r1 > rows) r1 = rows;
    float s = 0.f, s2 = 0.f;
    for (int r = r0 + rsub; r < r1; r += rstep) {
        float v = X[(size_t)r * cols + c];
        s += v;
        s2 += v * v;
    }
    atomicAdd(&stats[c], s);
    atomicAdd(&stats[cols + c], s2);
}

__global__ void bn_final_kernel(const float* __restrict__ stats,
                                const float* __restrict__ g, const float* __restrict__ be,
                                int rows, int cols,
                                float* __restrict__ sc, float* __restrict__ sh)
{
    int c = threadIdx.x;
    if (c >= cols) return;
    float inv = 1.f / (float)rows;
    float mean = stats[c] * inv;
    float var = stats[cols + c] * inv - mean * mean;
    float scale = g[c] * rsqrtf(var + EPSBN);
    sc[c] = scale;
    sh[c] = be[c] - mean * scale;
}

__global__ void bn_apply_kernel(float* __restrict__ X, int n, int cols,
                                const float* __restrict__ sc, const float* __restrict__ sh,
                                int act)
{
    int i = blockIdx.x * blockDim.x + threadIdx.x;
    if (i >= n) return;
    int c = i % cols;
    float v = X[i] * sc[c] + sh[c];
    if (act) v = lrelu(v);
    X[i] = v;
}

// ------------------------------ host orchestration ------------------------
extern "C" void kernel_launch(void* const* d_in, const int* in_sizes, int n_in,
                              void* d_out, int out_size)
{
    const float* x  = (const float*)d_in[0];
    const int*   ei = (const int*)d_in[1];
    const float* ea = (const float*)d_in[2];
    const int N = in_sizes[0] / 128;
    const int E = in_sizes[2];

    const float *W0, *as0, *ad0, *b0, *g0, *be0;
    const float *W1, *as1, *ad1, *b1, *g1, *be1;
    const float *W2, *as2, *ad2, *b2, *g2, *be2;
    if (in_sizes[7] == 256 * 256) {
        W0 = (const float*)d_in[3];  as0 = (const float*)d_in[4];  ad0 = (const float*)d_in[5];  b0 = (const float*)d_in[6];
        W1 = (const float*)d_in[7];  as1 = (const float*)d_in[8];  ad1 = (const float*)d_in[9];  b1 = (const float*)d_in[10];
        W2 = (const float*)d_in[11]; as2 = (const float*)d_in[12]; ad2 = (const float*)d_in[13]; b2 = (const float*)d_in[14];
        g0 = (const float*)d_in[15]; be0 = (const float*)d_in[16];
        g1 = (const float*)d_in[17]; be1 = (const float*)d_in[18];
        g2 = (const float*)d_in[19]; be2 = (const float*)d_in[20];
    } else {
        W0 = (const float*)d_in[3];  as0 = (const float*)d_in[4];  ad0 = (const float*)d_in[5];  b0 = (const float*)d_in[6];
        g0 = (const float*)d_in[7];  be0 = (const float*)d_in[8];
        W1 = (const float*)d_in[9];  as1 = (const float*)d_in[10]; ad1 = (const float*)d_in[11]; b1 = (const float*)d_in[12];
        g1 = (const float*)d_in[13]; be1 = (const float*)d_in[14];
        W2 = (const float*)d_in[15]; as2 = (const float*)d_in[16]; ad2 = (const float*)d_in[17]; b2 = (const float*)d_in[18];
        g2 = (const float*)d_in[19]; be2 = (const float*)d_in[20];
    }
    const float* Wm1 = (const float*)d_in[21];
    const float* bm1 = (const float*)d_in[22];
    const float* Wm2 = (const float*)d_in[23];
    const float* bm2 = (const float*)d_in[24];
    const float* Wm3 = (const float*)d_in[25];
    const float* bm3 = (const float*)d_in[26];
    float* out = (float*)d_out;

    float *bufA, *bufB, *h2, *asrc, *adst, *m, *watt, *stats, *bnsc, *bnsh;
    int *deg, *off, *cur, *csrc, *cdst;
    __nv_bfloat16 *xhi, *xlo, *y1hi, *y1lo;
    __nv_bfloat16 *w0hi, *w0lo, *w1hi, *w1lo, *w2hi, *w2lo;
    __nv_bfloat16 *wphi, *wplo, *cthi, *ctlo, *wm2hi, *wm2lo;
    cudaGetSymbolAddress((void**)&bufA, g_bufA);
    cudaGetSymbolAddress((void**)&bufB, g_bufB);
    cudaGetSymbolAddress((void**)&h2, g_h2);
    cudaGetSymbolAddress((void**)&asrc, g_asrc);
    cudaGetSymbolAddress((void**)&adst, g_adst);
    cudaGetSymbolAddress((void**)&m, g_m);
    cudaGetSymbolAddress((void**)&watt, g_watt);
    cudaGetSymbolAddress((void**)&stats, g_stats);
    cudaGetSymbolAddress((void**)&bnsc, g_bnsc);
    cudaGetSymbolAddress((void**)&bnsh, g_bnsh);
    cudaGetSymbolAddress((void**)&deg, g_deg);
    cudaGetSymbolAddress((void**)&off, g_off);
    cudaGetSymbolAddress((void**)&cur, g_cur);
    cudaGetSymbolAddress((void**)&csrc, g_csrc);
    cudaGetSymbolAddress((void**)&cdst, g_cdst);
    cudaGetSymbolAddress((void**)&xhi, g_xhi);
    cudaGetSymbolAddress((void**)&xlo, g_xlo);
    cudaGetSymbolAddress((void**)&y1hi, g_y1hi);
    cudaGetSymbolAddress((void**)&y1lo, g_y1lo);
    cudaGetSymbolAddress((void**)&w0hi, g_w0hi);  cudaGetSymbolAddress((void**)&w0lo, g_w0lo);
    cudaGetSymbolAddress((void**)&w1hi, g_w1hi);  cudaGetSymbolAddress((void**)&w1lo, g_w1lo);
    cudaGetSymbolAddress((void**)&w2hi, g_w2hi);  cudaGetSymbolAddress((void**)&w2lo, g_w2lo);
    cudaGetSymbolAddress((void**)&wphi, g_wphi);  cudaGetSymbolAddress((void**)&wplo, g_wplo);
    cudaGetSymbolAddress((void**)&cthi, g_cthi);  cudaGetSymbolAddress((void**)&ctlo, g_ctlo);
    cudaGetSymbolAddress((void**)&wm2hi, g_wm2hi); cudaGetSymbolAddress((void**)&wm2lo, g_wm2lo);

    const int tot = E + N;

    const int SM128 = 32768 + 2 * 128 * 128;   // 65536
    const int SM64  = 32768 + 2 * 64 * 128;    // 49152
    cudaFuncSetAttribute(hmma_gemm<128, 0, 0>, cudaFuncAttributeMaxDynamicSharedMemorySize, SM128);
    cudaFuncSetAttribute(hmma_gemm<128, 2, 0>, cudaFuncAttributeMaxDynamicSharedMemorySize, SM128);
    cudaFuncSetAttribute(hmma_gemm<128, 1, 1>, cudaFuncAttributeMaxDynamicSharedMemorySize, SM128);
    cudaFuncSetAttribute(hmma_gemm<64, 0, 2>,  cudaFuncAttributeMaxDynamicSharedMemorySize, SM64);

    // node GEMM from pre-split activations
    auto node_gemm = [&](const __nv_bfloat16* Ah, const __nv_bfloat16* Al,
                         const __nv_bfloat16* Bh, const __nv_bfloat16* Bl,
                         float* C, int M, int Kt, int Ncols) {
        dim3 grid((M + 127) / 128, Ncols / 128);
        hmma_gemm<128, 0, 0><<<grid, 256, SM128>>>(
            Ah, Al, Bh, Bl, C, nullptr, nullptr, M, Kt, Ncols,
            nullptr, nullptr, 0, nullptr, nullptr, nullptr, nullptr, nullptr,
            nullptr, nullptr);
    };

    // ---- launches 1-4 ordered so the profiled launch (#4) is the L0 GEMM ----
    split_act_kernel<<<(N * 128 + 255) / 256, 256>>>(x, xhi, xlo, N * 128, 127, nullptr, nullptr);
    split_wt_kernel<<<(128 * 256 + 255) / 256, 256>>>(W0, w0hi, w0lo, 128, 256);
    init_deg_kernel<<<(N + 255) / 256, 256>>>(deg, N);
    node_gemm(xhi, xlo, w0hi, w0lo, bufA, N, 128, 256);          // launch #4

    // ---- rest of CSR build ----
    count_kernel<<<(E + 255) / 256, 256>>>(ei, E, deg);
    scan_kernel<<<1, 1024>>>(deg, off, N);
    copy_cur_kernel<<<(N + 255) / 256, 256>>>(off, cur, N);
    scatter_edges_kernel<<<(E + 255) / 256, 256>>>(ei, E, cur, csrc, cdst);
    scatter_loops_kernel<<<(N + 255) / 256, 256>>>(N, cur, csrc, cdst);

    auto attention = [&](const float* hbuf, const float* aws, const float* awd,
                         const float* bias, float* outbuf, int concat) {
        alpha_kernel<<<(N * 4 + 255) / 256, 256>>>(hbuf, aws, awd, asrc, adst, N);
        gat_max_kernel<<<(N * 32 + 255) / 256, 256>>>((const float4*)asrc, (const float4*)adst,
                                                      off, csrc, (float4*)m, N);
        watt_kernel<<<(tot + 255) / 256, 256>>>((const float4*)asrc, (const float4*)adst,
                                                (const float4*)m, csrc, cdst, (float4*)watt, tot);
        gat_aggregate_kernel<<<N, 128>>>(hbuf, watt, off, csrc, bias, outbuf, concat);
    };

    auto bnstats = [&](const float* X, int cols, const float* g, const float* be) {
        zero_kernel<<<1, 512>>>(stats, 2 * cols);
        bn_stats_kernel<<<(N + 255) / 256, 256>>>(X, N, cols, stats, 256);
        bn_final_kernel<<<1, cols>>>(stats, g, be, N, cols, bnsc, bnsh);
    };

    // ---- layer 0 ----
    attention(bufA, as0, ad0, b0, bufB, 1);
    bnstats(bufB, 256, g0, be0);
    // fused BN-apply + lrelu + split for next layer's A
    split_act_kernel<<<(N * 256 + 255) / 256, 256>>>(bufB, xhi, xlo, N * 256, 255, bnsc, bnsh);

    // ---- layer 1 ----
    split_wt_kernel<<<(256 * 256 + 255) / 256, 256>>>(W1, w1hi, w1lo, 256, 256);
    node_gemm(xhi, xlo, w1hi, w1lo, bufA, N, 256, 256);
    attention(bufA, as1, ad1, b1, bufB, 1);
    bnstats(bufB, 256, g1, be1);
    split_act_kernel<<<(N * 256 + 255) / 256, 256>>>(bufB, xhi, xlo, N * 256, 255, bnsc, bnsh);

    // ---- layer 2 ----
    split_wt_kernel<<<(256 * 256 + 255) / 256, 256>>>(W2, w2hi, w2lo, 256, 256);
    node_gemm(xhi, xlo, w2hi, w2lo, bufA, N, 256, 256);
    attention(bufA, as2, ad2, b2, h2, 0);
    bnstats(h2, 64, g2, be2);
    bn_apply_kernel<<<(N * 64 + 255) / 256, 256>>>(h2, N * 64, 64, bnsc, bnsh, 0);

    // ---- edge MLP ----
    split_wp_kernel<<<(64 * 256 + 255) / 256, 256>>>(Wm1, wphi, wplo);
    // PQ = h2 @ Wp  (fp32 A converted in-loader)
    {
        dim3 grid((N + 127) / 128, 2);
        hmma_gemm<128, 2, 0><<<grid, 256, SM128>>>(
            nullptr, nullptr, wphi, wplo, bufA, nullptr, nullptr, N, 64, 256,
            h2, nullptr, 0, nullptr, nullptr, nullptr, nullptr, nullptr,
            nullptr, nullptr);
    }

    split_wt_kernel<<<(64 * 128 + 255) / 256, 256>>>(Wm1 + 128 * 128, cthi, ctlo, 64, 128);
    // Y1 (split bf16) = lrelu(|h2[s]-h2[d]| @ C + PQ[s] + PQ[d] + ea*w192 + bm1)
    hmma_gemm<128, 1, 1><<<dim3((E + 127) / 128, 1), 256, SM128>>>(
        nullptr, nullptr, cthi, ctlo, nullptr, y1hi, y1lo, E, 64, 128,
        nullptr, ei, E, h2, bufA, ea, Wm1 + 192 * 128, bm1, nullptr, nullptr);

    split_wt_kernel<<<(128 * 64 + 255) / 256, 256>>>(Wm2, wm2hi, wm2lo, 128, 64);
    // out = lrelu(Y1 @ Wm2 + bm2) . Wm3 + bm3, fused
    hmma_gemm<64, 0, 2><<<dim3((E + 127) / 128, 1), 256, SM64>>>(
        y1hi, y1lo, wm2hi, wm2lo, out, nullptr, nullptr, E, 128, 1,
        nullptr, nullptr, 0, nullptr, nullptr, nullptr, nullptr, bm2, Wm3, bm3);
}

// round 5
// speedup vs baseline: 1.9947x; 1.2017x over previous
#include <cuda_runtime.h>
#include <cuda_bf16.h>
#include <math.h>
#include <stdint.h>

#define NSLOPE 0.2f
#define EPSBN 1e-5f
#define NMAX 50000
#define EMAX 800000
#define TOTMAX (EMAX + NMAX)

// ------------------------------ scratch (device globals; no allocation) ---
__device__ float g_bufA[(size_t)NMAX * 256];
__device__ float g_bufB[(size_t)NMAX * 256];
__device__ float g_h2[(size_t)NMAX * 64];
__device__ float g_asrc[(size_t)NMAX * 4];
__device__ float g_adst[(size_t)NMAX * 4];
__device__ float g_watt[(size_t)TOTMAX * 4];
__device__ int   g_deg[NMAX];
__device__ int   g_off[NMAX + 1];
__device__ int   g_cur[NMAX];
__device__ int   g_csrc[TOTMAX];
__device__ int   g_cdst[TOTMAX];
__device__ float g_stats[512];
__device__ float g_bnsc[256];
__device__ float g_bnsh[256];
// split-bf16 buffers
__device__ __nv_bfloat16 g_xhi[(size_t)NMAX * 256];
__device__ __nv_bfloat16 g_xlo[(size_t)NMAX * 256];
__device__ __nv_bfloat16 g_y1hi[(size_t)EMAX * 128];
__device__ __nv_bfloat16 g_y1lo[(size_t)EMAX * 128];
__device__ __nv_bfloat16 g_w0hi[256 * 128],  g_w0lo[256 * 128];
__device__ __nv_bfloat16 g_w1hi[256 * 256],  g_w1lo[256 * 256];
__device__ __nv_bfloat16 g_w2hi[256 * 256],  g_w2lo[256 * 256];
__device__ __nv_bfloat16 g_wphi[256 * 64],   g_wplo[256 * 64];
__device__ __nv_bfloat16 g_cthi[128 * 64],   g_ctlo[128 * 64];
__device__ __nv_bfloat16 g_wm2hi[64 * 128],  g_wm2lo[64 * 128];

__device__ __forceinline__ float lrelu(float v) { return v > 0.f ? v : NSLOPE * v; }

// ======================= HMMA helpers =====================================
#define SW(o) ((o) ^ (((o) >> 3) & 0x70))

__device__ __forceinline__ uint32_t s2u(const void* p) {
    uint32_t a;
    asm("{ .reg .u64 t; cvta.to.shared.u64 t, %1; cvt.u32.u64 %0, t; }" : "=r"(a) : "l"(p));
    return a;
}

__device__ __forceinline__ void mma_bf16(float* c, const uint32_t* a, const uint32_t* b) {
    asm volatile(
        "mma.sync.aligned.m16n8k16.row.col.f32.bf16.bf16.f32 "
        "{%0,%1,%2,%3}, {%4,%5,%6,%7}, {%8,%9}, {%0,%1,%2,%3};"
        : "+f"(c[0]), "+f"(c[1]), "+f"(c[2]), "+f"(c[3])
        : "r"(a[0]), "r"(a[1]), "r"(a[2]), "r"(a[3]), "r"(b[0]), "r"(b[1]));
}

__device__ __forceinline__ void ldsm4(uint32_t* r, uint32_t addr) {
    asm volatile("ldmatrix.sync.aligned.m8n8.x4.shared.b16 {%0,%1,%2,%3}, [%4];"
                 : "=r"(r[0]), "=r"(r[1]), "=r"(r[2]), "=r"(r[3]) : "r"(addr));
}

__device__ __forceinline__ void ldsm2(uint32_t* r, uint32_t addr) {
    asm volatile("ldmatrix.sync.aligned.m8n8.x2.shared.b16 {%0,%1}, [%2];"
                 : "=r"(r[0]), "=r"(r[1]) : "r"(addr));
}

__device__ __forceinline__ void cpasync16(uint32_t saddr, const void* g) {
    asm volatile("cp.async.cg.shared.global [%0], [%1], 16;" :: "r"(saddr), "l"(g));
}

__device__ __forceinline__ uint32_t bfbits(float v) {
    __nv_bfloat16 b = __float2bfloat16_rn(v);
    return (uint32_t)__bfloat16_as_ushort(b);
}
__device__ __forceinline__ float bfval(uint32_t bits) {
    return __bfloat162float(__ushort_as_bfloat16((unsigned short)bits));
}

// ======================= split-bf16 HMMA GEMM =============================
// Block tile MT x NT (MT*NT == 8192), K-chunk 64, 8 warps of 32x32 tiles.
// acc = Ahi*Bhi + Ahi*Blo + Alo*Bhi (fp32 accumulate).
// ASRC: 0 = pre-split bf16 A, cp.async double-buffered pipeline
//       1 = A[e][k] = |h2[src[e]][k] - h2[dst[e]][k]| gather+split (Kt == 64)
// B: pre-split bf16, layout Bt[n][k] (ldb = Kt), n = global col.
// EPI : 0 = C[m][colBase+n] = acc (fp32)
//       1 = split-bf16 out: lrelu(acc + PQ[s][n] + PQ[d][128+n] + ea*w192 + bm1)
//       2 = out[e] = sum_n lrelu(acc[n] + bm2[n]) * wm3[n] + bm3 (MT=128, NT=64)
template <int MT, int NT, int ASRC, int EPI>
__global__ __launch_bounds__(256, 2) void hmma_gemm(
    const __nv_bfloat16* __restrict__ Ahi, const __nv_bfloat16* __restrict__ Alo,
    const __nv_bfloat16* __restrict__ Bhi, const __nv_bfloat16* __restrict__ Blo,
    float* __restrict__ C, __nv_bfloat16* __restrict__ Chi, __nv_bfloat16* __restrict__ Clo,
    int M, int Kt, int ldc,
    const int* __restrict__ ei, int E, const float* __restrict__ h2g,
    const float* __restrict__ PQ, const float* __restrict__ ea,
    const float* __restrict__ w192, const float* __restrict__ bias,
    const float* __restrict__ wm3, const float* __restrict__ bm3)
{
    extern __shared__ char sm[];
    constexpr int A_HI = 0;
    constexpr int A_LO = MT * 128;
    constexpr int B_HI = 2 * MT * 128;
    constexpr int B_LO = 2 * MT * 128 + NT * 128;
    constexpr int STAGE = 2 * MT * 128 + 2 * NT * 128;   // 48 KB
    constexpr int WM = (MT == 128) ? 4 : 2;              // warps along M

    const uint32_t sb = s2u(sm);
    const int t = threadIdx.x;
    const int wid = t >> 5, lane = t & 31;
    const int rowBase = blockIdx.x * MT;
    const int colBase = blockIdx.y * NT;
    const int mBase = (wid % WM) * 32;
    const int nBase = (wid / WM) * 32;

    float acc[2][4][4];
#pragma unroll
    for (int i = 0; i < 2; i++)
#pragma unroll
        for (int j = 0; j < 4; j++)
#pragma unroll
            for (int q = 0; q < 4; q++) acc[i][j][q] = 0.f;

    auto do_mma = [&](int st) {
        const uint32_t base = sb + st * STAGE;
#pragma unroll
        for (int ks = 0; ks < 4; ks++) {
            const int k0 = ks * 16;
            uint32_t ahi[2][4], alo[2][4];
#pragma unroll
            for (int fi = 0; fi < 2; fi++) {
                int row = mBase + 16 * fi + (lane & 15);
                int bo = SW(row * 128 + (k0 + ((lane >> 4) << 3)) * 2);
                ldsm4(ahi[fi], base + A_HI + bo);
                ldsm4(alo[fi], base + A_LO + bo);
            }
#pragma unroll
            for (int fj = 0; fj < 4; fj++) {
                int row = nBase + 8 * fj + (lane & 7);
                int bo = SW(row * 128 + (k0 + (((lane >> 3) & 1) << 3)) * 2);
                uint32_t bh[2], bl[2];
                ldsm2(bh, base + B_HI + bo);
                ldsm2(bl, base + B_LO + bo);
#pragma unroll
                for (int fi = 0; fi < 2; fi++) {
                    mma_bf16(acc[fi][fj], ahi[fi], bh);
                    mma_bf16(acc[fi][fj], ahi[fi], bl);
                    mma_bf16(acc[fi][fj], alo[fi], bh);
                }
            }
        }
    };

    if (ASRC == 0) {
        auto load_chunk = [&](int kc, int st) {
            const uint32_t base = sb + st * STAGE;
#pragma unroll
            for (int it = 0; it < MT / 32; it++) {
                int idx = t + it * 256;
                int r = idx >> 3, q = idx & 7;
                int gm = rowBase + r; if (gm >= M) gm = 0;
                size_t goff = (size_t)gm * Kt + kc + q * 8;
                uint32_t sa = base + A_HI + SW(r * 128 + q * 16);
                cpasync16(sa, Ahi + goff);
                cpasync16(sa + (A_LO - A_HI), Alo + goff);
            }
#pragma unroll
            for (int it = 0; it < NT / 32; it++) {
                int idx = t + it * 256;
                int n = idx >> 3, q = idx & 7;
                size_t goff = (size_t)(colBase + n) * Kt + kc + q * 8;
                uint32_t sa = base + B_HI + SW(n * 128 + q * 16);
                cpasync16(sa, Bhi + goff);
                cpasync16(sa + (B_LO - B_HI), Blo + goff);
            }
            asm volatile("cp.async.commit_group;" ::: "memory");
        };
        const int nch = Kt >> 6;
        load_chunk(0, 0);
        for (int i = 0; i < nch; i++) {
            if (i + 1 < nch) {
                load_chunk((i + 1) << 6, (i + 1) & 1);
                asm volatile("cp.async.wait_group 1;" ::: "memory");
            } else {
                asm volatile("cp.async.wait_group 0;" ::: "memory");
            }
            __syncthreads();
            do_mma(i & 1);
            __syncthreads();
        }
    } else {
        // single K=64 chunk: gather |h2[s]-h2[d]|, split in-loader; B via plain loads
#pragma unroll
        for (int it = 0; it < MT / 16; it++) {
            int idx = t + it * 256;          // MT rows x 16 float4s
            int r = idx >> 4, q = idx & 15;
            int e = rowBase + r; if (e >= M) e = 0;
            int s = ei[e], d = ei[E + e];
            float4 a4 = *(const float4*)(h2g + (size_t)s * 64 + q * 4);
            float4 b4 = *(const float4*)(h2g + (size_t)d * 64 + q * 4);
            float4 v = make_float4(fabsf(a4.x - b4.x), fabsf(a4.y - b4.y),
                                   fabsf(a4.z - b4.z), fabsf(a4.w - b4.w));
            uint32_t hx = bfbits(v.x), hy = bfbits(v.y), hz = bfbits(v.z), hw = bfbits(v.w);
            uint32_t lx = bfbits(v.x - bfval(hx)), ly = bfbits(v.y - bfval(hy));
            uint32_t lz = bfbits(v.z - bfval(hz)), lw = bfbits(v.w - bfval(hw));
            int so = SW(r * 128 + q * 8);
            *(uint2*)(sm + A_HI + so) = make_uint2(hx | (hy << 16), hz | (hw << 16));
            *(uint2*)(sm + A_LO + so) = make_uint2(lx | (ly << 16), lz | (lw << 16));
        }
#pragma unroll
        for (int it = 0; it < NT / 32; it++) {
            int idx = t + it * 256;
            int n = idx >> 3, q = idx & 7;
            size_t goff = (size_t)(colBase + n) * Kt + q * 8;
            int so = SW(n * 128 + q * 16);
            *(uint4*)(sm + B_HI + so) = *(const uint4*)(Bhi + goff);
            *(uint4*)(sm + B_LO + so) = *(const uint4*)(Blo + goff);
        }
        __syncthreads();
        do_mma(0);
    }

    // ---- epilogue ----
    if (EPI == 0) {
#pragma unroll
        for (int fi = 0; fi < 2; fi++) {
            int r0 = rowBase + mBase + 16 * fi + (lane >> 2);
#pragma unroll
            for (int fj = 0; fj < 4; fj++) {
                int c = colBase + nBase + 8 * fj + (lane & 3) * 2;
                if (r0 < M)
                    *(float2*)(C + (size_t)r0 * ldc + c) =
                        make_float2(acc[fi][fj][0], acc[fi][fj][1]);
                if (r0 + 8 < M)
                    *(float2*)(C + (size_t)(r0 + 8) * ldc + c) =
                        make_float2(acc[fi][fj][2], acc[fi][fj][3]);
            }
        }
    } else if (EPI == 1) {
#pragma unroll
        for (int fi = 0; fi < 2; fi++) {
#pragma unroll
            for (int half = 0; half < 2; half++) {
                int r = rowBase + mBase + 16 * fi + (lane >> 2) + half * 8;
                if (r >= M) continue;
                int s = ei[r], d = ei[E + r];
                float eav = ea[r];
                const float* pqs = PQ + (size_t)s * 256;
                const float* pqd = PQ + (size_t)d * 256 + 128;
#pragma unroll
                for (int fj = 0; fj < 4; fj++) {
                    int c = colBase + nBase + 8 * fj + (lane & 3) * 2;
                    float2 p1 = *(const float2*)(pqs + c);
                    float2 p2 = *(const float2*)(pqd + c);
                    float2 wv = *(const float2*)(w192 + c);
                    float2 bv = *(const float2*)(bias + c);
                    float v0 = lrelu(acc[fi][fj][half * 2 + 0] + p1.x + p2.x + eav * wv.x + bv.x);
                    float v1 = lrelu(acc[fi][fj][half * 2 + 1] + p1.y + p2.y + eav * wv.y + bv.y);
                    __nv_bfloat16 h0 = __float2bfloat16_rn(v0);
                    __nv_bfloat16 h1 = __float2bfloat16_rn(v1);
                    __nv_bfloat16 l0 = __float2bfloat16_rn(v0 - __bfloat162float(h0));
                    __nv_bfloat16 l1 = __float2bfloat16_rn(v1 - __bfloat162float(h1));
                    __nv_bfloat162 hp; hp.x = h0; hp.y = h1;
                    __nv_bfloat162 lp; lp.x = l0; lp.y = l1;
                    *(__nv_bfloat162*)(Chi + (size_t)r * 128 + c) = hp;
                    *(__nv_bfloat162*)(Clo + (size_t)r * 128 + c) = lp;
                }
            }
        }
    } else {  // EPI == 2, MT=128, NT=64: fused final dot
        __syncthreads();
        float* st = (float*)sm;        // [128][65]
#pragma unroll
        for (int fi = 0; fi < 2; fi++) {
            int lr = mBase + 16 * fi + (lane >> 2);
#pragma unroll
            for (int fj = 0; fj < 4; fj++) {
                int c = nBase + 8 * fj + (lane & 3) * 2;
                st[lr * 65 + c] = acc[fi][fj][0];
                st[lr * 65 + c + 1] = acc[fi][fj][1];
                st[(lr + 8) * 65 + c] = acc[fi][fj][2];
                st[(lr + 8) * 65 + c + 1] = acc[fi][fj][3];
            }
        }
        __syncthreads();
        int row = wid * 16 + (lane >> 1);
        int half = lane & 1;
        float ssum = 0.f;
#pragma unroll
        for (int i = 0; i < 32; i++) {
            int c = half * 32 + i;
            float v = st[row * 65 + c];
            v = lrelu(v + bias[c]);
            ssum += v * wm3[c];
        }
        ssum += __shfl_xor_sync(0xffffffffu, ssum, 1);
        int gm = rowBase + row;
        if (half == 0 && gm < M) C[gm] = ssum + bm3[0];
    }
}

// ------------------------------ split / prep kernels ----------------------
__global__ void split_act_kernel(const float* __restrict__ X,
                                 __nv_bfloat16* __restrict__ hi, __nv_bfloat16* __restrict__ lo,
                                 int n, int colsMask,
                                 const float* __restrict__ sc, const float* __restrict__ sh)
{
    int i = blockIdx.x * blockDim.x + threadIdx.x;
    if (i >= n) return;
    float v = X[i];
    if (sc) {
        int c = i & colsMask;
        v = lrelu(v * sc[c] + sh[c]);
    }
    __nv_bfloat16 h = __float2bfloat16_rn(v);
    hi[i] = h;
    lo[i] = __float2bfloat16_rn(v - __bfloat162float(h));
}

__global__ void split_wt_kernel(const float* __restrict__ W,
                                __nv_bfloat16* __restrict__ hi, __nv_bfloat16* __restrict__ lo,
                                int K, int C)
{
    int i = blockIdx.x * blockDim.x + threadIdx.x;
    if (i >= K * C) return;
    int k = i / C, c = i % C;
    float v = W[i];
    __nv_bfloat16 h = __float2bfloat16_rn(v);
    hi[(size_t)c * K + k] = h;
    lo[(size_t)c * K + k] = __float2bfloat16_rn(v - __bfloat162float(h));
}

__global__ void split_wp_kernel(const float* __restrict__ Wm1,
                                __nv_bfloat16* __restrict__ hi, __nv_bfloat16* __restrict__ lo)
{
    int i = blockIdx.x * blockDim.x + threadIdx.x;
    if (i >= 64 * 256) return;
    int c = i >> 6, k = i & 63;
    float v = (c < 128) ? Wm1[k * 128 + c] : Wm1[(64 + k) * 128 + (c - 128)];
    __nv_bfloat16 h = __float2bfloat16_rn(v);
    hi[i] = h;
    lo[i] = __float2bfloat16_rn(v - __bfloat162float(h));
}

// ------------------------------ CSR build ---------------------------------
__global__ void init_deg_kernel(int* __restrict__ deg, int n)
{
    int i = blockIdx.x * blockDim.x + threadIdx.x;
    if (i < n) deg[i] = 1;
}

__global__ void count_kernel(const int* __restrict__ ei, int E, int* __restrict__ deg)
{
    int i = blockIdx.x * blockDim.x + threadIdx.x;
    if (i < E) atomicAdd(&deg[ei[E + i]], 1);
}

__global__ void scan_kernel(const int* __restrict__ deg, int* __restrict__ off, int n)
{
    __shared__ int sh[1024];
    __shared__ int carry_s;
    int t = threadIdx.x;
    if (t == 0) carry_s = 0;
    __syncthreads();
    for (int base = 0; base < n; base += 1024) {
        int i = base + t;
        int v = (i < n) ? deg[i] : 0;
        sh[t] = v;
        __syncthreads();
        int sum = v;
        for (int ofs = 1; ofs < 1024; ofs <<= 1) {
            int add = (t >= ofs) ? sh[t - ofs] : 0;
            __syncthreads();
            sum += add;
            sh[t] = sum;
            __syncthreads();
        }
        int carry = carry_s;
        if (i < n) off[i] = carry + sum - v;
        __syncthreads();
        if (t == 1023) carry_s = carry + sum;
        __syncthreads();
    }
    if (t == 0) off[n] = carry_s;
}

__global__ void copy_cur_kernel(const int* __restrict__ off, int* __restrict__ cur, int n)
{
    int i = blockIdx.x * blockDim.x + threadIdx.x;
    if (i < n) cur[i] = off[i];
}

__global__ void scatter_edges_kernel(const int* __restrict__ ei, int E,
                                     int* __restrict__ cur,
                                     int* __restrict__ csrc, int* __restrict__ cdst)
{
    int i = blockIdx.x * blockDim.x + threadIdx.x;
    if (i >= E) return;
    int d = ei[E + i];
    int pos = atomicAdd(&cur[d], 1);
    csrc[pos] = ei[i];
    cdst[pos] = d;
}

__global__ void scatter_loops_kernel(int N, int* __restrict__ cur,
                                     int* __restrict__ csrc, int* __restrict__ cdst)
{
    int n = blockIdx.x * blockDim.x + threadIdx.x;
    if (n >= N) return;
    int pos = atomicAdd(&cur[n], 1);
    csrc[pos] = n;
    cdst[pos] = n;
}

// ------------------------------ GAT attention -----------------------------
__global__ void alpha_kernel(const float* __restrict__ h,
                             const float* __restrict__ aw_s, const float* __restrict__ aw_d,
                             float* __restrict__ asrc, float* __restrict__ adst, int N)
{
    int id = blockIdx.x * blockDim.x + threadIdx.x;
    if (id >= N * 4) return;
    int n = id >> 2, hh = id & 3;
    const float4* row = (const float4*)(h + (size_t)n * 256 + hh * 64);
    const float4* ws  = (const float4*)(aw_s + hh * 64);
    const float4* wd  = (const float4*)(aw_d + hh * 64);
    float sa = 0.f, sb = 0.f;
#pragma unroll
    for (int q = 0; q < 16; q++) {
        float4 v = row[q];
        float4 a = ws[q], b = wd[q];
        sa += v.x * a.x + v.y * a.y + v.z * a.z + v.w * a.w;
        sb += v.x * b.x + v.y * b.y + v.z * b.z + v.w * b.w;
    }
    asrc[id] = sa;
    adst[id] = sb;
}

// fused segment-max + exp weight (warp per dst node; 2nd pass hits L1)
__global__ void maxwatt_kernel(const float4* __restrict__ asrc4, const float4* __restrict__ adst4,
                               const int* __restrict__ off, const int* __restrict__ csrc,
                               float4* __restrict__ watt4, int N)
{
    int w = (blockIdx.x * blockDim.x + threadIdx.x) >> 5;
    int lane = threadIdx.x & 31;
    if (w >= N) return;
    float4 ad = adst4[w];
    int lo = off[w], hi = off[w + 1];
    float m0 = -1e30f, m1 = -1e30f, m2 = -1e30f, m3 = -1e30f;
    for (int p = lo + lane; p < hi; p += 32) {
        int s = csrc[p];
        float4 as = asrc4[s];
        m0 = fmaxf(m0, lrelu(as.x + ad.x));
        m1 = fmaxf(m1, lrelu(as.y + ad.y));
        m2 = fmaxf(m2, lrelu(as.z + ad.z));
        m3 = fmaxf(m3, lrelu(as.w + ad.w));
    }
#pragma unroll
    for (int o = 16; o > 0; o >>= 1) {
        m0 = fmaxf(m0, __shfl_xor_sync(0xffffffffu, m0, o));
        m1 = fmaxf(m1, __shfl_xor_sync(0xffffffffu, m1, o));
        m2 = fmaxf(m2, __shfl_xor_sync(0xffffffffu, m2, o));
        m3 = fmaxf(m3, __shfl_xor_sync(0xffffffffu, m3, o));
    }
    for (int p = lo + lane; p < hi; p += 32) {
        int s = csrc[p];
        float4 as = asrc4[s];
        watt4[p] = make_float4(expf(lrelu(as.x + ad.x) - m0),
                               expf(lrelu(as.y + ad.y) - m1),
                               expf(lrelu(as.z + ad.z) - m2),
                               expf(lrelu(as.w + ad.w) - m3));
    }
}

__global__ __launch_bounds__(128) void gat_aggregate_kernel(
    const float* __restrict__ h, const float* __restrict__ watt,
    const int* __restrict__ off, const int* __restrict__ csrc,
    const float* __restrict__ bias, float* __restrict__ out, int concat)
{
    int d = blockIdx.x;
    int t = threadIdx.x;            // 128
    int c = t * 2;
    int hh = t >> 5;
    int lo = off[d], hi = off[d + 1];
    float accx = 0.f, accy = 0.f, den = 0.f;
    int s_n = csrc[lo];
    float w_n = watt[lo * 4 + hh];
    for (int p = lo; p < hi; ++p) {
        int s = s_n;
        float w = w_n;
        int pn = p + 1;
        if (pn < hi) { s_n = csrc[pn]; w_n = watt[pn * 4 + hh]; }
        float2 hv = *(const float2*)(h + (size_t)s * 256 + c);
        den += w;
        accx += w * hv.x;
        accy += w * hv.y;
    }
    float inv = 1.f / den;
    accx *= inv; accy *= inv;
    if (concat) {
        *(float2*)(out + (size_t)d * 256 + c) =
            make_float2(accx + bias[c], accy + bias[c + 1]);
    } else {
        __shared__ float red[256];
        red[c] = accx; red[c + 1] = accy;
        __syncthreads();
        if (t < 32) {
#pragma unroll
            for (int j = 0; j < 2; j++) {
                int cc = t * 2 + j;
                out[(size_t)d * 64 + cc] =
                    0.25f * (red[cc] + red[cc + 64] + red[cc + 128] + red[cc + 192]) + bias[cc];
            }
        }
    }
}

// ------------------------------ BatchNorm ---------------------------------
__global__ void zero_kernel(float* __restrict__ p, int n)
{
    int i = blockIdx.x * blockDim.x + threadIdx.x;
    if (i < n) p[i] = 0.f;
}

__global__ void bn_stats_kernel(const float* __restrict__ X, int rows, int cols,
                                float* __restrict__ stats, int rowsPerBlock)
{
    int t = threadIdx.x;
    int c = t % cols;
    int rsub = t / cols;
    int rstep = 256 / cols;
    int r0 = blockIdx.x * rowsPerBlock;
    int r1 = r0 + rowsPerBlock; if (r1 > rows) r1 = rows;
    float s = 0.f, s2 = 0.f;
    for (int r = r0 + rsub; r < r1; r += rstep) {
        float v = X[(size_t)r * cols + c];
        s += v;
        s2 += v * v;
    }
    atomicAdd(&stats[c], s);
    atomicAdd(&stats[cols + c], s2);
}

__global__ void bn_final_kernel(const float* __restrict__ stats,
                                const float* __restrict__ g, const float* __restrict__ be,
                                int rows, int cols,
                                float* __restrict__ sc, float* __restrict__ sh)
{
    int c = threadIdx.x;
    if (c >= cols) return;
    float inv = 1.f / (float)rows;
    float mean = stats[c] * inv;
    float var = stats[cols + c] * inv - mean * mean;
    float scale = g[c] * rsqrtf(var + EPSBN);
    sc[c] = scale;
    sh[c] = be[c] - mean * scale;
}

__global__ void bn_apply_kernel(float* __restrict__ X, int n, int cols,
                                const float* __restrict__ sc, const float* __restrict__ sh,
                                int act)
{
    int i = blockIdx.x * blockDim.x + threadIdx.x;
    if (i >= n) return;
    int c = i % cols;
    float v = X[i] * sc[c] + sh[c];
    if (act) v = lrelu(v);
    X[i] = v;
}

// ------------------------------ host orchestration ------------------------
extern "C" void kernel_launch(void* const* d_in, const int* in_sizes, int n_in,
                              void* d_out, int out_size)
{
    const float* x  = (const float*)d_in[0];
    const int*   ei = (const int*)d_in[1];
    const float* ea = (const float*)d_in[2];
    const int N = in_sizes[0] / 128;
    const int E = in_sizes[2];

    const float *W0, *as0, *ad0, *b0, *g0, *be0;
    const float *W1, *as1, *ad1, *b1, *g1, *be1;
    const float *W2, *as2, *ad2, *b2, *g2, *be2;
    if (in_sizes[7] == 256 * 256) {
        W0 = (const float*)d_in[3];  as0 = (const float*)d_in[4];  ad0 = (const float*)d_in[5];  b0 = (const float*)d_in[6];
        W1 = (const float*)d_in[7];  as1 = (const float*)d_in[8];  ad1 = (const float*)d_in[9];  b1 = (const float*)d_in[10];
        W2 = (const float*)d_in[11]; as2 = (const float*)d_in[12]; ad2 = (const float*)d_in[13]; b2 = (const float*)d_in[14];
        g0 = (const float*)d_in[15]; be0 = (const float*)d_in[16];
        g1 = (const float*)d_in[17]; be1 = (const float*)d_in[18];
        g2 = (const float*)d_in[19]; be2 = (const float*)d_in[20];
    } else {
        W0 = (const float*)d_in[3];  as0 = (const float*)d_in[4];  ad0 = (const float*)d_in[5];  b0 = (const float*)d_in[6];
        g0 = (const float*)d_in[7];  be0 = (const float*)d_in[8];
        W1 = (const float*)d_in[9];  as1 = (const float*)d_in[10]; ad1 = (const float*)d_in[11]; b1 = (const float*)d_in[12];
        g1 = (const float*)d_in[13]; be1 = (const float*)d_in[14];
        W2 = (const float*)d_in[15]; as2 = (const float*)d_in[16]; ad2 = (const float*)d_in[17]; b2 = (const float*)d_in[18];
        g2 = (const float*)d_in[19]; be2 = (const float*)d_in[20];
    }
    const float* Wm1 = (const float*)d_in[21];
    const float* bm1 = (const float*)d_in[22];
    const float* Wm2 = (const float*)d_in[23];
    const float* bm2 = (const float*)d_in[24];
    const float* Wm3 = (const float*)d_in[25];
    const float* bm3 = (const float*)d_in[26];
    float* out = (float*)d_out;

    float *bufA, *bufB, *h2, *asrc, *adst, *watt, *stats, *bnsc, *bnsh;
    int *deg, *off, *cur, *csrc, *cdst;
    __nv_bfloat16 *xhi, *xlo, *y1hi, *y1lo;
    __nv_bfloat16 *w0hi, *w0lo, *w1hi, *w1lo, *w2hi, *w2lo;
    __nv_bfloat16 *wphi, *wplo, *cthi, *ctlo, *wm2hi, *wm2lo;
    cudaGetSymbolAddress((void**)&bufA, g_bufA);
    cudaGetSymbolAddress((void**)&bufB, g_bufB);
    cudaGetSymbolAddress((void**)&h2, g_h2);
    cudaGetSymbolAddress((void**)&asrc, g_asrc);
    cudaGetSymbolAddress((void**)&adst, g_adst);
    cudaGetSymbolAddress((void**)&watt, g_watt);
    cudaGetSymbolAddress((void**)&stats, g_stats);
    cudaGetSymbolAddress((void**)&bnsc, g_bnsc);
    cudaGetSymbolAddress((void**)&bnsh, g_bnsh);
    cudaGetSymbolAddress((void**)&deg, g_deg);
    cudaGetSymbolAddress((void**)&off, g_off);
    cudaGetSymbolAddress((void**)&cur, g_cur);
    cudaGetSymbolAddress((void**)&csrc, g_csrc);
    cudaGetSymbolAddress((void**)&cdst, g_cdst);
    cudaGetSymbolAddress((void**)&xhi, g_xhi);
    cudaGetSymbolAddress((void**)&xlo, g_xlo);
    cudaGetSymbolAddress((void**)&y1hi, g_y1hi);
    cudaGetSymbolAddress((void**)&y1lo, g_y1lo);
    cudaGetSymbolAddress((void**)&w0hi, g_w0hi);  cudaGetSymbolAddress((void**)&w0lo, g_w0lo);
    cudaGetSymbolAddress((void**)&w1hi, g_w1hi);  cudaGetSymbolAddress((void**)&w1lo, g_w1lo);
    cudaGetSymbolAddress((void**)&w2hi, g_w2hi);  cudaGetSymbolAddress((void**)&w2lo, g_w2lo);
    cudaGetSymbolAddress((void**)&wphi, g_wphi);  cudaGetSymbolAddress((void**)&wplo, g_wplo);
    cudaGetSymbolAddress((void**)&cthi, g_cthi);  cudaGetSymbolAddress((void**)&ctlo, g_ctlo);
    cudaGetSymbolAddress((void**)&wm2hi, g_wm2hi); cudaGetSymbolAddress((void**)&wm2lo, g_wm2lo);

    const int STAGE = 48 * 1024;
    const int SM2 = 2 * STAGE;
    cudaFuncSetAttribute(hmma_gemm<128, 64, 0, 0>, cudaFuncAttributeMaxDynamicSharedMemorySize, SM2);
    cudaFuncSetAttribute(hmma_gemm<64, 128, 1, 1>, cudaFuncAttributeMaxDynamicSharedMemorySize, STAGE);
    cudaFuncSetAttribute(hmma_gemm<128, 64, 0, 2>, cudaFuncAttributeMaxDynamicSharedMemorySize, SM2);

    auto node_gemm = [&](const __nv_bfloat16* Ah, const __nv_bfloat16* Al,
                         const __nv_bfloat16* Bh, const __nv_bfloat16* Bl,
                         float* C, int M, int Kt, int Ncols) {
        dim3 grid((M + 127) / 128, Ncols / 64);
        int smem = (Kt > 64) ? SM2 : STAGE;
        hmma_gemm<128, 64, 0, 0><<<grid, 256, smem>>>(
            Ah, Al, Bh, Bl, C, nullptr, nullptr, M, Kt, Ncols,
            nullptr, 0, nullptr, nullptr, nullptr, nullptr, nullptr,
            nullptr, nullptr);
    };

    // ---- launches 1-4 ordered so the profiled launch (#4) is the L0 GEMM ----
    split_act_kernel<<<(N * 128 + 255) / 256, 256>>>(x, xhi, xlo, N * 128, 127, nullptr, nullptr);
    split_wt_kernel<<<(128 * 256 + 255) / 256, 256>>>(W0, w0hi, w0lo, 128, 256);
    init_deg_kernel<<<(N + 255) / 256, 256>>>(deg, N);
    node_gemm(xhi, xlo, w0hi, w0lo, bufA, N, 128, 256);          // launch #4

    // ---- rest of CSR build ----
    count_kernel<<<(E + 255) / 256, 256>>>(ei, E, deg);
    scan_kernel<<<1, 1024>>>(deg, off, N);
    copy_cur_kernel<<<(N + 255) / 256, 256>>>(off, cur, N);
    scatter_edges_kernel<<<(E + 255) / 256, 256>>>(ei, E, cur, csrc, cdst);
    scatter_loops_kernel<<<(N + 255) / 256, 256>>>(N, cur, csrc, cdst);

    auto attention = [&](const float* hbuf, const float* aws, const float* awd,
                         const float* bias, float* outbuf, int concat) {
        alpha_kernel<<<(N * 4 + 255) / 256, 256>>>(hbuf, aws, awd, asrc, adst, N);
        maxwatt_kernel<<<(N * 32 + 255) / 256, 256>>>((const float4*)asrc, (const float4*)adst,
                                                      off, csrc, (float4*)watt, N);
        gat_aggregate_kernel<<<N, 128>>>(hbuf, watt, off, csrc, bias, outbuf, concat);
    };

    auto bnstats = [&](const float* X, int cols, const float* g, const float* be) {
        zero_kernel<<<1, 512>>>(stats, 2 * cols);
        bn_stats_kernel<<<(N + 255) / 256, 256>>>(X, N, cols, stats, 256);
        bn_final_kernel<<<1, cols>>>(stats, g, be, N, cols, bnsc, bnsh);
    };

    // ---- layer 0 ----
    attention(bufA, as0, ad0, b0, bufB, 1);
    bnstats(bufB, 256, g0, be0);
    split_act_kernel<<<(N * 256 + 255) / 256, 256>>>(bufB, xhi, xlo, N * 256, 255, bnsc, bnsh);

    // ---- layer 1 ----
    split_wt_kernel<<<(256 * 256 + 255) / 256, 256>>>(W1, w1hi, w1lo, 256, 256);
    node_gemm(xhi, xlo, w1hi, w1lo, bufA, N, 256, 256);
    attention(bufA, as1, ad1, b1, bufB, 1);
    bnstats(bufB, 256, g1, be1);
    split_act_kernel<<<(N * 256 + 255) / 256, 256>>>(bufB, xhi, xlo, N * 256, 255, bnsc, bnsh);

    // ---- layer 2 ----
    split_wt_kernel<<<(256 * 256 + 255) / 256, 256>>>(W2, w2hi, w2lo, 256, 256);
    node_gemm(xhi, xlo, w2hi, w2lo, bufA, N, 256, 256);
    attention(bufA, as2, ad2, b2, h2, 0);
    bnstats(h2, 64, g2, be2);
    bn_apply_kernel<<<(N * 64 + 255) / 256, 256>>>(h2, N * 64, 64, bnsc, bnsh, 0);
    // split h2 for the PQ GEMM (reuses xhi/xlo front)
    split_act_kernel<<<(N * 64 + 255) / 256, 256>>>(h2, xhi, xlo, N * 64, 63, nullptr, nullptr);

    // ---- edge MLP ----
    split_wp_kernel<<<(64 * 256 + 255) / 256, 256>>>(Wm1, wphi, wplo);
    node_gemm(xhi, xlo, wphi, wplo, bufA, N, 64, 256);   // bufA = PQ (N x 256)

    split_wt_kernel<<<(64 * 128 + 255) / 256, 256>>>(Wm1 + 128 * 128, cthi, ctlo, 64, 128);
    // Y1 (split bf16) = lrelu(|h2[s]-h2[d]| @ C + PQ[s] + PQ[d] + ea*w192 + bm1)
    hmma_gemm<64, 128, 1, 1><<<dim3((E + 63) / 64, 1), 256, STAGE>>>(
        nullptr, nullptr, cthi, ctlo, nullptr, y1hi, y1lo, E, 64, 128,
        ei, E, h2, bufA, ea, Wm1 + 192 * 128, bm1, nullptr, nullptr);

    split_wt_kernel<<<(128 * 64 + 255) / 256, 256>>>(Wm2, wm2hi, wm2lo, 128, 64);
    // out = lrelu(Y1 @ Wm2 + bm2) . Wm3 + bm3, fused
    hmma_gemm<128, 64, 0, 2><<<dim3((E + 127) / 128, 1), 256, SM2>>>(
        y1hi, y1lo, wm2hi, wm2lo, out, nullptr, nullptr, E, 128, 1,
        nullptr, 0, nullptr, nullptr, nullptr, nullptr, bm2, Wm3, bm3);
}

// round 6
// speedup vs baseline: 2.3320x; 1.1691x over previous
#include <cuda_runtime.h>
#include <cuda_bf16.h>
#include <math.h>
#include <stdint.h>

#define NSLOPE 0.2f
#define EPSBN 1e-5f
#define NMAX 50000
#define EMAX 800000
#define TOTMAX (EMAX + NMAX)

// ------------------------------ scratch (device globals; no allocation) ---
__device__ float g_bufA[(size_t)NMAX * 256];
__device__ float g_bufB[(size_t)NMAX * 256];
__device__ float g_h2[(size_t)NMAX * 64];
__device__ float g_asrc[(size_t)NMAX * 4];
__device__ float g_adst[(size_t)NMAX * 4];
__device__ float g_watt[(size_t)TOTMAX * 4];
__device__ int   g_deg[NMAX];
__device__ int   g_off[NMAX + 1];
__device__ int   g_cur[NMAX];
__device__ int   g_csrc[TOTMAX];
__device__ int   g_cdst[TOTMAX];
__device__ float g_stats[512];
__device__ float g_bnsc[256];
__device__ float g_bnsh[256];
// split-bf16 buffers
__device__ __nv_bfloat16 g_xhi[(size_t)NMAX * 256];
__device__ __nv_bfloat16 g_xlo[(size_t)NMAX * 256];
__device__ __nv_bfloat16 g_w0hi[256 * 128],  g_w0lo[256 * 128];
__device__ __nv_bfloat16 g_w1hi[256 * 256],  g_w1lo[256 * 256];
__device__ __nv_bfloat16 g_w2hi[256 * 256],  g_w2lo[256 * 256];
__device__ __nv_bfloat16 g_wphi[256 * 64],   g_wplo[256 * 64];
__device__ __nv_bfloat16 g_cthi[128 * 64],   g_ctlo[128 * 64];
__device__ __nv_bfloat16 g_wm2hi[64 * 128],  g_wm2lo[64 * 128];

__device__ __forceinline__ float lrelu(float v) { return v > 0.f ? v : NSLOPE * v; }

// ======================= HMMA helpers =====================================
#define SW(o) ((o) ^ (((o) >> 3) & 0x70))

__device__ __forceinline__ uint32_t s2u(const void* p) {
    uint32_t a;
    asm("{ .reg .u64 t; cvta.to.shared.u64 t, %1; cvt.u32.u64 %0, t; }" : "=r"(a) : "l"(p));
    return a;
}

__device__ __forceinline__ void mma_bf16(float* c, const uint32_t* a, const uint32_t* b) {
    asm volatile(
        "mma.sync.aligned.m16n8k16.row.col.f32.bf16.bf16.f32 "
        "{%0,%1,%2,%3}, {%4,%5,%6,%7}, {%8,%9}, {%0,%1,%2,%3};"
        : "+f"(c[0]), "+f"(c[1]), "+f"(c[2]), "+f"(c[3])
        : "r"(a[0]), "r"(a[1]), "r"(a[2]), "r"(a[3]), "r"(b[0]), "r"(b[1]));
}

__device__ __forceinline__ void ldsm4(uint32_t* r, uint32_t addr) {
    asm volatile("ldmatrix.sync.aligned.m8n8.x4.shared.b16 {%0,%1,%2,%3}, [%4];"
                 : "=r"(r[0]), "=r"(r[1]), "=r"(r[2]), "=r"(r[3]) : "r"(addr));
}

__device__ __forceinline__ void ldsm2(uint32_t* r, uint32_t addr) {
    asm volatile("ldmatrix.sync.aligned.m8n8.x2.shared.b16 {%0,%1}, [%2];"
                 : "=r"(r[0]), "=r"(r[1]) : "r"(addr));
}

__device__ __forceinline__ void cpasync16(uint32_t saddr, const void* g) {
    asm volatile("cp.async.cg.shared.global [%0], [%1], 16;" :: "r"(saddr), "l"(g));
}

__device__ __forceinline__ uint32_t bfbits(float v) {
    __nv_bfloat16 b = __float2bfloat16_rn(v);
    return (uint32_t)__bfloat16_as_ushort(b);
}
__device__ __forceinline__ float bfval(uint32_t bits) {
    return __bfloat162float(__ushort_as_bfloat16((unsigned short)bits));
}

// ======================= split-bf16 HMMA node GEMM ========================
// Block tile 128 x 64, K-chunk 64, 8 warps of 32x32, cp.async double-buffer.
// acc = Ahi*Bhi + Ahi*Blo + Alo*Bhi (fp32 accumulate).
__global__ __launch_bounds__(256, 2) void hmma_gemm(
    const __nv_bfloat16* __restrict__ Ahi, const __nv_bfloat16* __restrict__ Alo,
    const __nv_bfloat16* __restrict__ Bhi, const __nv_bfloat16* __restrict__ Blo,
    float* __restrict__ C, int M, int Kt, int ldc)
{
    extern __shared__ char sm[];
    constexpr int A_HI = 0;
    constexpr int A_LO = 128 * 128;
    constexpr int B_HI = 2 * 128 * 128;
    constexpr int B_LO = 2 * 128 * 128 + 64 * 128;
    constexpr int STAGE = 2 * 128 * 128 + 2 * 64 * 128;   // 48 KB

    const uint32_t sb = s2u(sm);
    const int t = threadIdx.x;
    const int wid = t >> 5, lane = t & 31;
    const int rowBase = blockIdx.x * 128;
    const int colBase = blockIdx.y * 64;
    const int mBase = (wid & 3) * 32;
    const int nBase = (wid >> 2) * 32;

    float acc[2][4][4];
#pragma unroll
    for (int i = 0; i < 2; i++)
#pragma unroll
        for (int j = 0; j < 4; j++)
#pragma unroll
            for (int q = 0; q < 4; q++) acc[i][j][q] = 0.f;

    auto do_mma = [&](int st) {
        const uint32_t base = sb + st * STAGE;
#pragma unroll
        for (int ks = 0; ks < 4; ks++) {
            const int k0 = ks * 16;
            uint32_t ahi[2][4], alo[2][4];
#pragma unroll
            for (int fi = 0; fi < 2; fi++) {
                int row = mBase + 16 * fi + (lane & 15);
                int bo = SW(row * 128 + (k0 + ((lane >> 4) << 3)) * 2);
                ldsm4(ahi[fi], base + A_HI + bo);
                ldsm4(alo[fi], base + A_LO + bo);
            }
#pragma unroll
            for (int fj = 0; fj < 4; fj++) {
                int row = nBase + 8 * fj + (lane & 7);
                int bo = SW(row * 128 + (k0 + (((lane >> 3) & 1) << 3)) * 2);
                uint32_t bh[2], bl[2];
                ldsm2(bh, base + B_HI + bo);
                ldsm2(bl, base + B_LO + bo);
#pragma unroll
                for (int fi = 0; fi < 2; fi++) {
                    mma_bf16(acc[fi][fj], ahi[fi], bh);
                    mma_bf16(acc[fi][fj], ahi[fi], bl);
                    mma_bf16(acc[fi][fj], alo[fi], bh);
                }
            }
        }
    };

    auto load_chunk = [&](int kc, int st) {
        const uint32_t base = sb + st * STAGE;
#pragma unroll
        for (int it = 0; it < 4; it++) {
            int idx = t + it * 256;
            int r = idx >> 3, q = idx & 7;
            int gm = rowBase + r; if (gm >= M) gm = 0;
            size_t goff = (size_t)gm * Kt + kc + q * 8;
            uint32_t sa = base + A_HI + SW(r * 128 + q * 16);
            cpasync16(sa, Ahi + goff);
            cpasync16(sa + (A_LO - A_HI), Alo + goff);
        }
#pragma unroll
        for (int it = 0; it < 2; it++) {
            int idx = t + it * 256;
            int n = idx >> 3, q = idx & 7;
            size_t goff = (size_t)(colBase + n) * Kt + kc + q * 8;
            uint32_t sa = base + B_HI + SW(n * 128 + q * 16);
            cpasync16(sa, Bhi + goff);
            cpasync16(sa + (B_LO - B_HI), Blo + goff);
        }
        asm volatile("cp.async.commit_group;" ::: "memory");
    };

    const int nch = Kt >> 6;
    load_chunk(0, 0);
    for (int i = 0; i < nch; i++) {
        if (i + 1 < nch) {
            load_chunk((i + 1) << 6, (i + 1) & 1);
            asm volatile("cp.async.wait_group 1;" ::: "memory");
        } else {
            asm volatile("cp.async.wait_group 0;" ::: "memory");
        }
        __syncthreads();
        do_mma(i & 1);
        __syncthreads();
    }

#pragma unroll
    for (int fi = 0; fi < 2; fi++) {
        int r0 = rowBase + mBase + 16 * fi + (lane >> 2);
#pragma unroll
        for (int fj = 0; fj < 4; fj++) {
            int c = colBase + nBase + 8 * fj + (lane & 3) * 2;
            if (r0 < M)
                *(float2*)(C + (size_t)r0 * ldc + c) =
                    make_float2(acc[fi][fj][0], acc[fi][fj][1]);
            if (r0 + 8 < M)
                *(float2*)(C + (size_t)(r0 + 8) * ldc + c) =
                    make_float2(acc[fi][fj][2], acc[fi][fj][3]);
        }
    }
}

// ======================= fused edge MLP ===================================
// Per 64-edge block:
//   T1 = lrelu(|h2[s]-h2[d]| @ Ct^T + PQ[s] + PQ[d] + ea*w192 + bm1)  (64x128)
//   out[e] = sum_n lrelu((T1 @ Wm2)[n] + bm2[n]) * wm3[n] + bm3
// Ct: [128 n][64 k] split bf16;  Wm2t: [64 n][128 k] split bf16.
__global__ __launch_bounds__(256, 2) void edge_mlp_kernel(
    const __nv_bfloat16* __restrict__ cthi, const __nv_bfloat16* __restrict__ ctlo,
    const __nv_bfloat16* __restrict__ wm2hi, const __nv_bfloat16* __restrict__ wm2lo,
    const int* __restrict__ ei, int E, const float* __restrict__ h2g,
    const float* __restrict__ PQ, const float* __restrict__ ea,
    const float* __restrict__ w192, const float* __restrict__ bm1,
    const float* __restrict__ bm2, const float* __restrict__ wm3,
    const float* __restrict__ bm3, float* __restrict__ out)
{
    extern __shared__ char sm[];
    constexpr int SA_HI = 0;            // 64x64 k, 128B rows -> 8 KB
    constexpr int SA_LO = 8192;
    constexpr int CT_HI = 16384;        // 128 n x 64 k -> 16 KB
    constexpr int CT_LO = 32768;
    constexpr int T1_HI = 49152;        // 2 k-chunks x (64 x 64k) -> 16 KB
    constexpr int T1_LO = 65536;
    constexpr int W2_HI = 81920;        // 2 k-chunks x (64 n x 64k) -> 16 KB
    constexpr int W2_LO = 98304;        // total 112 KB

    const uint32_t sb = s2u(sm);
    const int t = threadIdx.x;
    const int wid = t >> 5, lane = t & 31;
    const int rowBase = blockIdx.x * 64;

    // ---- async load Ct (128x8 octets) and Wm2t (64x16 octets) ----
#pragma unroll
    for (int it = 0; it < 4; it++) {
        int idx = t + it * 256;          // 0..1023
        int n = idx >> 3, q = idx & 7;
        uint32_t sa = sb + CT_HI + SW(n * 128 + q * 16);
        cpasync16(sa, cthi + (size_t)n * 64 + q * 8);
        cpasync16(sa + (CT_LO - CT_HI), ctlo + (size_t)n * 64 + q * 8);
    }
#pragma unroll
    for (int it = 0; it < 4; it++) {
        int idx = t + it * 256;          // 0..1023 : n(64) x q(16)
        int n = idx >> 4, q = idx & 15;
        int kc = q >> 3, kin = (q & 7) * 16;
        uint32_t sa = sb + W2_HI + kc * 8192 + SW(n * 128 + kin);
        cpasync16(sa, wm2hi + (size_t)n * 128 + q * 8);
        cpasync16(sa + (W2_LO - W2_HI), wm2lo + (size_t)n * 128 + q * 8);
    }
    asm volatile("cp.async.commit_group;" ::: "memory");

    // ---- build SA = split(|h2[s]-h2[d]|), 64 rows x 16 float4 ----
#pragma unroll
    for (int it = 0; it < 4; it++) {
        int idx = t + it * 256;
        int r = idx >> 4, q = idx & 15;
        int e = rowBase + r; if (e >= E) e = E - 1;
        int s = ei[e], d = ei[E + e];
        float4 a4 = *(const float4*)(h2g + (size_t)s * 64 + q * 4);
        float4 b4 = *(const float4*)(h2g + (size_t)d * 64 + q * 4);
        float4 v = make_float4(fabsf(a4.x - b4.x), fabsf(a4.y - b4.y),
                               fabsf(a4.z - b4.z), fabsf(a4.w - b4.w));
        uint32_t hx = bfbits(v.x), hy = bfbits(v.y), hz = bfbits(v.z), hw = bfbits(v.w);
        uint32_t lx = bfbits(v.x - bfval(hx)), ly = bfbits(v.y - bfval(hy));
        uint32_t lz = bfbits(v.z - bfval(hz)), lw = bfbits(v.w - bfval(hw));
        int so = SW(r * 128 + q * 8);
        *(uint2*)(sm + SA_HI + so) = make_uint2(hx | (hy << 16), hz | (hw << 16));
        *(uint2*)(sm + SA_LO + so) = make_uint2(lx | (ly << 16), lz | (lw << 16));
    }
    asm volatile("cp.async.wait_group 0;" ::: "memory");
    __syncthreads();

    // ---- MMA1: 8 warps, 2M x 4N, K=64 ----
    {
        const int mBase = (wid & 1) * 32;
        const int nBase = (wid >> 1) * 32;
        float acc[2][4][4];
#pragma unroll
        for (int i = 0; i < 2; i++)
#pragma unroll
            for (int j = 0; j < 4; j++)
#pragma unroll
                for (int q = 0; q < 4; q++) acc[i][j][q] = 0.f;

#pragma unroll
        for (int ks = 0; ks < 4; ks++) {
            const int k0 = ks * 16;
            uint32_t ahi[2][4], alo[2][4];
#pragma unroll
            for (int fi = 0; fi < 2; fi++) {
                int row = mBase + 16 * fi + (lane & 15);
                int bo = SW(row * 128 + (k0 + ((lane >> 4) << 3)) * 2);
                ldsm4(ahi[fi], sb + SA_HI + bo);
                ldsm4(alo[fi], sb + SA_LO + bo);
            }
#pragma unroll
            for (int fj = 0; fj < 4; fj++) {
                int row = nBase + 8 * fj + (lane & 7);
                int bo = SW(row * 128 + (k0 + (((lane >> 3) & 1) << 3)) * 2);
                uint32_t bh[2], bl[2];
                ldsm2(bh, sb + CT_HI + bo);
                ldsm2(bl, sb + CT_LO + bo);
#pragma unroll
                for (int fi = 0; fi < 2; fi++) {
                    mma_bf16(acc[fi][fj], ahi[fi], bh);
                    mma_bf16(acc[fi][fj], ahi[fi], bl);
                    mma_bf16(acc[fi][fj], alo[fi], bh);
                }
            }
        }

        // epilogue 1 -> T1 smem (split bf16)
#pragma unroll
        for (int fi = 0; fi < 2; fi++) {
#pragma unroll
            for (int half = 0; half < 2; half++) {
                int r = mBase + 16 * fi + (lane >> 2) + half * 8;
                int e = rowBase + r; if (e >= E) e = E - 1;
                int s = ei[e], d = ei[E + e];
                float eav = ea[e];
                const float* pqs = PQ + (size_t)s * 256;
                const float* pqd = PQ + (size_t)d * 256 + 128;
#pragma unroll
                for (int fj = 0; fj < 4; fj++) {
                    int c = nBase + 8 * fj + (lane & 3) * 2;
                    float2 p1 = *(const float2*)(pqs + c);
                    float2 p2 = *(const float2*)(pqd + c);
                    float2 wv = *(const float2*)(w192 + c);
                    float2 bv = *(const float2*)(bm1 + c);
                    float v0 = lrelu(acc[fi][fj][half * 2 + 0] + p1.x + p2.x + eav * wv.x + bv.x);
                    float v1 = lrelu(acc[fi][fj][half * 2 + 1] + p1.y + p2.y + eav * wv.y + bv.y);
                    uint32_t h0 = bfbits(v0), h1 = bfbits(v1);
                    uint32_t l0 = bfbits(v0 - bfval(h0)), l1 = bfbits(v1 - bfval(h1));
                    int kc = c >> 6, kin = c & 63;
                    int so = kc * 8192 + SW(r * 128 + kin * 2);
                    *(uint32_t*)(sm + T1_HI + so) = h0 | (h1 << 16);
                    *(uint32_t*)(sm + T1_LO + so) = l0 | (l1 << 16);
                }
            }
        }
    }
    __syncthreads();

    // ---- MMA2: warps 0-3, 2M x 2N, K=128 ----
    float* st = (float*)sm;   // reuse SA region: [64][2]
    if (wid < 4) {
        const int mBase = (wid & 1) * 32;
        const int nBase = (wid >> 1) * 32;
        float acc[2][4][4];
#pragma unroll
        for (int i = 0; i < 2; i++)
#pragma unroll
            for (int j = 0; j < 4; j++)
#pragma unroll
                for (int q = 0; q < 4; q++) acc[i][j][q] = 0.f;

#pragma unroll
        for (int ks = 0; ks < 8; ks++) {
            const int k0g = ks * 16;
            const int kc = k0g >> 6, k0 = k0g & 63;
            uint32_t ahi[2][4], alo[2][4];
#pragma unroll
            for (int fi = 0; fi < 2; fi++) {
                int row = mBase + 16 * fi + (lane & 15);
                int bo = kc * 8192 + SW(row * 128 + (k0 + ((lane >> 4) << 3)) * 2);
                ldsm4(ahi[fi], sb + T1_HI + bo);
                ldsm4(alo[fi], sb + T1_LO + bo);
            }
#pragma unroll
            for (int fj = 0; fj < 4; fj++) {
                int row = nBase + 8 * fj + (lane & 7);
                int bo = kc * 8192 + SW(row * 128 + (k0 + (((lane >> 3) & 1) << 3)) * 2);
                uint32_t bh[2], bl[2];
                ldsm2(bh, sb + W2_HI + bo);
                ldsm2(bl, sb + W2_LO + bo);
#pragma unroll
                for (int fi = 0; fi < 2; fi++) {
                    mma_bf16(acc[fi][fj], ahi[fi], bh);
                    mma_bf16(acc[fi][fj], ahi[fi], bl);
                    mma_bf16(acc[fi][fj], alo[fi], bh);
                }
            }
        }

        // fused final dot: per-row partial over this warp's 32 cols
#pragma unroll
        for (int fi = 0; fi < 2; fi++) {
#pragma unroll
            for (int half = 0; half < 2; half++) {
                int r = mBase + 16 * fi + (lane >> 2) + half * 8;
                float part = 0.f;
#pragma unroll
                for (int fj = 0; fj < 4; fj++) {
#pragma unroll
                    for (int qq = 0; qq < 2; qq++) {
                        int c = nBase + 8 * fj + (lane & 3) * 2 + qq;
                        float v = lrelu(acc[fi][fj][half * 2 + qq] + bm2[c]);
                        part += v * wm3[c];
                    }
                }
                part += __shfl_xor_sync(0xffffffffu, part, 1);
                part += __shfl_xor_sync(0xffffffffu, part, 2);
                if ((lane & 3) == 0) st[r * 2 + (wid >> 1)] = part;
            }
        }
    }
    __syncthreads();
    if (t < 64) {
        int e = rowBase + t;
        if (e < E) out[e] = st[t * 2] + st[t * 2 + 1] + bm3[0];
    }
}

// ------------------------------ split / prep kernels ----------------------
__global__ void split_act_kernel(const float* __restrict__ X,
                                 __nv_bfloat16* __restrict__ hi, __nv_bfloat16* __restrict__ lo,
                                 int n, int colsMask,
                                 const float* __restrict__ sc, const float* __restrict__ sh)
{
    int i = blockIdx.x * blockDim.x + threadIdx.x;
    if (i >= n) return;
    float v = X[i];
    if (sc) {
        int c = i & colsMask;
        v = lrelu(v * sc[c] + sh[c]);
    }
    __nv_bfloat16 h = __float2bfloat16_rn(v);
    hi[i] = h;
    lo[i] = __float2bfloat16_rn(v - __bfloat162float(h));
}

__global__ void split_wt_kernel(const float* __restrict__ W,
                                __nv_bfloat16* __restrict__ hi, __nv_bfloat16* __restrict__ lo,
                                int K, int C)
{
    int i = blockIdx.x * blockDim.x + threadIdx.x;
    if (i >= K * C) return;
    int k = i / C, c = i % C;
    float v = W[i];
    __nv_bfloat16 h = __float2bfloat16_rn(v);
    hi[(size_t)c * K + k] = h;
    lo[(size_t)c * K + k] = __float2bfloat16_rn(v - __bfloat162float(h));
}

__global__ void split_wp_kernel(const float* __restrict__ Wm1,
                                __nv_bfloat16* __restrict__ hi, __nv_bfloat16* __restrict__ lo)
{
    int i = blockIdx.x * blockDim.x + threadIdx.x;
    if (i >= 64 * 256) return;
    int c = i >> 6, k = i & 63;
    float v = (c < 128) ? Wm1[k * 128 + c] : Wm1[(64 + k) * 128 + (c - 128)];
    __nv_bfloat16 h = __float2bfloat16_rn(v);
    hi[i] = h;
    lo[i] = __float2bfloat16_rn(v - __bfloat162float(h));
}

// ------------------------------ CSR build ---------------------------------
__global__ void init_deg_kernel(int* __restrict__ deg, int n)
{
    int i = blockIdx.x * blockDim.x + threadIdx.x;
    if (i < n) deg[i] = 1;
}

__global__ void count_kernel(const int* __restrict__ ei, int E, int* __restrict__ deg)
{
    int i = blockIdx.x * blockDim.x + threadIdx.x;
    if (i < E) atomicAdd(&deg[ei[E + i]], 1);
}

__global__ void scan_kernel(const int* __restrict__ deg, int* __restrict__ off, int n)
{
    __shared__ int sh[1024];
    __shared__ int carry_s;
    int t = threadIdx.x;
    if (t == 0) carry_s = 0;
    __syncthreads();
    for (int base = 0; base < n; base += 1024) {
        int i = base + t;
        int v = (i < n) ? deg[i] : 0;
        sh[t] = v;
        __syncthreads();
        int sum = v;
        for (int ofs = 1; ofs < 1024; ofs <<= 1) {
            int add = (t >= ofs) ? sh[t - ofs] : 0;
            __syncthreads();
            sum += add;
            sh[t] = sum;
            __syncthreads();
        }
        int carry = carry_s;
        if (i < n) off[i] = carry + sum - v;
        __syncthreads();
        if (t == 1023) carry_s = carry + sum;
        __syncthreads();
    }
    if (t == 0) off[n] = carry_s;
}

__global__ void copy_cur_kernel(const int* __restrict__ off, int* __restrict__ cur, int n)
{
    int i = blockIdx.x * blockDim.x + threadIdx.x;
    if (i < n) cur[i] = off[i];
}

__global__ void scatter_edges_kernel(const int* __restrict__ ei, int E,
                                     int* __restrict__ cur,
                                     int* __restrict__ csrc, int* __restrict__ cdst)
{
    int i = blockIdx.x * blockDim.x + threadIdx.x;
    if (i >= E) return;
    int d = ei[E + i];
    int pos = atomicAdd(&cur[d], 1);
    csrc[pos] = ei[i];
    cdst[pos] = d;
}

__global__ void scatter_loops_kernel(int N, int* __restrict__ cur,
                                     int* __restrict__ csrc, int* __restrict__ cdst)
{
    int n = blockIdx.x * blockDim.x + threadIdx.x;
    if (n >= N) return;
    int pos = atomicAdd(&cur[n], 1);
    csrc[pos] = n;
    cdst[pos] = n;
}

// ------------------------------ GAT attention -----------------------------
__global__ void alpha_kernel(const float* __restrict__ h,
                             const float* __restrict__ aw_s, const float* __restrict__ aw_d,
                             float* __restrict__ asrc, float* __restrict__ adst, int N)
{
    int id = blockIdx.x * blockDim.x + threadIdx.x;
    if (id >= N * 4) return;
    int n = id >> 2, hh = id & 3;
    const float4* row = (const float4*)(h + (size_t)n * 256 + hh * 64);
    const float4* ws  = (const float4*)(aw_s + hh * 64);
    const float4* wd  = (const float4*)(aw_d + hh * 64);
    float sa = 0.f, sb = 0.f;
#pragma unroll
    for (int q = 0; q < 16; q++) {
        float4 v = row[q];
        float4 a = ws[q], b = wd[q];
        sa += v.x * a.x + v.y * a.y + v.z * a.z + v.w * a.w;
        sb += v.x * b.x + v.y * b.y + v.z * b.z + v.w * b.w;
    }
    asrc[id] = sa;
    adst[id] = sb;
}

__global__ void maxwatt_kernel(const float4* __restrict__ asrc4, const float4* __restrict__ adst4,
                               const int* __restrict__ off, const int* __restrict__ csrc,
                               float4* __restrict__ watt4, int N)
{
    int w = (blockIdx.x * blockDim.x + threadIdx.x) >> 5;
    int lane = threadIdx.x & 31;
    if (w >= N) return;
    float4 ad = adst4[w];
    int lo = off[w], hi = off[w + 1];
    float m0 = -1e30f, m1 = -1e30f, m2 = -1e30f, m3 = -1e30f;
    for (int p = lo + lane; p < hi; p += 32) {
        int s = csrc[p];
        float4 as = asrc4[s];
        m0 = fmaxf(m0, lrelu(as.x + ad.x));
        m1 = fmaxf(m1, lrelu(as.y + ad.y));
        m2 = fmaxf(m2, lrelu(as.z + ad.z));
        m3 = fmaxf(m3, lrelu(as.w + ad.w));
    }
#pragma unroll
    for (int o = 16; o > 0; o >>= 1) {
        m0 = fmaxf(m0, __shfl_xor_sync(0xffffffffu, m0, o));
        m1 = fmaxf(m1, __shfl_xor_sync(0xffffffffu, m1, o));
        m2 = fmaxf(m2, __shfl_xor_sync(0xffffffffu, m2, o));
        m3 = fmaxf(m3, __shfl_xor_sync(0xffffffffu, m3, o));
    }
    for (int p = lo + lane; p < hi; p += 32) {
        int s = csrc[p];
        float4 as = asrc4[s];
        watt4[p] = make_float4(expf(lrelu(as.x + ad.x) - m0),
                               expf(lrelu(as.y + ad.y) - m1),
                               expf(lrelu(as.z + ad.z) - m2),
                               expf(lrelu(as.w + ad.w) - m3));
    }
}

__global__ __launch_bounds__(128) void gat_aggregate_kernel(
    const float* __restrict__ h, const float* __restrict__ watt,
    const int* __restrict__ off, const int* __restrict__ csrc,
    const float* __restrict__ bias, float* __restrict__ out, int concat)
{
    int d = blockIdx.x;
    int t = threadIdx.x;            // 128
    int c = t * 2;
    int hh = t >> 5;
    int lo = off[d], hi = off[d + 1];
    float accx = 0.f, accy = 0.f, den = 0.f;
    int s_n = csrc[lo];
    float w_n = watt[lo * 4 + hh];
    for (int p = lo; p < hi; ++p) {
        int s = s_n;
        float w = w_n;
        int pn = p + 1;
        if (pn < hi) { s_n = csrc[pn]; w_n = watt[pn * 4 + hh]; }
        float2 hv = *(const float2*)(h + (size_t)s * 256 + c);
        den += w;
        accx += w * hv.x;
        accy += w * hv.y;
    }
    float inv = 1.f / den;
    accx *= inv; accy *= inv;
    if (concat) {
        *(float2*)(out + (size_t)d * 256 + c) =
            make_float2(accx + bias[c], accy + bias[c + 1]);
    } else {
        __shared__ float red[256];
        red[c] = accx; red[c + 1] = accy;
        __syncthreads();
        if (t < 32) {
#pragma unroll
            for (int j = 0; j < 2; j++) {
                int cc = t * 2 + j;
                out[(size_t)d * 64 + cc] =
                    0.25f * (red[cc] + red[cc + 64] + red[cc + 128] + red[cc + 192]) + bias[cc];
            }
        }
    }
}

// ------------------------------ BatchNorm ---------------------------------
__global__ void zero_kernel(float* __restrict__ p, int n)
{
    int i = blockIdx.x * blockDim.x + threadIdx.x;
    if (i < n) p[i] = 0.f;
}

__global__ void bn_stats_kernel(const float* __restrict__ X, int rows, int cols,
                                float* __restrict__ stats, int rowsPerBlock)
{
    int t = threadIdx.x;
    int c = t % cols;
    int rsub = t / cols;
    int rstep = 256 / cols;
    int r0 = blockIdx.x * rowsPerBlock;
    int r1 = r0 + rowsPerBlock; if (r1 > rows) r1 = rows;
    float s = 0.f, s2 = 0.f;
    for (int r = r0 + rsub; r < r1; r += rstep) {
        float v = X[(size_t)r * cols + c];
        s += v;
        s2 += v * v;
    }
    atomicAdd(&stats[c], s);
    atomicAdd(&stats[cols + c], s2);
}

__global__ void bn_final_kernel(const float* __restrict__ stats,
                                const float* __restrict__ g, const float* __restrict__ be,
                                int rows, int cols,
                                float* __restrict__ sc, float* __restrict__ sh)
{
    int c = threadIdx.x;
    if (c >= cols) return;
    float inv = 1.f / (float)rows;
    float mean = stats[c] * inv;
    float var = stats[cols + c] * inv - mean * mean;
    float scale = g[c] * rsqrtf(var + EPSBN);
    sc[c] = scale;
    sh[c] = be[c] - mean * scale;
}

__global__ void bn_apply_kernel(float* __restrict__ X, int n, int cols,
                                const float* __restrict__ sc, const float* __restrict__ sh,
                                int act)
{
    int i = blockIdx.x * blockDim.x + threadIdx.x;
    if (i >= n) return;
    int c = i % cols;
    float v = X[i] * sc[c] + sh[c];
    if (act) v = lrelu(v);
    X[i] = v;
}

// ------------------------------ host orchestration ------------------------
extern "C" void kernel_launch(void* const* d_in, const int* in_sizes, int n_in,
                              void* d_out, int out_size)
{
    const float* x  = (const float*)d_in[0];
    const int*   ei = (const int*)d_in[1];
    const float* ea = (const float*)d_in[2];
    const int N = in_sizes[0] / 128;
    const int E = in_sizes[2];

    const float *W0, *as0, *ad0, *b0, *g0, *be0;
    const float *W1, *as1, *ad1, *b1, *g1, *be1;
    const float *W2, *as2, *ad2, *b2, *g2, *be2;
    if (in_sizes[7] == 256 * 256) {
        W0 = (const float*)d_in[3];  as0 = (const float*)d_in[4];  ad0 = (const float*)d_in[5];  b0 = (const float*)d_in[6];
        W1 = (const float*)d_in[7];  as1 = (const float*)d_in[8];  ad1 = (const float*)d_in[9];  b1 = (const float*)d_in[10];
        W2 = (const float*)d_in[11]; as2 = (const float*)d_in[12]; ad2 = (const float*)d_in[13]; b2 = (const float*)d_in[14];
        g0 = (const float*)d_in[15]; be0 = (const float*)d_in[16];
        g1 = (const float*)d_in[17]; be1 = (const float*)d_in[18];
        g2 = (const float*)d_in[19]; be2 = (const float*)d_in[20];
    } else {
        W0 = (const float*)d_in[3];  as0 = (const float*)d_in[4];  ad0 = (const float*)d_in[5];  b0 = (const float*)d_in[6];
        g0 = (const float*)d_in[7];  be0 = (const float*)d_in[8];
        W1 = (const float*)d_in[9];  as1 = (const float*)d_in[10]; ad1 = (const float*)d_in[11]; b1 = (const float*)d_in[12];
        g1 = (const float*)d_in[13]; be1 = (const float*)d_in[14];
        W2 = (const float*)d_in[15]; as2 = (const float*)d_in[16]; ad2 = (const float*)d_in[17]; b2 = (const float*)d_in[18];
        g2 = (const float*)d_in[19]; be2 = (const float*)d_in[20];
    }
    const float* Wm1 = (const float*)d_in[21];
    const float* bm1 = (const float*)d_in[22];
    const float* Wm2 = (const float*)d_in[23];
    const float* bm2 = (const float*)d_in[24];
    const float* Wm3 = (const float*)d_in[25];
    const float* bm3 = (const float*)d_in[26];
    float* out = (float*)d_out;

    float *bufA, *bufB, *h2, *asrc, *adst, *watt, *stats, *bnsc, *bnsh;
    int *deg, *off, *cur, *csrc, *cdst;
    __nv_bfloat16 *xhi, *xlo;
    __nv_bfloat16 *w0hi, *w0lo, *w1hi, *w1lo, *w2hi, *w2lo;
    __nv_bfloat16 *wphi, *wplo, *cthi, *ctlo, *wm2hi, *wm2lo;
    cudaGetSymbolAddress((void**)&bufA, g_bufA);
    cudaGetSymbolAddress((void**)&bufB, g_bufB);
    cudaGetSymbolAddress((void**)&h2, g_h2);
    cudaGetSymbolAddress((void**)&asrc, g_asrc);
    cudaGetSymbolAddress((void**)&adst, g_adst);
    cudaGetSymbolAddress((void**)&watt, g_watt);
    cudaGetSymbolAddress((void**)&stats, g_stats);
    cudaGetSymbolAddress((void**)&bnsc, g_bnsc);
    cudaGetSymbolAddress((void**)&bnsh, g_bnsh);
    cudaGetSymbolAddress((void**)&deg, g_deg);
    cudaGetSymbolAddress((void**)&off, g_off);
    cudaGetSymbolAddress((void**)&cur, g_cur);
    cudaGetSymbolAddress((void**)&csrc, g_csrc);
    cudaGetSymbolAddress((void**)&cdst, g_cdst);
    cudaGetSymbolAddress((void**)&xhi, g_xhi);
    cudaGetSymbolAddress((void**)&xlo, g_xlo);
    cudaGetSymbolAddress((void**)&w0hi, g_w0hi);  cudaGetSymbolAddress((void**)&w0lo, g_w0lo);
    cudaGetSymbolAddress((void**)&w1hi, g_w1hi);  cudaGetSymbolAddress((void**)&w1lo, g_w1lo);
    cudaGetSymbolAddress((void**)&w2hi, g_w2hi);  cudaGetSymbolAddress((void**)&w2lo, g_w2lo);
    cudaGetSymbolAddress((void**)&wphi, g_wphi);  cudaGetSymbolAddress((void**)&wplo, g_wplo);
    cudaGetSymbolAddress((void**)&cthi, g_cthi);  cudaGetSymbolAddress((void**)&ctlo, g_ctlo);
    cudaGetSymbolAddress((void**)&wm2hi, g_wm2hi); cudaGetSymbolAddress((void**)&wm2lo, g_wm2lo);

    const int STAGE = 48 * 1024;
    const int SM2 = 2 * STAGE;
    const int SMEDGE = 112 * 1024;
    cudaFuncSetAttribute(hmma_gemm, cudaFuncAttributeMaxDynamicSharedMemorySize, SM2);
    cudaFuncSetAttribute(edge_mlp_kernel, cudaFuncAttributeMaxDynamicSharedMemorySize, SMEDGE);

    auto node_gemm = [&](const __nv_bfloat16* Ah, const __nv_bfloat16* Al,
                         const __nv_bfloat16* Bh, const __nv_bfloat16* Bl,
                         float* C, int M, int Kt, int Ncols) {
        dim3 grid((M + 127) / 128, Ncols / 64);
        int smem = (Kt > 64) ? SM2 : STAGE;
        hmma_gemm<<<grid, 256, smem>>>(Ah, Al, Bh, Bl, C, M, Kt, Ncols);
    };

    // ---- launches 1-4 ordered so the profiled launch (#4) is the L0 GEMM ----
    split_act_kernel<<<(N * 128 + 255) / 256, 256>>>(x, xhi, xlo, N * 128, 127, nullptr, nullptr);
    split_wt_kernel<<<(128 * 256 + 255) / 256, 256>>>(W0, w0hi, w0lo, 128, 256);
    init_deg_kernel<<<(N + 255) / 256, 256>>>(deg, N);
    node_gemm(xhi, xlo, w0hi, w0lo, bufA, N, 128, 256);          // launch #4

    // ---- rest of CSR build ----
    count_kernel<<<(E + 255) / 256, 256>>>(ei, E, deg);
    scan_kernel<<<1, 1024>>>(deg, off, N);
    copy_cur_kernel<<<(N + 255) / 256, 256>>>(off, cur, N);
    scatter_edges_kernel<<<(E + 255) / 256, 256>>>(ei, E, cur, csrc, cdst);
    scatter_loops_kernel<<<(N + 255) / 256, 256>>>(N, cur, csrc, cdst);

    auto attention = [&](const float* hbuf, const float* aws, const float* awd,
                         const float* bias, float* outbuf, int concat) {
        alpha_kernel<<<(N * 4 + 255) / 256, 256>>>(hbuf, aws, awd, asrc, adst, N);
        maxwatt_kernel<<<(N * 32 + 255) / 256, 256>>>((const float4*)asrc, (const float4*)adst,
                                                      off, csrc, (float4*)watt, N);
        gat_aggregate_kernel<<<N, 128>>>(hbuf, watt, off, csrc, bias, outbuf, concat);
    };

    auto bnstats = [&](const float* X, int cols, const float* g, const float* be) {
        zero_kernel<<<1, 512>>>(stats, 2 * cols);
        bn_stats_kernel<<<(N + 255) / 256, 256>>>(X, N, cols, stats, 256);
        bn_final_kernel<<<1, cols>>>(stats, g, be, N, cols, bnsc, bnsh);
    };

    // ---- layer 0 ----
    attention(bufA, as0, ad0, b0, bufB, 1);
    bnstats(bufB, 256, g0, be0);
    split_act_kernel<<<(N * 256 + 255) / 256, 256>>>(bufB, xhi, xlo, N * 256, 255, bnsc, bnsh);

    // ---- layer 1 ----
    split_wt_kernel<<<(256 * 256 + 255) / 256, 256>>>(W1, w1hi, w1lo, 256, 256);
    node_gemm(xhi, xlo, w1hi, w1lo, bufA, N, 256, 256);
    attention(bufA, as1, ad1, b1, bufB, 1);
    bnstats(bufB, 256, g1, be1);
    split_act_kernel<<<(N * 256 + 255) / 256, 256>>>(bufB, xhi, xlo, N * 256, 255, bnsc, bnsh);

    // ---- layer 2 ----
    split_wt_kernel<<<(256 * 256 + 255) / 256, 256>>>(W2, w2hi, w2lo, 256, 256);
    node_gemm(xhi, xlo, w2hi, w2lo, bufA, N, 256, 256);
    attention(bufA, as2, ad2, b2, h2, 0);
    bnstats(h2, 64, g2, be2);
    bn_apply_kernel<<<(N * 64 + 255) / 256, 256>>>(h2, N * 64, 64, bnsc, bnsh, 0);
    split_act_kernel<<<(N * 64 + 255) / 256, 256>>>(h2, xhi, xlo, N * 64, 63, nullptr, nullptr);

    // ---- edge MLP ----
    split_wp_kernel<<<(64 * 256 + 255) / 256, 256>>>(Wm1, wphi, wplo);
    node_gemm(xhi, xlo, wphi, wplo, bufA, N, 64, 256);   // bufA = PQ (N x 256)

    split_wt_kernel<<<(64 * 128 + 255) / 256, 256>>>(Wm1 + 128 * 128, cthi, ctlo, 64, 128);
    split_wt_kernel<<<(128 * 64 + 255) / 256, 256>>>(Wm2, wm2hi, wm2lo, 128, 64);

    edge_mlp_kernel<<<(E + 63) / 64, 256, SMEDGE>>>(
        cthi, ctlo, wm2hi, wm2lo, ei, E, h2, bufA, ea,
        Wm1 + 192 * 128, bm1, bm2, Wm3, bm3, out);
}

// round 8
// speedup vs baseline: 2.5631x; 1.0991x over previous
#include <cuda_runtime.h>
#include <cuda_bf16.h>
#include <math.h>
#include <stdint.h>

#define NSLOPE 0.2f
#define EPSBN 1e-5f
#define NMAX 50000
#define EMAX 800000
#define TOTMAX (EMAX + NMAX)

// ------------------------------ scratch (device globals; no allocation) ---
__device__ float g_bufA[(size_t)NMAX * 256];
__device__ float g_bufB[(size_t)NMAX * 256];
__device__ float g_h2[(size_t)NMAX * 64];
__device__ float g_asrc[(size_t)NMAX * 4];
__device__ float g_adst[(size_t)NMAX * 4];
__device__ float g_watt[(size_t)TOTMAX * 4];
__device__ int   g_deg[NMAX];
__device__ int   g_off[NMAX + 1];
__device__ int   g_cur[NMAX];
__device__ int   g_csrc[TOTMAX];
__device__ int   g_cdst[TOTMAX];
__device__ float g_stats[512];          // zero-init; self-cleaning
__device__ int   g_bncnt;               // zero-init; self-cleaning
__device__ float g_bnsc[256];
__device__ float g_bnsh[256];
// split-bf16 buffers
__device__ __nv_bfloat16 g_xhi[(size_t)NMAX * 256];
__device__ __nv_bfloat16 g_xlo[(size_t)NMAX * 256];
__device__ __nv_bfloat16 g_w0hi[256 * 128],  g_w0lo[256 * 128];
__device__ __nv_bfloat16 g_w1hi[256 * 256],  g_w1lo[256 * 256];
__device__ __nv_bfloat16 g_w2hi[256 * 256],  g_w2lo[256 * 256];
__device__ __nv_bfloat16 g_wphi[256 * 64],   g_wplo[256 * 64];
__device__ __nv_bfloat16 g_cthi[128 * 64],   g_ctlo[128 * 64];
__device__ __nv_bfloat16 g_wm2hi[64 * 128],  g_wm2lo[64 * 128];

__device__ __forceinline__ float lrelu(float v) { return v > 0.f ? v : NSLOPE * v; }

// ======================= HMMA helpers =====================================
#define SW(o) ((o) ^ (((o) >> 3) & 0x70))

__device__ __forceinline__ uint32_t s2u(const void* p) {
    uint32_t a;
    asm("{ .reg .u64 t; cvta.to.shared.u64 t, %1; cvt.u32.u64 %0, t; }" : "=r"(a) : "l"(p));
    return a;
}

__device__ __forceinline__ void mma_bf16(float* c, const uint32_t* a, const uint32_t* b) {
    asm volatile(
        "mma.sync.aligned.m16n8k16.row.col.f32.bf16.bf16.f32 "
        "{%0,%1,%2,%3}, {%4,%5,%6,%7}, {%8,%9}, {%0,%1,%2,%3};"
        : "+f"(c[0]), "+f"(c[1]), "+f"(c[2]), "+f"(c[3])
        : "r"(a[0]), "r"(a[1]), "r"(a[2]), "r"(a[3]), "r"(b[0]), "r"(b[1]));
}

__device__ __forceinline__ void ldsm4(uint32_t* r, uint32_t addr) {
    asm volatile("ldmatrix.sync.aligned.m8n8.x4.shared.b16 {%0,%1,%2,%3}, [%4];"
                 : "=r"(r[0]), "=r"(r[1]), "=r"(r[2]), "=r"(r[3]) : "r"(addr));
}

__device__ __forceinline__ void ldsm2(uint32_t* r, uint32_t addr) {
    asm volatile("ldmatrix.sync.aligned.m8n8.x2.shared.b16 {%0,%1}, [%2];"
                 : "=r"(r[0]), "=r"(r[1]) : "r"(addr));
}

__device__ __forceinline__ void cpasync16(uint32_t saddr, const void* g) {
    asm volatile("cp.async.cg.shared.global [%0], [%1], 16;" :: "r"(saddr), "l"(g));
}

__device__ __forceinline__ uint32_t bfbits(float v) {
    __nv_bfloat16 b = __float2bfloat16_rn(v);
    return (uint32_t)__bfloat16_as_ushort(b);
}
__device__ __forceinline__ float bfval(uint32_t bits) {
    return __bfloat162float(__ushort_as_bfloat16((unsigned short)bits));
}

// ======================= split-bf16 HMMA node GEMM ========================
// Block tile 128 x 64, K-chunk 64, 8 warps of 32x32, cp.async double-buffer.
// ALPHA=1: also compute per-head attention dots (col-block == head, Ncols=256):
//   asrc[n,head] = sum_d h[n,head*64+d]*aws[head,d], same for adst.
template <int ALPHA>
__global__ __launch_bounds__(256, 2) void hmma_gemm(
    const __nv_bfloat16* __restrict__ Ahi, const __nv_bfloat16* __restrict__ Alo,
    const __nv_bfloat16* __restrict__ Bhi, const __nv_bfloat16* __restrict__ Blo,
    float* __restrict__ C, int M, int Kt, int ldc,
    const float* __restrict__ aws, const float* __restrict__ awd,
    float* __restrict__ asrcO, float* __restrict__ adstO)
{
    extern __shared__ char sm[];
    constexpr int A_HI = 0;
    constexpr int A_LO = 128 * 128;
    constexpr int B_HI = 2 * 128 * 128;
    constexpr int B_LO = 2 * 128 * 128 + 64 * 128;
    constexpr int STAGE = 2 * 128 * 128 + 2 * 64 * 128;   // 48 KB

    const uint32_t sb = s2u(sm);
    const int t = threadIdx.x;
    const int wid = t >> 5, lane = t & 31;
    const int rowBase = blockIdx.x * 128;
    const int colBase = blockIdx.y * 64;
    const int mBase = (wid & 3) * 32;
    const int nBase = (wid >> 2) * 32;

    float acc[2][4][4];
#pragma unroll
    for (int i = 0; i < 2; i++)
#pragma unroll
        for (int j = 0; j < 4; j++)
#pragma unroll
            for (int q = 0; q < 4; q++) acc[i][j][q] = 0.f;

    auto do_mma = [&](int st) {
        const uint32_t base = sb + st * STAGE;
#pragma unroll
        for (int ks = 0; ks < 4; ks++) {
            const int k0 = ks * 16;
            uint32_t ahi[2][4], alo[2][4];
#pragma unroll
            for (int fi = 0; fi < 2; fi++) {
                int row = mBase + 16 * fi + (lane & 15);
                int bo = SW(row * 128 + (k0 + ((lane >> 4) << 3)) * 2);
                ldsm4(ahi[fi], base + A_HI + bo);
                ldsm4(alo[fi], base + A_LO + bo);
            }
#pragma unroll
            for (int fj = 0; fj < 4; fj++) {
                int row = nBase + 8 * fj + (lane & 7);
                int bo = SW(row * 128 + (k0 + (((lane >> 3) & 1) << 3)) * 2);
                uint32_t bh[2], bl[2];
                ldsm2(bh, base + B_HI + bo);
                ldsm2(bl, base + B_LO + bo);
#pragma unroll
                for (int fi = 0; fi < 2; fi++) {
                    mma_bf16(acc[fi][fj], ahi[fi], bh);
                    mma_bf16(acc[fi][fj], ahi[fi], bl);
                    mma_bf16(acc[fi][fj], alo[fi], bh);
                }
            }
        }
    };

    auto load_chunk = [&](int kc, int st) {
        const uint32_t base = sb + st * STAGE;
#pragma unroll
        for (int it = 0; it < 4; it++) {
            int idx = t + it * 256;
            int r = idx >> 3, q = idx & 7;
            int gm = rowBase + r; if (gm >= M) gm = 0;
            size_t goff = (size_t)gm * Kt + kc + q * 8;
            uint32_t sa = base + A_HI + SW(r * 128 + q * 16);
            cpasync16(sa, Ahi + goff);
            cpasync16(sa + (A_LO - A_HI), Alo + goff);
        }
#pragma unroll
        for (int it = 0; it < 2; it++) {
            int idx = t + it * 256;
            int n = idx >> 3, q = idx & 7;
            size_t goff = (size_t)(colBase + n) * Kt + kc + q * 8;
            uint32_t sa = base + B_HI + SW(n * 128 + q * 16);
            cpasync16(sa, Bhi + goff);
            cpasync16(sa + (B_LO - B_HI), Blo + goff);
        }
        asm volatile("cp.async.commit_group;" ::: "memory");
    };

    const int nch = Kt >> 6;
    load_chunk(0, 0);
    for (int i = 0; i < nch; i++) {
        if (i + 1 < nch) {
            load_chunk((i + 1) << 6, (i + 1) & 1);
            asm volatile("cp.async.wait_group 1;" ::: "memory");
        } else {
            asm volatile("cp.async.wait_group 0;" ::: "memory");
        }
        __syncthreads();
        do_mma(i & 1);
        __syncthreads();
    }

    // ---- C writeback ----
#pragma unroll
    for (int fi = 0; fi < 2; fi++) {
        int r0 = rowBase + mBase + 16 * fi + (lane >> 2);
#pragma unroll
        for (int fj = 0; fj < 4; fj++) {
            int c = colBase + nBase + 8 * fj + (lane & 3) * 2;
            if (r0 < M)
                *(float2*)(C + (size_t)r0 * ldc + c) =
                    make_float2(acc[fi][fj][0], acc[fi][fj][1]);
            if (r0 + 8 < M)
                *(float2*)(C + (size_t)(r0 + 8) * ldc + c) =
                    make_float2(acc[fi][fj][2], acc[fi][fj][3]);
        }
    }

    if (ALPHA) {
        const int head = blockIdx.y;
        float ps[2][2] = {{0.f, 0.f}, {0.f, 0.f}};
        float pd[2][2] = {{0.f, 0.f}, {0.f, 0.f}};
#pragma unroll
        for (int fj = 0; fj < 4; fj++)
#pragma unroll
            for (int qq = 0; qq < 2; qq++) {
                int dim = nBase + 8 * fj + (lane & 3) * 2 + qq;
                float ws = __ldg(aws + head * 64 + dim);
                float wd = __ldg(awd + head * 64 + dim);
#pragma unroll
                for (int fi = 0; fi < 2; fi++)
#pragma unroll
                    for (int half = 0; half < 2; half++) {
                        float a = acc[fi][fj][half * 2 + qq];
                        ps[fi][half] += a * ws;
                        pd[fi][half] += a * wd;
                    }
            }
        float* ared = (float*)sm;      // 512 floats
#pragma unroll
        for (int fi = 0; fi < 2; fi++)
#pragma unroll
            for (int half = 0; half < 2; half++) {
                float vs = ps[fi][half], vd = pd[fi][half];
                vs += __shfl_xor_sync(0xffffffffu, vs, 1);
                vs += __shfl_xor_sync(0xffffffffu, vs, 2);
                vd += __shfl_xor_sync(0xffffffffu, vd, 1);
                vd += __shfl_xor_sync(0xffffffffu, vd, 2);
                if ((lane & 3) == 0) {
                    int r = mBase + 16 * fi + (lane >> 2) + 8 * half;
                    int wc = wid >> 2;
                    ared[r * 2 + wc] = vs;
                    ared[256 + r * 2 + wc] = vd;
                }
            }
        __syncthreads();
        if (t < 128) {
            int gm = rowBase + t;
            if (gm < M) {
                asrcO[gm * 4 + head] = ared[t * 2] + ared[t * 2 + 1];
                adstO[gm * 4 + head] = ared[256 + t * 2] + ared[256 + t * 2 + 1];
            }
        }
    }
}

// ======================= persistent fused edge MLP ========================
// Per 64-edge tile:
//   T1 = lrelu(|h2[s]-h2[d]| @ Ct^T + PQ[s] + PQ[d] + ea*w192 + bm1)  (64x128)
//   out[e] = sum_n lrelu((T1 @ Wm2)[n] + bm2[n]) * wm3[n] + bm3
// Weights loaded ONCE per CTA; CTA loops over tiles (grid-stride).
__global__ __launch_bounds__(256, 2) void edge_mlp_kernel(
    const __nv_bfloat16* __restrict__ cthi, const __nv_bfloat16* __restrict__ ctlo,
    const __nv_bfloat16* __restrict__ wm2hi, const __nv_bfloat16* __restrict__ wm2lo,
    const int* __restrict__ ei, int E, const float* __restrict__ h2g,
    const float* __restrict__ PQ, const float* __restrict__ ea,
    const float* __restrict__ w192, const float* __restrict__ bm1,
    const float* __restrict__ bm2, const float* __restrict__ wm3,
    const float* __restrict__ bm3, float* __restrict__ out, int nTiles)
{
    extern __shared__ char sm[];
    constexpr int SA_HI = 0;            // 64x64 k tile (also reused as st)
    constexpr int SA_LO = 8192;
    constexpr int CT_HI = 16384;
    constexpr int CT_LO = 32768;
    constexpr int T1_HI = 49152;        // 2 k-chunks x (64 x 64k)
    constexpr int T1_LO = 65536;
    constexpr int W2_HI = 81920;
    constexpr int W2_LO = 98304;        // total 112 KB

    const uint32_t sb = s2u(sm);
    const int t = threadIdx.x;
    const int wid = t >> 5, lane = t & 31;

    // ---- one-time weight loads ----
#pragma unroll
    for (int it = 0; it < 4; it++) {
        int idx = t + it * 256;
        int n = idx >> 3, q = idx & 7;
        uint32_t sa = sb + CT_HI + SW(n * 128 + q * 16);
        cpasync16(sa, cthi + (size_t)n * 64 + q * 8);
        cpasync16(sa + (CT_LO - CT_HI), ctlo + (size_t)n * 64 + q * 8);
    }
#pragma unroll
    for (int it = 0; it < 4; it++) {
        int idx = t + it * 256;
        int n = idx >> 4, q = idx & 15;
        int kc = q >> 3, kin = (q & 7) * 16;
        uint32_t sa = sb + W2_HI + kc * 8192 + SW(n * 128 + kin);
        cpasync16(sa, wm2hi + (size_t)n * 128 + q * 8);
        cpasync16(sa + (W2_LO - W2_HI), wm2lo + (size_t)n * 128 + q * 8);
    }
    asm volatile("cp.async.commit_group;" ::: "memory");
    asm volatile("cp.async.wait_group 0;" ::: "memory");

    for (int tile = blockIdx.x; tile < nTiles; tile += gridDim.x) {
        const int rowBase = tile * 64;

        // ---- build SA = split(|h2[s]-h2[d]|) ----
#pragma unroll
        for (int it = 0; it < 4; it++) {
            int idx = t + it * 256;
            int r = idx >> 4, q = idx & 15;
            int e = rowBase + r; if (e >= E) e = E - 1;
            int s = ei[e], d = ei[E + e];
            float4 a4 = *(const float4*)(h2g + (size_t)s * 64 + q * 4);
            float4 b4 = *(const float4*)(h2g + (size_t)d * 64 + q * 4);
            float4 v = make_float4(fabsf(a4.x - b4.x), fabsf(a4.y - b4.y),
                                   fabsf(a4.z - b4.z), fabsf(a4.w - b4.w));
            uint32_t hx = bfbits(v.x), hy = bfbits(v.y), hz = bfbits(v.z), hw = bfbits(v.w);
            uint32_t lx = bfbits(v.x - bfval(hx)), ly = bfbits(v.y - bfval(hy));
            uint32_t lz = bfbits(v.z - bfval(hz)), lw = bfbits(v.w - bfval(hw));
            int so = SW(r * 128 + q * 8);
            *(uint2*)(sm + SA_HI + so) = make_uint2(hx | (hy << 16), hz | (hw << 16));
            *(uint2*)(sm + SA_LO + so) = make_uint2(lx | (ly << 16), lz | (lw << 16));
        }
        __syncthreads();

        // ---- MMA1: 8 warps, 2M x 4N, K=64 ----
        {
            const int mBase = (wid & 1) * 32;
            const int nBase = (wid >> 1) * 32;
            float acc[2][4][4];
#pragma unroll
            for (int i = 0; i < 2; i++)
#pragma unroll
                for (int j = 0; j < 4; j++)
#pragma unroll
                    for (int q = 0; q < 4; q++) acc[i][j][q] = 0.f;

#pragma unroll
            for (int ks = 0; ks < 4; ks++) {
                const int k0 = ks * 16;
                uint32_t ahi[2][4], alo[2][4];
#pragma unroll
                for (int fi = 0; fi < 2; fi++) {
                    int row = mBase + 16 * fi + (lane & 15);
                    int bo = SW(row * 128 + (k0 + ((lane >> 4) << 3)) * 2);
                    ldsm4(ahi[fi], sb + SA_HI + bo);
                    ldsm4(alo[fi], sb + SA_LO + bo);
                }
#pragma unroll
                for (int fj = 0; fj < 4; fj++) {
                    int row = nBase + 8 * fj + (lane & 7);
                    int bo = SW(row * 128 + (k0 + (((lane >> 3) & 1) << 3)) * 2);
                    uint32_t bh[2], bl[2];
                    ldsm2(bh, sb + CT_HI + bo);
                    ldsm2(bl, sb + CT_LO + bo);
#pragma unroll
                    for (int fi = 0; fi < 2; fi++) {
                        mma_bf16(acc[fi][fj], ahi[fi], bh);
                        mma_bf16(acc[fi][fj], ahi[fi], bl);
                        mma_bf16(acc[fi][fj], alo[fi], bh);
                    }
                }
            }

            // epilogue -> T1 smem (split bf16)
#pragma unroll
            for (int fi = 0; fi < 2; fi++) {
#pragma unroll
                for (int half = 0; half < 2; half++) {
                    int r = mBase + 16 * fi + (lane >> 2) + half * 8;
                    int e = rowBase + r; if (e >= E) e = E - 1;
                    int s = ei[e], d = ei[E + e];
                    float eav = ea[e];
                    const float* pqs = PQ + (size_t)s * 256;
                    const float* pqd = PQ + (size_t)d * 256 + 128;
#pragma unroll
                    for (int fj = 0; fj < 4; fj++) {
                        int c = nBase + 8 * fj + (lane & 3) * 2;
                        float2 p1 = *(const float2*)(pqs + c);
                        float2 p2 = *(const float2*)(pqd + c);
                        float2 wv = *(const float2*)(w192 + c);
                        float2 bv = *(const float2*)(bm1 + c);
                        float v0 = lrelu(acc[fi][fj][half * 2 + 0] + p1.x + p2.x + eav * wv.x + bv.x);
                        float v1 = lrelu(acc[fi][fj][half * 2 + 1] + p1.y + p2.y + eav * wv.y + bv.y);
                        uint32_t h0 = bfbits(v0), h1 = bfbits(v1);
                        uint32_t l0 = bfbits(v0 - bfval(h0)), l1 = bfbits(v1 - bfval(h1));
                        int kc = c >> 6, kin = c & 63;
                        int so = kc * 8192 + SW(r * 128 + kin * 2);
                        *(uint32_t*)(sm + T1_HI + so) = h0 | (h1 << 16);
                        *(uint32_t*)(sm + T1_LO + so) = l0 | (l1 << 16);
                    }
                }
            }
        }
        __syncthreads();

        // ---- MMA2: 8 warps, each 32 rows x 16 cols, full K=128 ----
        float* st = (float*)sm;        // reuse SA region: [64][4]
        {
            const int mB = (wid & 1) * 32;
            const int nB = (wid >> 1) * 16;
            float acc2[2][2][4];
#pragma unroll
            for (int i = 0; i < 2; i++)
#pragma unroll
                for (int j = 0; j < 2; j++)
#pragma unroll
                    for (int q = 0; q < 4; q++) acc2[i][j][q] = 0.f;

#pragma unroll
            for (int ks = 0; ks < 8; ks++) {
                const int kc = ks >> 2, k0 = (ks & 3) * 16;
                uint32_t ahi[2][4], alo[2][4];
#pragma unroll
                for (int fi = 0; fi < 2; fi++) {
                    int row = mB + 16 * fi + (lane & 15);
                    int bo = kc * 8192 + SW(row * 128 + (k0 + ((lane >> 4) << 3)) * 2);
                    ldsm4(ahi[fi], sb + T1_HI + bo);
                    ldsm4(alo[fi], sb + T1_LO + bo);
                }
#pragma unroll
                for (int fj = 0; fj < 2; fj++) {
                    int row = nB + 8 * fj + (lane & 7);
                    int bo = kc * 8192 + SW(row * 128 + (k0 + (((lane >> 3) & 1) << 3)) * 2);
                    uint32_t bh[2], bl[2];
                    ldsm2(bh, sb + W2_HI + bo);
                    ldsm2(bl, sb + W2_LO + bo);
#pragma unroll
                    for (int fi = 0; fi < 2; fi++) {
                        mma_bf16(acc2[fi][fj], ahi[fi], bh);
                        mma_bf16(acc2[fi][fj], ahi[fi], bl);
                        mma_bf16(acc2[fi][fj], alo[fi], bh);
                    }
                }
            }

            // fused final dot over this warp's 16 cols
#pragma unroll
            for (int fi = 0; fi < 2; fi++) {
#pragma unroll
                for (int half = 0; half < 2; half++) {
                    int r = mB + 16 * fi + (lane >> 2) + half * 8;
                    float part = 0.f;
#pragma unroll
                    for (int fj = 0; fj < 2; fj++) {
#pragma unroll
                        for (int qq = 0; qq < 2; qq++) {
                            int c = nB + 8 * fj + (lane & 3) * 2 + qq;
                            float v = lrelu(acc2[fi][fj][half * 2 + qq] + bm2[c]);
                            part += v * wm3[c];
                        }
                    }
                    part += __shfl_xor_sync(0xffffffffu, part, 1);
                    part += __shfl_xor_sync(0xffffffffu, part, 2);
                    if ((lane & 3) == 0) st[r * 4 + (wid >> 1)] = part;
                }
            }
        }
        __syncthreads();
        if (t < 64) {
            int e = rowBase + t;
            if (e < E)
                out[e] = st[t * 4] + st[t * 4 + 1] + st[t * 4 + 2] + st[t * 4 + 3] + bm3[0];
        }
        __syncthreads();
    }
}

// ------------------------------ split / prep kernels ----------------------
__global__ void split_act_kernel(const float* __restrict__ X,
                                 __nv_bfloat16* __restrict__ hi, __nv_bfloat16* __restrict__ lo,
                                 int n, int colsMask,
                                 const float* __restrict__ sc, const float* __restrict__ sh)
{
    int i = blockIdx.x * blockDim.x + threadIdx.x;
    if (i >= n) return;
    float v = X[i];
    if (sc) {
        int c = i & colsMask;
        v = lrelu(v * sc[c] + sh[c]);
    }
    __nv_bfloat16 h = __float2bfloat16_rn(v);
    hi[i] = h;
    lo[i] = __float2bfloat16_rn(v - __bfloat162float(h));
}

// BN apply (no act) + split + in-place fp32 writeback (for h2)
__global__ void bn_apply_split_kernel(float* __restrict__ X,
                                      __nv_bfloat16* __restrict__ hi, __nv_bfloat16* __restrict__ lo,
                                      int n, int colsMask,
                                      const float* __restrict__ sc, const float* __restrict__ sh)
{
    int i = blockIdx.x * blockDim.x + threadIdx.x;
    if (i >= n) return;
    int c = i & colsMask;
    float v = X[i] * sc[c] + sh[c];
    X[i] = v;
    __nv_bfloat16 h = __float2bfloat16_rn(v);
    hi[i] = h;
    lo[i] = __float2bfloat16_rn(v - __bfloat162float(h));
}

__global__ void split_wt_kernel(const float* __restrict__ W,
                                __nv_bfloat16* __restrict__ hi, __nv_bfloat16* __restrict__ lo,
                                int K, int C)
{
    int i = blockIdx.x * blockDim.x + threadIdx.x;
    if (i >= K * C) return;
    int k = i / C, c = i % C;
    float v = W[i];
    __nv_bfloat16 h = __float2bfloat16_rn(v);
    hi[(size_t)c * K + k] = h;
    lo[(size_t)c * K + k] = __float2bfloat16_rn(v - __bfloat162float(h));
}

__global__ void split_wp_kernel(const float* __restrict__ Wm1,
                                __nv_bfloat16* __restrict__ hi, __nv_bfloat16* __restrict__ lo)
{
    int i = blockIdx.x * blockDim.x + threadIdx.x;
    if (i >= 64 * 256) return;
    int c = i >> 6, k = i & 63;
    float v = (c < 128) ? Wm1[k * 128 + c] : Wm1[(64 + k) * 128 + (c - 128)];
    __nv_bfloat16 h = __float2bfloat16_rn(v);
    hi[i] = h;
    lo[i] = __float2bfloat16_rn(v - __bfloat162float(h));
}

// ------------------------------ CSR build ---------------------------------
__global__ void init_deg_kernel(int* __restrict__ deg, int n)
{
    int i = blockIdx.x * blockDim.x + threadIdx.x;
    if (i < n) deg[i] = 1;
}

__global__ void count_kernel(const int* __restrict__ ei, int E, int* __restrict__ deg)
{
    int i = blockIdx.x * blockDim.x + threadIdx.x;
    if (i < E) atomicAdd(&deg[ei[E + i]], 1);
}

__global__ void scan_kernel(const int* __restrict__ deg, int* __restrict__ off, int n)
{
    __shared__ int sh[1024];
    __shared__ int carry_s;
    int t = threadIdx.x;
    if (t == 0) carry_s = 0;
    __syncthreads();
    for (int base = 0; base < n; base += 1024) {
        int i = base + t;
        int v = (i < n) ? deg[i] : 0;
        sh[t] = v;
        __syncthreads();
        int sum = v;
        for (int ofs = 1; ofs < 1024; ofs <<= 1) {
            int add = (t >= ofs) ? sh[t - ofs] : 0;
            __syncthreads();
            sum += add;
            sh[t] = sum;
            __syncthreads();
        }
        int carry = carry_s;
        if (i < n) off[i] = carry + sum - v;
        __syncthreads();
        if (t == 1023) carry_s = carry + sum;
        __syncthreads();
    }
    if (t == 0) off[n] = carry_s;
}

__global__ void copy_cur_kernel(const int* __restrict__ off, int* __restrict__ cur, int n)
{
    int i = blockIdx.x * blockDim.x + threadIdx.x;
    if (i < n) cur[i] = off[i];
}

__global__ void scatter_edges_kernel(const int* __restrict__ ei, int E,
                                     int* __restrict__ cur,
                                     int* __restrict__ csrc, int* __restrict__ cdst)
{
    int i = blockIdx.x * blockDim.x + threadIdx.x;
    if (i >= E) return;
    int d = ei[E + i];
    int pos = atomicAdd(&cur[d], 1);
    csrc[pos] = ei[i];
    cdst[pos] = d;
}

__global__ void scatter_loops_kernel(int N, int* __restrict__ cur,
                                     int* __restrict__ csrc, int* __restrict__ cdst)
{
    int n = blockIdx.x * blockDim.x + threadIdx.x;
    if (n >= N) return;
    int pos = atomicAdd(&cur[n], 1);
    csrc[pos] = n;
    cdst[pos] = n;
}

// ------------------------------ GAT attention -----------------------------
__global__ void maxwatt_kernel(const float4* __restrict__ asrc4, const float4* __restrict__ adst4,
                               const int* __restrict__ off, const int* __restrict__ csrc,
                               float4* __restrict__ watt4, int N)
{
    int w = (blockIdx.x * blockDim.x + threadIdx.x) >> 5;
    int lane = threadIdx.x & 31;
    if (w >= N) return;
    float4 ad = adst4[w];
    int lo = off[w], hi = off[w + 1];
    float m0 = -1e30f, m1 = -1e30f, m2 = -1e30f, m3 = -1e30f;
    for (int p = lo + lane; p < hi; p += 32) {
        int s = csrc[p];
        float4 as = asrc4[s];
        m0 = fmaxf(m0, lrelu(as.x + ad.x));
        m1 = fmaxf(m1, lrelu(as.y + ad.y));
        m2 = fmaxf(m2, lrelu(as.z + ad.z));
        m3 = fmaxf(m3, lrelu(as.w + ad.w));
    }
#pragma unroll
    for (int o = 16; o > 0; o >>= 1) {
        m0 = fmaxf(m0, __shfl_xor_sync(0xffffffffu, m0, o));
        m1 = fmaxf(m1, __shfl_xor_sync(0xffffffffu, m1, o));
        m2 = fmaxf(m2, __shfl_xor_sync(0xffffffffu, m2, o));
        m3 = fmaxf(m3, __shfl_xor_sync(0xffffffffu, m3, o));
    }
    for (int p = lo + lane; p < hi; p += 32) {
        int s = csrc[p];
        float4 as = asrc4[s];
        watt4[p] = make_float4(expf(lrelu(as.x + ad.x) - m0),
                               expf(lrelu(as.y + ad.y) - m1),
                               expf(lrelu(as.z + ad.z) - m2),
                               expf(lrelu(as.w + ad.w) - m3));
    }
}

__global__ __launch_bounds__(128) void gat_aggregate_kernel(
    const float* __restrict__ h, const float* __restrict__ watt,
    const int* __restrict__ off, const int* __restrict__ csrc,
    const float* __restrict__ bias, float* __restrict__ out, int concat)
{
    int d = blockIdx.x;
    int t = threadIdx.x;            // 128
    int c = t * 2;
    int hh = t >> 5;
    int lo = off[d], hi = off[d + 1];
    float accx = 0.f, accy = 0.f, den = 0.f;
    int p = lo;
    for (; p + 4 <= hi; p += 4) {
        int s0 = csrc[p], s1 = csrc[p + 1], s2 = csrc[p + 2], s3 = csrc[p + 3];
        float w0 = watt[p * 4 + hh], w1 = watt[(p + 1) * 4 + hh];
        float w2 = watt[(p + 2) * 4 + hh], w3 = watt[(p + 3) * 4 + hh];
        float2 h0 = *(const float2*)(h + (size_t)s0 * 256 + c);
        float2 h1 = *(const float2*)(h + (size_t)s1 * 256 + c);
        float2 h2v = *(const float2*)(h + (size_t)s2 * 256 + c);
        float2 h3 = *(const float2*)(h + (size_t)s3 * 256 + c);
        den += (w0 + w1) + (w2 + w3);
        accx += w0 * h0.x + w1 * h1.x + w2 * h2v.x + w3 * h3.x;
        accy += w0 * h0.y + w1 * h1.y + w2 * h2v.y + w3 * h3.y;
    }
    for (; p < hi; ++p) {
        int s = csrc[p];
        float w = watt[p * 4 + hh];
        float2 hv = *(const float2*)(h + (size_t)s * 256 + c);
        den += w;
        accx += w * hv.x;
        accy += w * hv.y;
    }
    float inv = 1.f / den;
    accx *= inv; accy *= inv;
    if (concat) {
        *(float2*)(out + (size_t)d * 256 + c) =
            make_float2(accx + bias[c], accy + bias[c + 1]);
    } else {
        __shared__ float red[256];
        red[c] = accx; red[c + 1] = accy;
        __syncthreads();
        if (t < 32) {
#pragma unroll
            for (int j = 0; j < 2; j++) {
                int cc = t * 2 + j;
                out[(size_t)d * 64 + cc] =
                    0.25f * (red[cc] + red[cc + 64] + red[cc + 128] + red[cc + 192]) + bias[cc];
            }
        }
    }
}

// ------------------------------ fused BatchNorm stats+final ---------------
__global__ void bn_stats_fused_kernel(const float* __restrict__ X, int rows, int cols,
                                      float* __restrict__ stats,
                                      const float* __restrict__ g, const float* __restrict__ be,
                                      float* __restrict__ sc, float* __restrict__ sh,
                                      int rowsPerBlock)
{
    __shared__ int isLast;
    int t = threadIdx.x;
    int c = t % cols;
    int rsub = t / cols;
    int rstep = 256 / cols;
    int r0 = blockIdx.x * rowsPerBlock;
    int r1 = r0 + rowsPerBlock; if (r1 > rows) r1 = rows;
    float s = 0.f, s2 = 0.f;
    for (int r = r0 + rsub; r < r1; r += rstep) {
        float v = X[(size_t)r * cols + c];
        s += v;
        s2 += v * v;
    }
    atomicAdd(&stats[c], s);
    atomicAdd(&stats[cols + c], s2);
    __threadfence();
    if (t == 0) {
        int done = atomicAdd(&g_bncnt, 1);
        isLast = (done == gridDim.x - 1);
    }
    __syncthreads();
    if (isLast) {
        if (t < cols) {
            float inv = 1.f / (float)rows;
            float mean = stats[t] * inv;
            float var = stats[cols + t] * inv - mean * mean;
            float scale = g[t] * rsqrtf(var + EPSBN);
            sc[t] = scale;
            sh[t] = be[t] - mean * scale;
            stats[t] = 0.f;
            stats[cols + t] = 0.f;
        }
        __threadfence();
        if (t == 0) *((volatile int*)&g_bncnt) = 0;
    }
}

// ------------------------------ host orchestration ------------------------
extern "C" void kernel_launch(void* const* d_in, const int* in_sizes, int n_in,
                              void* d_out, int out_size)
{
    const float* x  = (const float*)d_in[0];
    const int*   ei = (const int*)d_in[1];
    const float* ea = (const float*)d_in[2];
    const int N = in_sizes[0] / 128;
    const int E = in_sizes[2];

    const float *W0, *as0, *ad0, *b0, *g0, *be0;
    const float *W1, *as1, *ad1, *b1, *g1, *be1;
    const float *W2, *as2, *ad2, *b2, *g2, *be2;
    if (in_sizes[7] == 256 * 256) {
        W0 = (const float*)d_in[3];  as0 = (const float*)d_in[4];  ad0 = (const float*)d_in[5];  b0 = (const float*)d_in[6];
        W1 = (const float*)d_in[7];  as1 = (const float*)d_in[8];  ad1 = (const float*)d_in[9];  b1 = (const float*)d_in[10];
        W2 = (const float*)d_in[11]; as2 = (const float*)d_in[12]; ad2 = (const float*)d_in[13]; b2 = (const float*)d_in[14];
        g0 = (const float*)d_in[15]; be0 = (const float*)d_in[16];
        g1 = (const float*)d_in[17]; be1 = (const float*)d_in[18];
        g2 = (const float*)d_in[19]; be2 = (const float*)d_in[20];
    } else {
        W0 = (const float*)d_in[3];  as0 = (const float*)d_in[4];  ad0 = (const float*)d_in[5];  b0 = (const float*)d_in[6];
        g0 = (const float*)d_in[7];  be0 = (const float*)d_in[8];
        W1 = (const float*)d_in[9];  as1 = (const float*)d_in[10]; ad1 = (const float*)d_in[11]; b1 = (const float*)d_in[12];
        g1 = (const float*)d_in[13]; be1 = (const float*)d_in[14];
        W2 = (const float*)d_in[15]; as2 = (const float*)d_in[16]; ad2 = (const float*)d_in[17]; b2 = (const float*)d_in[18];
        g2 = (const float*)d_in[19]; be2 = (const float*)d_in[20];
    }
    const float* Wm1 = (const float*)d_in[21];
    const float* bm1 = (const float*)d_in[22];
    const float* Wm2 = (const float*)d_in[23];
    const float* bm2 = (const float*)d_in[24];
    const float* Wm3 = (const float*)d_in[25];
    const float* bm3 = (const float*)d_in[26];
    float* out = (float*)d_out;

    float *bufA, *bufB, *h2, *asrc, *adst, *watt, *stats, *bnsc, *bnsh;
    int *deg, *off, *cur, *csrc, *cdst;
    __nv_bfloat16 *xhi, *xlo;
    __nv_bfloat16 *w0hi, *w0lo, *w1hi, *w1lo, *w2hi, *w2lo;
    __nv_bfloat16 *wphi, *wplo, *cthi, *ctlo, *wm2hi, *wm2lo;
    cudaGetSymbolAddress((void**)&bufA, g_bufA);
    cudaGetSymbolAddress((void**)&bufB, g_bufB);
    cudaGetSymbolAddress((void**)&h2, g_h2);
    cudaGetSymbolAddress((void**)&asrc, g_asrc);
    cudaGetSymbolAddress((void**)&adst, g_adst);
    cudaGetSymbolAddress((void**)&watt, g_watt);
    cudaGetSymbolAddress((void**)&stats, g_stats);
    cudaGetSymbolAddress((void**)&bnsc, g_bnsc);
    cudaGetSymbolAddress((void**)&bnsh, g_bnsh);
    cudaGetSymbolAddress((void**)&deg, g_deg);
    cudaGetSymbolAddress((void**)&off, g_off);
    cudaGetSymbolAddress((void**)&cur, g_cur);
    cudaGetSymbolAddress((void**)&csrc, g_csrc);
    cudaGetSymbolAddress((void**)&cdst, g_cdst);
    cudaGetSymbolAddress((void**)&xhi, g_xhi);
    cudaGetSymbolAddress((void**)&xlo, g_xlo);
    cudaGetSymbolAddress((void**)&w0hi, g_w0hi);  cudaGetSymbolAddress((void**)&w0lo, g_w0lo);
    cudaGetSymbolAddress((void**)&w1hi, g_w1hi);  cudaGetSymbolAddress((void**)&w1lo, g_w1lo);
    cudaGetSymbolAddress((void**)&w2hi, g_w2hi);  cudaGetSymbolAddress((void**)&w2lo, g_w2lo);
    cudaGetSymbolAddress((void**)&wphi, g_wphi);  cudaGetSymbolAddress((void**)&wplo, g_wplo);
    cudaGetSymbolAddress((void**)&cthi, g_cthi);  cudaGetSymbolAddress((void**)&ctlo, g_ctlo);
    cudaGetSymbolAddress((void**)&wm2hi, g_wm2hi); cudaGetSymbolAddress((void**)&wm2lo, g_wm2lo);

    const int STAGE = 48 * 1024;
    const int SM2 = 2 * STAGE;
    const int SMEDGE = 112 * 1024;
    cudaFuncSetAttribute(hmma_gemm<0>, cudaFuncAttributeMaxDynamicSharedMemorySize, SM2);
    cudaFuncSetAttribute(hmma_gemm<1>, cudaFuncAttributeMaxDynamicSharedMemorySize, SM2);
    cudaFuncSetAttribute(edge_mlp_kernel, cudaFuncAttributeMaxDynamicSharedMemorySize, SMEDGE);

    auto node_gemm = [&](const __nv_bfloat16* Ah, const __nv_bfloat16* Al,
                         const __nv_bfloat16* Bh, const __nv_bfloat16* Bl,
                         float* C, int M, int Kt, int Ncols,
                         const float* aws, const float* awd) {
        dim3 grid((M + 127) / 128, Ncols / 64);
        int smem = (Kt > 64) ? SM2 : STAGE;
        if (aws)
            hmma_gemm<1><<<grid, 256, smem>>>(Ah, Al, Bh, Bl, C, M, Kt, Ncols,
                                              aws, awd, asrc, adst);
        else
            hmma_gemm<0><<<grid, 256, smem>>>(Ah, Al, Bh, Bl, C, M, Kt, Ncols,
                                              nullptr, nullptr, nullptr, nullptr);
    };

    // ---- launches 1-4: profiled launch (#4) is the L0 GEMM ----
    split_act_kernel<<<(N * 128 + 255) / 256, 256>>>(x, xhi, xlo, N * 128, 127, nullptr, nullptr);
    split_wt_kernel<<<(128 * 256 + 255) / 256, 256>>>(W0, w0hi, w0lo, 128, 256);
    init_deg_kernel<<<(N + 255) / 256, 256>>>(deg, N);
    node_gemm(xhi, xlo, w0hi, w0lo, bufA, N, 128, 256, as0, ad0);   // launch #4

    // ---- CSR build ----
    count_kernel<<<(E + 255) / 256, 256>>>(ei, E, deg);
    scan_kernel<<<1, 1024>>>(deg, off, N);
    copy_cur_kernel<<<(N + 255) / 256, 256>>>(off, cur, N);
    scatter_edges_kernel<<<(E + 255) / 256, 256>>>(ei, E, cur, csrc, cdst);
    scatter_loops_kernel<<<(N + 255) / 256, 256>>>(N, cur, csrc, cdst);

    auto attention = [&](const float* hbuf, const float* bias, float* outbuf, int concat) {
        maxwatt_kernel<<<(N * 32 + 255) / 256, 256>>>((const float4*)asrc, (const float4*)adst,
                                                      off, csrc, (float4*)watt, N);
        gat_aggregate_kernel<<<N, 128>>>(hbuf, watt, off, csrc, bias, outbuf, concat);
    };

    auto bnstats = [&](const float* X, int cols, const float* g, const float* be) {
        bn_stats_fused_kernel<<<(N + 255) / 256, 256>>>(X, N, cols, stats, g, be,
                                                        bnsc, bnsh, 256);
    };

    // ---- layer 0 ----
    attention(bufA, b0, bufB, 1);
    bnstats(bufB, 256, g0, be0);
    split_act_kernel<<<(N * 256 + 255) / 256, 256>>>(bufB, xhi, xlo, N * 256, 255, bnsc, bnsh);

    // ---- layer 1 ----
    split_wt_kernel<<<(256 * 256 + 255) / 256, 256>>>(W1, w1hi, w1lo, 256, 256);
    node_gemm(xhi, xlo, w1hi, w1lo, bufA, N, 256, 256, as1, ad1);
    attention(bufA, b1, bufB, 1);
    bnstats(bufB, 256, g1, be1);
    split_act_kernel<<<(N * 256 + 255) / 256, 256>>>(bufB, xhi, xlo, N * 256, 255, bnsc, bnsh);

    // ---- layer 2 ----
    split_wt_kernel<<<(256 * 256 + 255) / 256, 256>>>(W2, w2hi, w2lo, 256, 256);
    node_gemm(xhi, xlo, w2hi, w2lo, bufA, N, 256, 256, as2, ad2);
    attention(bufA, b2, h2, 0);
    bnstats(h2, 64, g2, be2);
    bn_apply_split_kernel<<<(N * 64 + 255) / 256, 256>>>(h2, xhi, xlo, N * 64, 63, bnsc, bnsh);

    // ---- edge MLP ----
    split_wp_kernel<<<(64 * 256 + 255) / 256, 256>>>(Wm1, wphi, wplo);
    node_gemm(xhi, xlo, wphi, wplo, bufA, N, 64, 256, nullptr, nullptr);  // PQ

    split_wt_kernel<<<(64 * 128 + 255) / 256, 256>>>(Wm1 + 128 * 128, cthi, ctlo, 64, 128);
    split_wt_kernel<<<(128 * 64 + 255) / 256, 256>>>(Wm2, wm2hi, wm2lo, 128, 64);

    const int nTiles = (E + 63) / 64;
    edge_mlp_kernel<<<296, 256, SMEDGE>>>(
        cthi, ctlo, wm2hi, wm2lo, ei, E, h2, bufA, ea,
        Wm1 + 192 * 128, bm1, bm2, Wm3, bm3, out, nTiles);
}

// round 12
// speedup vs baseline: 2.6474x; 1.0329x over previous
#include <cuda_runtime.h>
#include <cuda_bf16.h>
#include <math.h>
#include <stdint.h>

#define NSLOPE 0.2f
#define EPSBN 1e-5f
#define NMAX 50000
#define EMAX 800000
#define TOTMAX (EMAX + NMAX)

// ------------------------------ scratch (device globals; no allocation) ---
__device__ float g_bufA[(size_t)NMAX * 256];
__device__ float g_bufB[(size_t)NMAX * 256];
__device__ float g_h2[(size_t)NMAX * 64];
__device__ float g_asrc[(size_t)NMAX * 4];
__device__ float g_adst[(size_t)NMAX * 4];
__device__ float g_watt[(size_t)TOTMAX * 4];
__device__ int   g_deg[NMAX];
__device__ int   g_off[NMAX + 1];
__device__ int   g_cur[NMAX];
__device__ int   g_csrc[TOTMAX];
__device__ int   g_cdst[TOTMAX];
__device__ float g_stats[512];          // zero-init; self-cleaning
__device__ int   g_bncnt;               // zero-init; self-cleaning
__device__ float g_bnsc[256];
__device__ float g_bnsh[256];
// split-bf16 buffers
__device__ __nv_bfloat16 g_xhi[(size_t)NMAX * 256];
__device__ __nv_bfloat16 g_xlo[(size_t)NMAX * 256];
__device__ __nv_bfloat16 g_w0hi[256 * 128],  g_w0lo[256 * 128];
__device__ __nv_bfloat16 g_w1hi[256 * 256],  g_w1lo[256 * 256];
__device__ __nv_bfloat16 g_w2hi[256 * 256],  g_w2lo[256 * 256];
__device__ __nv_bfloat16 g_wphi[256 * 64],   g_wplo[256 * 64];
__device__ __nv_bfloat16 g_cthi[128 * 64],   g_ctlo[128 * 64];
__device__ __nv_bfloat16 g_wm2hi[64 * 128],  g_wm2lo[64 * 128];

__device__ __forceinline__ float lrelu(float v) { return v > 0.f ? v : NSLOPE * v; }

// ======================= HMMA helpers =====================================
#define SW(o) ((o) ^ (((o) >> 3) & 0x70))

__device__ __forceinline__ uint32_t s2u(const void* p) {
    uint32_t a;
    asm("{ .reg .u64 t; cvta.to.shared.u64 t, %1; cvt.u32.u64 %0, t; }" : "=r"(a) : "l"(p));
    return a;
}

__device__ __forceinline__ void mma_bf16(float* c, const uint32_t* a, const uint32_t* b) {
    asm volatile(
        "mma.sync.aligned.m16n8k16.row.col.f32.bf16.bf16.f32 "
        "{%0,%1,%2,%3}, {%4,%5,%6,%7}, {%8,%9}, {%0,%1,%2,%3};"
        : "+f"(c[0]), "+f"(c[1]), "+f"(c[2]), "+f"(c[3])
        : "r"(a[0]), "r"(a[1]), "r"(a[2]), "r"(a[3]), "r"(b[0]), "r"(b[1]));
}

__device__ __forceinline__ void ldsm4(uint32_t* r, uint32_t addr) {
    asm volatile("ldmatrix.sync.aligned.m8n8.x4.shared.b16 {%0,%1,%2,%3}, [%4];"
                 : "=r"(r[0]), "=r"(r[1]), "=r"(r[2]), "=r"(r[3]) : "r"(addr));
}

__device__ __forceinline__ void ldsm2(uint32_t* r, uint32_t addr) {
    asm volatile("ldmatrix.sync.aligned.m8n8.x2.shared.b16 {%0,%1}, [%2];"
                 : "=r"(r[0]), "=r"(r[1]) : "r"(addr));
}

__device__ __forceinline__ void cpasync16(uint32_t saddr, const void* g) {
    asm volatile("cp.async.cg.shared.global [%0], [%1], 16;" :: "r"(saddr), "l"(g));
}

__device__ __forceinline__ uint32_t bfbits(float v) {
    __nv_bfloat16 b = __float2bfloat16_rn(v);
    return (uint32_t)__bfloat16_as_ushort(b);
}
__device__ __forceinline__ float bfval(uint32_t bits) {
    return __bfloat162float(__ushort_as_bfloat16((unsigned short)bits));
}

// ======================= split-bf16 HMMA node GEMM ========================
template <int ALPHA>
__global__ __launch_bounds__(256, 2) void hmma_gemm(
    const __nv_bfloat16* __restrict__ Ahi, const __nv_bfloat16* __restrict__ Alo,
    const __nv_bfloat16* __restrict__ Bhi, const __nv_bfloat16* __restrict__ Blo,
    float* __restrict__ C, int M, int Kt, int ldc,
    const float* __restrict__ aws, const float* __restrict__ awd,
    float* __restrict__ asrcO, float* __restrict__ adstO)
{
    extern __shared__ char sm[];
    constexpr int A_HI = 0;
    constexpr int A_LO = 128 * 128;
    constexpr int B_HI = 2 * 128 * 128;
    constexpr int B_LO = 2 * 128 * 128 + 64 * 128;
    constexpr int STAGE = 2 * 128 * 128 + 2 * 64 * 128;   // 48 KB

    const uint32_t sb = s2u(sm);
    const int t = threadIdx.x;
    const int wid = t >> 5, lane = t & 31;
    const int rowBase = blockIdx.x * 128;
    const int colBase = blockIdx.y * 64;
    const int mBase = (wid & 3) * 32;
    const int nBase = (wid >> 2) * 32;

    float acc[2][4][4];
#pragma unroll
    for (int i = 0; i < 2; i++)
#pragma unroll
        for (int j = 0; j < 4; j++)
#pragma unroll
            for (int q = 0; q < 4; q++) acc[i][j][q] = 0.f;

    auto do_mma = [&](int st) {
        const uint32_t base = sb + st * STAGE;
#pragma unroll
        for (int ks = 0; ks < 4; ks++) {
            const int k0 = ks * 16;
            uint32_t ahi[2][4], alo[2][4];
#pragma unroll
            for (int fi = 0; fi < 2; fi++) {
                int row = mBase + 16 * fi + (lane & 15);
                int bo = SW(row * 128 + (k0 + ((lane >> 4) << 3)) * 2);
                ldsm4(ahi[fi], base + A_HI + bo);
                ldsm4(alo[fi], base + A_LO + bo);
            }
#pragma unroll
            for (int fj = 0; fj < 4; fj++) {
                int row = nBase + 8 * fj + (lane & 7);
                int bo = SW(row * 128 + (k0 + (((lane >> 3) & 1) << 3)) * 2);
                uint32_t bh[2], bl[2];
                ldsm2(bh, base + B_HI + bo);
                ldsm2(bl, base + B_LO + bo);
#pragma unroll
                for (int fi = 0; fi < 2; fi++) {
                    mma_bf16(acc[fi][fj], ahi[fi], bh);
                    mma_bf16(acc[fi][fj], ahi[fi], bl);
                    mma_bf16(acc[fi][fj], alo[fi], bh);
                }
            }
        }
    };

    auto load_chunk = [&](int kc, int st) {
        const uint32_t base = sb + st * STAGE;
#pragma unroll
        for (int it = 0; it < 4; it++) {
            int idx = t + it * 256;
            int r = idx >> 3, q = idx & 7;
            int gm = rowBase + r; if (gm >= M) gm = 0;
            size_t goff = (size_t)gm * Kt + kc + q * 8;
            uint32_t sa = base + A_HI + SW(r * 128 + q * 16);
            cpasync16(sa, Ahi + goff);
            cpasync16(sa + (A_LO - A_HI), Alo + goff);
        }
#pragma unroll
        for (int it = 0; it < 2; it++) {
            int idx = t + it * 256;
            int n = idx >> 3, q = idx & 7;
            size_t goff = (size_t)(colBase + n) * Kt + kc + q * 8;
            uint32_t sa = base + B_HI + SW(n * 128 + q * 16);
            cpasync16(sa, Bhi + goff);
            cpasync16(sa + (B_LO - B_HI), Blo + goff);
        }
        asm volatile("cp.async.commit_group;" ::: "memory");
    };

    const int nch = Kt >> 6;
    load_chunk(0, 0);
    for (int i = 0; i < nch; i++) {
        if (i + 1 < nch) {
            load_chunk((i + 1) << 6, (i + 1) & 1);
            asm volatile("cp.async.wait_group 1;" ::: "memory");
        } else {
            asm volatile("cp.async.wait_group 0;" ::: "memory");
        }
        __syncthreads();
        do_mma(i & 1);
        __syncthreads();
    }

    // ---- C writeback ----
#pragma unroll
    for (int fi = 0; fi < 2; fi++) {
        int r0 = rowBase + mBase + 16 * fi + (lane >> 2);
#pragma unroll
        for (int fj = 0; fj < 4; fj++) {
            int c = colBase + nBase + 8 * fj + (lane & 3) * 2;
            if (r0 < M)
                *(float2*)(C + (size_t)r0 * ldc + c) =
                    make_float2(acc[fi][fj][0], acc[fi][fj][1]);
            if (r0 + 8 < M)
                *(float2*)(C + (size_t)(r0 + 8) * ldc + c) =
                    make_float2(acc[fi][fj][2], acc[fi][fj][3]);
        }
    }

    if (ALPHA) {
        const int head = blockIdx.y;
        float ps[2][2] = {{0.f, 0.f}, {0.f, 0.f}};
        float pd[2][2] = {{0.f, 0.f}, {0.f, 0.f}};
#pragma unroll
        for (int fj = 0; fj < 4; fj++)
#pragma unroll
            for (int qq = 0; qq < 2; qq++) {
                int dim = nBase + 8 * fj + (lane & 3) * 2 + qq;
                float ws = __ldg(aws + head * 64 + dim);
                float wd = __ldg(awd + head * 64 + dim);
#pragma unroll
                for (int fi = 0; fi < 2; fi++)
#pragma unroll
                    for (int half = 0; half < 2; half++) {
                        float a = acc[fi][fj][half * 2 + qq];
                        ps[fi][half] += a * ws;
                        pd[fi][half] += a * wd;
                    }
            }
        float* ared = (float*)sm;      // 512 floats
#pragma unroll
        for (int fi = 0; fi < 2; fi++)
#pragma unroll
            for (int half = 0; half < 2; half++) {
                float vs = ps[fi][half], vd = pd[fi][half];
                vs += __shfl_xor_sync(0xffffffffu, vs, 1);
                vs += __shfl_xor_sync(0xffffffffu, vs, 2);
                vd += __shfl_xor_sync(0xffffffffu, vd, 1);
                vd += __shfl_xor_sync(0xffffffffu, vd, 2);
                if ((lane & 3) == 0) {
                    int r = mBase + 16 * fi + (lane >> 2) + 8 * half;
                    int wc = wid >> 2;
                    ared[r * 2 + wc] = vs;
                    ared[256 + r * 2 + wc] = vd;
                }
            }
        __syncthreads();
        if (t < 128) {
            int gm = rowBase + t;
            if (gm < M) {
                asrcO[gm * 4 + head] = ared[t * 2] + ared[t * 2 + 1];
                adstO[gm * 4 + head] = ared[256 + t * 2] + ared[256 + t * 2 + 1];
            }
        }
    }
}

// ======================= persistent fused edge MLP ========================
__global__ __launch_bounds__(256, 2) void edge_mlp_kernel(
    const __nv_bfloat16* __restrict__ cthi, const __nv_bfloat16* __restrict__ ctlo,
    const __nv_bfloat16* __restrict__ wm2hi, const __nv_bfloat16* __restrict__ wm2lo,
    const int* __restrict__ ei, int E, const float* __restrict__ h2g,
    const float* __restrict__ PQ, const float* __restrict__ ea,
    const float* __restrict__ w192, const float* __restrict__ bm1,
    const float* __restrict__ bm2, const float* __restrict__ wm3,
    const float* __restrict__ bm3, float* __restrict__ out, int nTiles)
{
    extern __shared__ char sm[];
    constexpr int SA_HI = 0;
    constexpr int SA_LO = 8192;
    constexpr int CT_HI = 16384;
    constexpr int CT_LO = 32768;
    constexpr int T1_HI = 49152;
    constexpr int T1_LO = 65536;
    constexpr int W2_HI = 81920;
    constexpr int W2_LO = 98304;        // total 112 KB

    const uint32_t sb = s2u(sm);
    const int t = threadIdx.x;
    const int wid = t >> 5, lane = t & 31;

    // ---- one-time weight loads ----
#pragma unroll
    for (int it = 0; it < 4; it++) {
        int idx = t + it * 256;
        int n = idx >> 3, q = idx & 7;
        uint32_t sa = sb + CT_HI + SW(n * 128 + q * 16);
        cpasync16(sa, cthi + (size_t)n * 64 + q * 8);
        cpasync16(sa + (CT_LO - CT_HI), ctlo + (size_t)n * 64 + q * 8);
    }
#pragma unroll
    for (int it = 0; it < 4; it++) {
        int idx = t + it * 256;
        int n = idx >> 4, q = idx & 15;
        int kc = q >> 3, kin = (q & 7) * 16;
        uint32_t sa = sb + W2_HI + kc * 8192 + SW(n * 128 + kin);
        cpasync16(sa, wm2hi + (size_t)n * 128 + q * 8);
        cpasync16(sa + (W2_LO - W2_HI), wm2lo + (size_t)n * 128 + q * 8);
    }
    asm volatile("cp.async.commit_group;" ::: "memory");
    asm volatile("cp.async.wait_group 0;" ::: "memory");

    for (int tile = blockIdx.x; tile < nTiles; tile += gridDim.x) {
        const int rowBase = tile * 64;

#pragma unroll
        for (int it = 0; it < 4; it++) {
            int idx = t + it * 256;
            int r = idx >> 4, q = idx & 15;
            int e = rowBase + r; if (e >= E) e = E - 1;
            int s = ei[e], d = ei[E + e];
            float4 a4 = *(const float4*)(h2g + (size_t)s * 64 + q * 4);
            float4 b4 = *(const float4*)(h2g + (size_t)d * 64 + q * 4);
            float4 v = make_float4(fabsf(a4.x - b4.x), fabsf(a4.y - b4.y),
                                   fabsf(a4.z - b4.z), fabsf(a4.w - b4.w));
            uint32_t hx = bfbits(v.x), hy = bfbits(v.y), hz = bfbits(v.z), hw = bfbits(v.w);
            uint32_t lx = bfbits(v.x - bfval(hx)), ly = bfbits(v.y - bfval(hy));
            uint32_t lz = bfbits(v.z - bfval(hz)), lw = bfbits(v.w - bfval(hw));
            int so = SW(r * 128 + q * 8);
            *(uint2*)(sm + SA_HI + so) = make_uint2(hx | (hy << 16), hz | (hw << 16));
            *(uint2*)(sm + SA_LO + so) = make_uint2(lx | (ly << 16), lz | (lw << 16));
        }
        __syncthreads();

        // ---- MMA1: 8 warps, 2M x 4N, K=64 ----
        {
            const int mBase = (wid & 1) * 32;
            const int nBase = (wid >> 1) * 32;
            float acc[2][4][4];
#pragma unroll
            for (int i = 0; i < 2; i++)
#pragma unroll
                for (int j = 0; j < 4; j++)
#pragma unroll
                    for (int q = 0; q < 4; q++) acc[i][j][q] = 0.f;

#pragma unroll
            for (int ks = 0; ks < 4; ks++) {
                const int k0 = ks * 16;
                uint32_t ahi[2][4], alo[2][4];
#pragma unroll
                for (int fi = 0; fi < 2; fi++) {
                    int row = mBase + 16 * fi + (lane & 15);
                    int bo = SW(row * 128 + (k0 + ((lane >> 4) << 3)) * 2);
                    ldsm4(ahi[fi], sb + SA_HI + bo);
                    ldsm4(alo[fi], sb + SA_LO + bo);
                }
#pragma unroll
                for (int fj = 0; fj < 4; fj++) {
                    int row = nBase + 8 * fj + (lane & 7);
                    int bo = SW(row * 128 + (k0 + (((lane >> 3) & 1) << 3)) * 2);
                    uint32_t bh[2], bl[2];
                    ldsm2(bh, sb + CT_HI + bo);
                    ldsm2(bl, sb + CT_LO + bo);
#pragma unroll
                    for (int fi = 0; fi < 2; fi++) {
                        mma_bf16(acc[fi][fj], ahi[fi], bh);
                        mma_bf16(acc[fi][fj], ahi[fi], bl);
                        mma_bf16(acc[fi][fj], alo[fi], bh);
                    }
                }
            }

#pragma unroll
            for (int fi = 0; fi < 2; fi++) {
#pragma unroll
                for (int half = 0; half < 2; half++) {
                    int r = mBase + 16 * fi + (lane >> 2) + half * 8;
                    int e = rowBase + r; if (e >= E) e = E - 1;
                    int s = ei[e], d = ei[E + e];
                    float eav = ea[e];
                    const float* pqs = PQ + (size_t)s * 256;
                    const float* pqd = PQ + (size_t)d * 256 + 128;
#pragma unroll
                    for (int fj = 0; fj < 4; fj++) {
                        int c = nBase + 8 * fj + (lane & 3) * 2;
                        float2 p1 = *(const float2*)(pqs + c);
                        float2 p2 = *(const float2*)(pqd + c);
                        float2 wv = *(const float2*)(w192 + c);
                        float2 bv = *(const float2*)(bm1 + c);
                        float v0 = lrelu(acc[fi][fj][half * 2 + 0] + p1.x + p2.x + eav * wv.x + bv.x);
                        float v1 = lrelu(acc[fi][fj][half * 2 + 1] + p1.y + p2.y + eav * wv.y + bv.y);
                        uint32_t h0 = bfbits(v0), h1 = bfbits(v1);
                        uint32_t l0 = bfbits(v0 - bfval(h0)), l1 = bfbits(v1 - bfval(h1));
                        int kc = c >> 6, kin = c & 63;
                        int so = kc * 8192 + SW(r * 128 + kin * 2);
                        *(uint32_t*)(sm + T1_HI + so) = h0 | (h1 << 16);
                        *(uint32_t*)(sm + T1_LO + so) = l0 | (l1 << 16);
                    }
                }
            }
        }
        __syncthreads();

        // ---- MMA2: 8 warps, each 32 rows x 16 cols, full K=128 ----
        float* st = (float*)sm;
        {
            const int mB = (wid & 1) * 32;
            const int nB = (wid >> 1) * 16;
            float acc2[2][2][4];
#pragma unroll
            for (int i = 0; i < 2; i++)
#pragma unroll
                for (int j = 0; j < 2; j++)
#pragma unroll
                    for (int q = 0; q < 4; q++) acc2[i][j][q] = 0.f;

#pragma unroll
            for (int ks = 0; ks < 8; ks++) {
                const int kc = ks >> 2, k0 = (ks & 3) * 16;
                uint32_t ahi[2][4], alo[2][4];
#pragma unroll
                for (int fi = 0; fi < 2; fi++) {
                    int row = mB + 16 * fi + (lane & 15);
                    int bo = kc * 8192 + SW(row * 128 + (k0 + ((lane >> 4) << 3)) * 2);
                    ldsm4(ahi[fi], sb + T1_HI + bo);
                    ldsm4(alo[fi], sb + T1_LO + bo);
                }
#pragma unroll
                for (int fj = 0; fj < 2; fj++) {
                    int row = nB + 8 * fj + (lane & 7);
                    int bo = kc * 8192 + SW(row * 128 + (k0 + (((lane >> 3) & 1) << 3)) * 2);
                    uint32_t bh[2], bl[2];
                    ldsm2(bh, sb + W2_HI + bo);
                    ldsm2(bl, sb + W2_LO + bo);
#pragma unroll
                    for (int fi = 0; fi < 2; fi++) {
                        mma_bf16(acc2[fi][fj], ahi[fi], bh);
                        mma_bf16(acc2[fi][fj], ahi[fi], bl);
                        mma_bf16(acc2[fi][fj], alo[fi], bh);
                    }
                }
            }

#pragma unroll
            for (int fi = 0; fi < 2; fi++) {
#pragma unroll
                for (int half = 0; half < 2; half++) {
                    int r = mB + 16 * fi + (lane >> 2) + half * 8;
                    float part = 0.f;
#pragma unroll
                    for (int fj = 0; fj < 2; fj++) {
#pragma unroll
                        for (int qq = 0; qq < 2; qq++) {
                            int c = nB + 8 * fj + (lane & 3) * 2 + qq;
                            float v = lrelu(acc2[fi][fj][half * 2 + qq] + bm2[c]);
                            part += v * wm3[c];
                        }
                    }
                    part += __shfl_xor_sync(0xffffffffu, part, 1);
                    part += __shfl_xor_sync(0xffffffffu, part, 2);
                    if ((lane & 3) == 0) st[r * 4 + (wid >> 1)] = part;
                }
            }
        }
        __syncthreads();
        if (t < 64) {
            int e = rowBase + t;
            if (e < E)
                out[e] = st[t * 4] + st[t * 4 + 1] + st[t * 4 + 2] + st[t * 4 + 3] + bm3[0];
        }
        __syncthreads();
    }
}

// ------------------------------ split / prep kernels ----------------------
// vectorized: one float2 -> bfloat162 pair per thread (same per-element math)
__global__ void split_act_kernel(const float* __restrict__ X,
                                 __nv_bfloat16* __restrict__ hi, __nv_bfloat16* __restrict__ lo,
                                 int n2, int colsMask,
                                 const float* __restrict__ sc, const float* __restrict__ sh)
{
    int i = blockIdx.x * blockDim.x + threadIdx.x;
    if (i >= n2) return;
    float2 v2 = ((const float2*)X)[i];
    if (sc) {
        int c0 = (i * 2) & colsMask;
        v2.x = lrelu(v2.x * sc[c0] + sh[c0]);
        v2.y = lrelu(v2.y * sc[c0 + 1] + sh[c0 + 1]);
    }
    __nv_bfloat16 h0 = __float2bfloat16_rn(v2.x);
    __nv_bfloat16 h1 = __float2bfloat16_rn(v2.y);
    __nv_bfloat162 hp; hp.x = h0; hp.y = h1;
    __nv_bfloat162 lp;
    lp.x = __float2bfloat16_rn(v2.x - __bfloat162float(h0));
    lp.y = __float2bfloat16_rn(v2.y - __bfloat162float(h1));
    ((__nv_bfloat162*)hi)[i] = hp;
    ((__nv_bfloat162*)lo)[i] = lp;
}

// BN apply (no act) + split + in-place fp32 writeback (for h2), vectorized
__global__ void bn_apply_split_kernel(float* __restrict__ X,
                                      __nv_bfloat16* __restrict__ hi, __nv_bfloat16* __restrict__ lo,
                                      int n2, int colsMask,
                                      const float* __restrict__ sc, const float* __restrict__ sh)
{
    int i = blockIdx.x * blockDim.x + threadIdx.x;
    if (i >= n2) return;
    float2 v2 = ((float2*)X)[i];
    int c0 = (i * 2) & colsMask;
    v2.x = v2.x * sc[c0] + sh[c0];
    v2.y = v2.y * sc[c0 + 1] + sh[c0 + 1];
    ((float2*)X)[i] = v2;
    __nv_bfloat16 h0 = __float2bfloat16_rn(v2.x);
    __nv_bfloat16 h1 = __float2bfloat16_rn(v2.y);
    __nv_bfloat162 hp; hp.x = h0; hp.y = h1;
    __nv_bfloat162 lp;
    lp.x = __float2bfloat16_rn(v2.x - __bfloat162float(h0));
    lp.y = __float2bfloat16_rn(v2.y - __bfloat162float(h1));
    ((__nv_bfloat162*)hi)[i] = hp;
    ((__nv_bfloat162*)lo)[i] = lp;
}

__global__ void split_wt_kernel(const float* __restrict__ W,
                                __nv_bfloat16* __restrict__ hi, __nv_bfloat16* __restrict__ lo,
                                int K, int C)
{
    int i = blockIdx.x * blockDim.x + threadIdx.x;
    if (i >= K * C) return;
    int k = i / C, c = i % C;
    float v = W[i];
    __nv_bfloat16 h = __float2bfloat16_rn(v);
    hi[(size_t)c * K + k] = h;
    lo[(size_t)c * K + k] = __float2bfloat16_rn(v - __bfloat162float(h));
}

__global__ void split_wp_kernel(const float* __restrict__ Wm1,
                                __nv_bfloat16* __restrict__ hi, __nv_bfloat16* __restrict__ lo)
{
    int i = blockIdx.x * blockDim.x + threadIdx.x;
    if (i >= 64 * 256) return;
    int c = i >> 6, k = i & 63;
    float v = (c < 128) ? Wm1[k * 128 + c] : Wm1[(64 + k) * 128 + (c - 128)];
    __nv_bfloat16 h = __float2bfloat16_rn(v);
    hi[i] = h;
    lo[i] = __float2bfloat16_rn(v - __bfloat162float(h));
}

// ------------------------------ CSR build ---------------------------------
__global__ void init_deg_kernel(int* __restrict__ deg, int n)
{
    int i = blockIdx.x * blockDim.x + threadIdx.x;
    if (i < n) deg[i] = 1;
}

__global__ void count_kernel(const int* __restrict__ ei, int E, int* __restrict__ deg)
{
    int i = blockIdx.x * blockDim.x + threadIdx.x;
    if (i < E) atomicAdd(&deg[ei[E + i]], 1);
}

__global__ void scan_kernel(const int* __restrict__ deg, int* __restrict__ off, int n)
{
    __shared__ int sh[1024];
    __shared__ int carry_s;
    int t = threadIdx.x;
    if (t == 0) carry_s = 0;
    __syncthreads();
    for (int base = 0; base < n; base += 1024) {
        int i = base + t;
        int v = (i < n) ? deg[i] : 0;
        sh[t] = v;
        __syncthreads();
        int sum = v;
        for (int ofs = 1; ofs < 1024; ofs <<= 1) {
            int add = (t >= ofs) ? sh[t - ofs] : 0;
            __syncthreads();
            sum += add;
            sh[t] = sum;
            __syncthreads();
        }
        int carry = carry_s;
        if (i < n) off[i] = carry + sum - v;
        __syncthreads();
        if (t == 1023) carry_s = carry + sum;
        __syncthreads();
    }
    if (t == 0) off[n] = carry_s;
}

__global__ void copy_cur_kernel(const int* __restrict__ off, int* __restrict__ cur, int n)
{
    int i = blockIdx.x * blockDim.x + threadIdx.x;
    if (i < n) cur[i] = off[i];
}

__global__ void scatter_edges_kernel(const int* __restrict__ ei, int E,
                                     int* __restrict__ cur,
                                     int* __restrict__ csrc, int* __restrict__ cdst)
{
    int i = blockIdx.x * blockDim.x + threadIdx.x;
    if (i >= E) return;
    int d = ei[E + i];
    int pos = atomicAdd(&cur[d], 1);
    csrc[pos] = ei[i];
    cdst[pos] = d;
}

__global__ void scatter_loops_kernel(int N, int* __restrict__ cur,
                                     int* __restrict__ csrc, int* __restrict__ cdst)
{
    int n = blockIdx.x * blockDim.x + threadIdx.x;
    if (n >= N) return;
    int pos = atomicAdd(&cur[n], 1);
    csrc[pos] = n;
    cdst[pos] = n;
}

// ------------------------------ GAT attention -----------------------------
__global__ void maxwatt_kernel(const float4* __restrict__ asrc4, const float4* __restrict__ adst4,
                               const int* __restrict__ off, const int* __restrict__ csrc,
                               float4* __restrict__ watt4, int N)
{
    int w = (blockIdx.x * blockDim.x + threadIdx.x) >> 5;
    int lane = threadIdx.x & 31;
    if (w >= N) return;
    float4 ad = adst4[w];
    int lo = off[w], hi = off[w + 1];
    float m0 = -1e30f, m1 = -1e30f, m2 = -1e30f, m3 = -1e30f;
    for (int p = lo + lane; p < hi; p += 32) {
        int s = csrc[p];
        float4 as = asrc4[s];
        m0 = fmaxf(m0, lrelu(as.x + ad.x));
        m1 = fmaxf(m1, lrelu(as.y + ad.y));
        m2 = fmaxf(m2, lrelu(as.z + ad.z));
        m3 = fmaxf(m3, lrelu(as.w + ad.w));
    }
#pragma unroll
    for (int o = 16; o > 0; o >>= 1) {
        m0 = fmaxf(m0, __shfl_xor_sync(0xffffffffu, m0, o));
        m1 = fmaxf(m1, __shfl_xor_sync(0xffffffffu, m1, o));
        m2 = fmaxf(m2, __shfl_xor_sync(0xffffffffu, m2, o));
        m3 = fmaxf(m3, __shfl_xor_sync(0xffffffffu, m3, o));
    }
    for (int p = lo + lane; p < hi; p += 32) {
        int s = csrc[p];
        float4 as = asrc4[s];
        watt4[p] = make_float4(expf(lrelu(as.x + ad.x) - m0),
                               expf(lrelu(as.y + ad.y) - m1),
                               expf(lrelu(as.z + ad.z) - m2),
                               expf(lrelu(as.w + ad.w) - m3));
    }
}

__global__ __launch_bounds__(128) void gat_aggregate_kernel(
    const float* __restrict__ h, const float* __restrict__ watt,
    const int* __restrict__ off, const int* __restrict__ csrc,
    const float* __restrict__ bias, float* __restrict__ out, int concat)
{
    int d = blockIdx.x;
    int t = threadIdx.x;
    int c = t * 2;
    int hh = t >> 5;
    int lo = off[d], hi = off[d + 1];
    float accx = 0.f, accy = 0.f, den = 0.f;
    int p = lo;
    for (; p + 4 <= hi; p += 4) {
        int s0 = csrc[p], s1 = csrc[p + 1], s2 = csrc[p + 2], s3 = csrc[p + 3];
        float w0 = watt[p * 4 + hh], w1 = watt[(p + 1) * 4 + hh];
        float w2 = watt[(p + 2) * 4 + hh], w3 = watt[(p + 3) * 4 + hh];
        float2 h0 = *(const float2*)(h + (size_t)s0 * 256 + c);
        float2 h1 = *(const float2*)(h + (size_t)s1 * 256 + c);
        float2 h2v = *(const float2*)(h + (size_t)s2 * 256 + c);
        float2 h3 = *(const float2*)(h + (size_t)s3 * 256 + c);
        den += (w0 + w1) + (w2 + w3);
        accx += w0 * h0.x + w1 * h1.x + w2 * h2v.x + w3 * h3.x;
        accy += w0 * h0.y + w1 * h1.y + w2 * h2v.y + w3 * h3.y;
    }
    for (; p < hi; ++p) {
        int s = csrc[p];
        float w = watt[p * 4 + hh];
        float2 hv = *(const float2*)(h + (size_t)s * 256 + c);
        den += w;
        accx += w * hv.x;
        accy += w * hv.y;
    }
    float inv = 1.f / den;
    accx *= inv; accy *= inv;
    if (concat) {
        *(float2*)(out + (size_t)d * 256 + c) =
            make_float2(accx + bias[c], accy + bias[c + 1]);
    } else {
        __shared__ float red[256];
        red[c] = accx; red[c + 1] = accy;
        __syncthreads();
        if (t < 32) {
#pragma unroll
            for (int j = 0; j < 2; j++) {
                int cc = t * 2 + j;
                out[(size_t)d * 64 + cc] =
                    0.25f * (red[cc] + red[cc + 64] + red[cc + 128] + red[cc + 192]) + bias[cc];
            }
        }
    }
}

// ------------------------------ fused BatchNorm stats+final ---------------
__global__ void bn_stats_fused_kernel(const float* __restrict__ X, int rows, int cols,
                                      float* __restrict__ stats,
                                      const float* __restrict__ g, const float* __restrict__ be,
                                      float* __restrict__ sc, float* __restrict__ sh,
                                      int rowsPerBlock)
{
    __shared__ int isLast;
    int t = threadIdx.x;
    int c = t % cols;
    int rsub = t / cols;
    int rstep = 256 / cols;
    int r0 = blockIdx.x * rowsPerBlock;
    int r1 = r0 + rowsPerBlock; if (r1 > rows) r1 = rows;
    float s = 0.f, s2 = 0.f;
    for (int r = r0 + rsub; r < r1; r += rstep) {
        float v = X[(size_t)r * cols + c];
        s += v;
        s2 += v * v;
    }
    atomicAdd(&stats[c], s);
    atomicAdd(&stats[cols + c], s2);
    __threadfence();
    if (t == 0) {
        int done = atomicAdd(&g_bncnt, 1);
        isLast = (done == gridDim.x - 1);
    }
    __syncthreads();
    if (isLast) {
        if (t < cols) {
            float inv = 1.f / (float)rows;
            float mean = stats[t] * inv;
            float var = stats[cols + t] * inv - mean * mean;
            float scale = g[t] * rsqrtf(var + EPSBN);
            sc[t] = scale;
            sh[t] = be[t] - mean * scale;
            stats[t] = 0.f;
            stats[cols + t] = 0.f;
        }
        __threadfence();
        if (t == 0) *((volatile int*)&g_bncnt) = 0;
    }
}

// ------------------------------ host orchestration ------------------------
extern "C" void kernel_launch(void* const* d_in, const int* in_sizes, int n_in,
                              void* d_out, int out_size)
{
    const float* x  = (const float*)d_in[0];
    const int*   ei = (const int*)d_in[1];
    const float* ea = (const float*)d_in[2];
    const int N = in_sizes[0] / 128;
    const int E = in_sizes[2];

    const float *W0, *as0, *ad0, *b0, *g0, *be0;
    const float *W1, *as1, *ad1, *b1, *g1, *be1;
    const float *W2, *as2, *ad2, *b2, *g2, *be2;
    if (in_sizes[7] == 256 * 256) {
        W0 = (const float*)d_in[3];  as0 = (const float*)d_in[4];  ad0 = (const float*)d_in[5];  b0 = (const float*)d_in[6];
        W1 = (const float*)d_in[7];  as1 = (const float*)d_in[8];  ad1 = (const float*)d_in[9];  b1 = (const float*)d_in[10];
        W2 = (const float*)d_in[11]; as2 = (const float*)d_in[12]; ad2 = (const float*)d_in[13]; b2 = (const float*)d_in[14];
        g0 = (const float*)d_in[15]; be0 = (const float*)d_in[16];
        g1 = (const float*)d_in[17]; be1 = (const float*)d_in[18];
        g2 = (const float*)d_in[19]; be2 = (const float*)d_in[20];
    } else {
        W0 = (const float*)d_in[3];  as0 = (const float*)d_in[4];  ad0 = (const float*)d_in[5];  b0 = (const float*)d_in[6];
        g0 = (const float*)d_in[7];  be0 = (const float*)d_in[8];
        W1 = (const float*)d_in[9];  as1 = (const float*)d_in[10]; ad1 = (const float*)d_in[11]; b1 = (const float*)d_in[12];
        g1 = (const float*)d_in[13]; be1 = (const float*)d_in[14];
        W2 = (const float*)d_in[15]; as2 = (const float*)d_in[16]; ad2 = (const float*)d_in[17]; b2 = (const float*)d_in[18];
        g2 = (const float*)d_in[19]; be2 = (const float*)d_in[20];
    }
    const float* Wm1 = (const float*)d_in[21];
    const float* bm1 = (const float*)d_in[22];
    const float* Wm2 = (const float*)d_in[23];
    const float* bm2 = (const float*)d_in[24];
    const float* Wm3 = (const float*)d_in[25];
    const float* bm3 = (const float*)d_in[26];
    float* out = (float*)d_out;

    float *bufA, *bufB, *h2, *asrc, *adst, *watt, *stats, *bnsc, *bnsh;
    int *deg, *off, *cur, *csrc, *cdst;
    __nv_bfloat16 *xhi, *xlo;
    __nv_bfloat16 *w0hi, *w0lo, *w1hi, *w1lo, *w2hi, *w2lo;
    __nv_bfloat16 *wphi, *wplo, *cthi, *ctlo, *wm2hi, *wm2lo;
    cudaGetSymbolAddress((void**)&bufA, g_bufA);
    cudaGetSymbolAddress((void**)&bufB, g_bufB);
    cudaGetSymbolAddress((void**)&h2, g_h2);
    cudaGetSymbolAddress((void**)&asrc, g_asrc);
    cudaGetSymbolAddress((void**)&adst, g_adst);
    cudaGetSymbolAddress((void**)&watt, g_watt);
    cudaGetSymbolAddress((void**)&stats, g_stats);
    cudaGetSymbolAddress((void**)&bnsc, g_bnsc);
    cudaGetSymbolAddress((void**)&bnsh, g_bnsh);
    cudaGetSymbolAddress((void**)&deg, g_deg);
    cudaGetSymbolAddress((void**)&off, g_off);
    cudaGetSymbolAddress((void**)&cur, g_cur);
    cudaGetSymbolAddress((void**)&csrc, g_csrc);
    cudaGetSymbolAddress((void**)&cdst, g_cdst);
    cudaGetSymbolAddress((void**)&xhi, g_xhi);
    cudaGetSymbolAddress((void**)&xlo, g_xlo);
    cudaGetSymbolAddress((void**)&w0hi, g_w0hi);  cudaGetSymbolAddress((void**)&w0lo, g_w0lo);
    cudaGetSymbolAddress((void**)&w1hi, g_w1hi);  cudaGetSymbolAddress((void**)&w1lo, g_w1lo);
    cudaGetSymbolAddress((void**)&w2hi, g_w2hi);  cudaGetSymbolAddress((void**)&w2lo, g_w2lo);
    cudaGetSymbolAddress((void**)&wphi, g_wphi);  cudaGetSymbolAddress((void**)&wplo, g_wplo);
    cudaGetSymbolAddress((void**)&cthi, g_cthi);  cudaGetSymbolAddress((void**)&ctlo, g_ctlo);
    cudaGetSymbolAddress((void**)&wm2hi, g_wm2hi); cudaGetSymbolAddress((void**)&wm2lo, g_wm2lo);

    const int STAGE = 48 * 1024;
    const int SM2 = 2 * STAGE;
    const int SMEDGE = 112 * 1024;
    cudaFuncSetAttribute(hmma_gemm<0>, cudaFuncAttributeMaxDynamicSharedMemorySize, SM2);
    cudaFuncSetAttribute(hmma_gemm<1>, cudaFuncAttributeMaxDynamicSharedMemorySize, SM2);
    cudaFuncSetAttribute(edge_mlp_kernel, cudaFuncAttributeMaxDynamicSharedMemorySize, SMEDGE);

    auto node_gemm = [&](const __nv_bfloat16* Ah, const __nv_bfloat16* Al,
                         const __nv_bfloat16* Bh, const __nv_bfloat16* Bl,
                         float* C, int M, int Kt, int Ncols,
                         const float* aws, const float* awd) {
        dim3 grid((M + 127) / 128, Ncols / 64);
        int smem = (Kt > 64) ? SM2 : STAGE;
        if (aws)
            hmma_gemm<1><<<grid, 256, smem>>>(Ah, Al, Bh, Bl, C, M, Kt, Ncols,
                                              aws, awd, asrc, adst);
        else
            hmma_gemm<0><<<grid, 256, smem>>>(Ah, Al, Bh, Bl, C, M, Kt, Ncols,
                                              nullptr, nullptr, nullptr, nullptr);
    };

    // ---- launches 1-4: profiled launch (#4) is the L0 GEMM ----
    split_act_kernel<<<(N * 64 + 255) / 256, 256>>>(x, xhi, xlo, N * 64, 127, nullptr, nullptr);
    split_wt_kernel<<<(128 * 256 + 255) / 256, 256>>>(W0, w0hi, w0lo, 128, 256);
    init_deg_kernel<<<(N + 255) / 256, 256>>>(deg, N);
    node_gemm(xhi, xlo, w0hi, w0lo, bufA, N, 128, 256, as0, ad0);   // launch #4

    // ---- CSR build ----
    count_kernel<<<(E + 255) / 256, 256>>>(ei, E, deg);
    scan_kernel<<<1, 1024>>>(deg, off, N);
    copy_cur_kernel<<<(N + 255) / 256, 256>>>(off, cur, N);
    scatter_edges_kernel<<<(E + 255) / 256, 256>>>(ei, E, cur, csrc, cdst);
    scatter_loops_kernel<<<(N + 255) / 256, 256>>>(N, cur, csrc, cdst);

    auto attention = [&](const float* hbuf, const float* bias, float* outbuf, int concat) {
        maxwatt_kernel<<<(N * 32 + 255) / 256, 256>>>((const float4*)asrc, (const float4*)adst,
                                                      off, csrc, (float4*)watt, N);
        gat_aggregate_kernel<<<N, 128>>>(hbuf, watt, off, csrc, bias, outbuf, concat);
    };

    auto bnstats = [&](const float* X, int cols, const float* g, const float* be) {
        bn_stats_fused_kernel<<<(N + 255) / 256, 256>>>(X, N, cols, stats, g, be,
                                                        bnsc, bnsh, 256);
    };

    // ---- layer 0 ----
    attention(bufA, b0, bufB, 1);
    bnstats(bufB, 256, g0, be0);
    split_act_kernel<<<(N * 128 + 255) / 256, 256>>>(bufB, xhi, xlo, N * 128, 255, bnsc, bnsh);

    // ---- layer 1 ----
    split_wt_kernel<<<(256 * 256 + 255) / 256, 256>>>(W1, w1hi, w1lo, 256, 256);
    node_gemm(xhi, xlo, w1hi, w1lo, bufA, N, 256, 256, as1, ad1);
    attention(bufA, b1, bufB, 1);
    bnstats(bufB, 256, g1, be1);
    split_act_kernel<<<(N * 128 + 255) / 256, 256>>>(bufB, xhi, xlo, N * 128, 255, bnsc, bnsh);

    // ---- layer 2 ----
    split_wt_kernel<<<(256 * 256 + 255) / 256, 256>>>(W2, w2hi, w2lo, 256, 256);
    node_gemm(xhi, xlo, w2hi, w2lo, bufA, N, 256, 256, as2, ad2);
    attention(bufA, b2, h2, 0);
    bnstats(h2, 64, g2, be2);
    bn_apply_split_kernel<<<(N * 32 + 255) / 256, 256>>>(h2, xhi, xlo, N * 32, 63, bnsc, bnsh);

    // ---- edge MLP ----
    split_wp_kernel<<<(64 * 256 + 255) / 256, 256>>>(Wm1, wphi, wplo);
    node_gemm(xhi, xlo, wphi, wplo, bufA, N, 64, 256, nullptr, nullptr);  // PQ

    split_wt_kernel<<<(64 * 128 + 255) / 256, 256>>>(Wm1 + 128 * 128, cthi, ctlo, 64, 128);
    split_wt_kernel<<<(128 * 64 + 255) / 256, 256>>>(Wm2, wm2hi, wm2lo, 128, 64);

    const int nTiles = (E + 63) / 64;
    edge_mlp_kernel<<<296, 256, SMEDGE>>>(
        cthi, ctlo, wm2hi, wm2lo, ei, E, h2, bufA, ea,
        Wm1 + 192 * 128, bm1, bm2, Wm3, bm3, out, nTiles);
}